// round 13
// baseline (speedup 1.0000x reference)
#include <cuda_runtime.h>
#include <cuda_bf16.h>
#include <math.h>
#include <float.h>
#include <stdint.h>

#define S 2048
#define H 2048
#define NH 16
#define D 128
#define E 8
#define TOPK 4
#define IE 1408
#define IS 5632

// ---------------- scratch ----------------
__device__ float g_hhi[S * H];
__device__ float g_hlo[S * H];
__device__ float g_q[S * H];
__device__ float g_k[S * H];
__device__ float g_qhi[S * H];
__device__ float g_qlo[S * H];
__device__ float g_khi[S * H];
__device__ float g_klo[S * H];
__device__ float g_vhi[S * H];
__device__ float g_vlo[S * H];
__device__ float g_scores[(size_t)NH * S * S];
__device__ float g_slo[(size_t)NH * S * S];
__device__ float g_ahi[S * H];
__device__ float g_alo[S * H];
__device__ float g_x1[S * H];
__device__ float g_h2[S * H];
__device__ float g_ch2[S * H];
__device__ float g_gb[(size_t)E * S * IE];
__device__ float g_ub[(size_t)E * S * IE];
__device__ float g_eo[(size_t)E * S * H];
__device__ float g_sgb[S * IS];
__device__ float g_sub[S * IS];
__device__ float g_sdwn[S * H];
__device__ float g_gatev[S];
__device__ int g_idx[E * S];
__device__ int g_cnt[E];
__device__ int g_tokmap[S * TOPK];
__device__ float g_tokw[S * TOPK];
__device__ float g_ceg[(size_t)E * H * IE];
__device__ float g_ceu[(size_t)E * H * IE];
__device__ float g_ced[(size_t)E * IE * H];
__device__ float g_csg[(size_t)H * IS];
__device__ float g_csu[(size_t)H * IS];
__device__ float g_csd[(size_t)IS * H];
__device__ float g_wsp[(size_t)8 * H * H];

// ================= helpers =================
__device__ __forceinline__ uint32_t smem_to_u32(const void* p) {
    uint32_t a;
    asm("{ .reg .u64 t; cvta.to.shared.u64 t, %1; cvt.u32.u64 %0, t; }"
        : "=r"(a) : "l"(p));
    return a;
}
__device__ __forceinline__ float f2tf32f(float f) {
    uint32_t r;
    asm("cvt.rna.tf32.f32 %0, %1;" : "=r"(r) : "f"(f));
    return __uint_as_float(r);
}
__device__ __forceinline__ void mma_tf32(float* d, const uint32_t* a,
                                         const uint32_t* b) {
    asm volatile(
        "mma.sync.aligned.m16n8k8.row.col.f32.tf32.tf32.f32 "
        "{%0,%1,%2,%3}, {%4,%5,%6,%7}, {%8,%9}, {%0,%1,%2,%3};"
        : "+f"(d[0]), "+f"(d[1]), "+f"(d[2]), "+f"(d[3])
        : "r"(a[0]), "r"(a[1]), "r"(a[2]), "r"(a[3]), "r"(b[0]), "r"(b[1]));
}
__device__ __forceinline__ void cp_async16(uint32_t dst, const void* src) {
    asm volatile("cp.async.ca.shared.global [%0], [%1], 16;"
                 :: "r"(dst), "l"(src));
}

// ================= tf32 mma GEMM v3b (MoE path, 5-stage) ======================
#define APADF 20
#define BPADF 136
#define A_STAGE_B (128 * APADF * 4)
#define B_STAGE_B (16 * BPADF * 4)
#define STAGE_B (A_STAGE_B + B_STAGE_B)  // 18944
#define MMA_SMEM (STAGE_B * 5)           // 94720

__global__ __launch_bounds__(128, 2)
void mma_gemm_kernel(const float* __restrict__ A, int lda, long long aStrE,
                     const float* __restrict__ B0, const float* __restrict__ B1,
                     int ldb, long long bStrE,
                     float* __restrict__ C0, float* __restrict__ C1,
                     int ldc, long long cStrE,
                     int M, int N, int K,
                     const int* __restrict__ gidxBase, int gidxStr,
                     const int* __restrict__ cntBase, int eShift) {
    extern __shared__ char smem[];
    const uint32_t sb = smem_to_u32(smem);
    const int z = blockIdx.z;
    const int e = z >> eShift;
    const int which = z & ((1 << eShift) - 1);
    const float* B = (which ? B1 : B0) + (long long)e * bStrE;
    float* C = (which ? C1 : C0) + (long long)e * cStrE;
    A += (long long)e * aStrE;

    const int cnt = cntBase ? cntBase[e] : M;
    const int mEff = min(M, cnt);
    const int row0 = blockIdx.y * 128;
    const int col0 = blockIdx.x * 128;
    if (row0 >= mEff) return;
    const int* gidx = gidxBase ? gidxBase + (long long)e * gidxStr : nullptr;

    const int tid = threadIdx.x;
    const int wid = tid >> 5;
    const int lane = tid & 31;
    const int g = lane >> 2;
    const int t4 = lane & 3;
    const int warpM = wid >> 1;
    const int warpN = wid & 1;

    const float* aG[4];
    uint32_t aS[4];
#pragma unroll
    for (int j = 0; j < 4; j++) {
        int u = tid + 128 * j;
        int m = u >> 2, c4 = u & 3;
        int arow = row0 + m;
        int src;
        if (gidx) src = (arow < cnt) ? gidx[arow] : 0;
        else src = min(arow, M - 1);
        aG[j] = A + (size_t)src * lda + c4 * 4;
        aS[j] = sb + (uint32_t)(m * APADF + c4 * 4) * 4u;
    }
    const float* bG[4];
    uint32_t bS[4];
#pragma unroll
    for (int j = 0; j < 4; j++) {
        int u = tid + 128 * j;
        int n4 = u & 31, kk = u >> 5;
        bG[j] = B + (size_t)kk * ldb + col0 + n4 * 4;
        bS[j] = sb + A_STAGE_B + (uint32_t)(kk * BPADF + n4 * 4) * 4u;
    }

    float acc[4][8][4];
#pragma unroll
    for (int mt = 0; mt < 4; mt++)
#pragma unroll
        for (int nt = 0; nt < 8; nt++)
#pragma unroll
            for (int r = 0; r < 4; r++) acc[mt][nt][r] = 0.f;

    const int nT = K / 16;
    const uint32_t stOff[5] = {0u, (uint32_t)STAGE_B, 2u * STAGE_B,
                               3u * STAGE_B, 4u * STAGE_B};

#define ISSUE(i, st)                                                  \
    do {                                                              \
        uint32_t _off = stOff[st];                                    \
        int _k0 = (i) * 16;                                           \
        cp_async16(aS[0] + _off, aG[0] + _k0);                        \
        cp_async16(aS[1] + _off, aG[1] + _k0);                        \
        cp_async16(aS[2] + _off, aG[2] + _k0);                        \
        cp_async16(aS[3] + _off, aG[3] + _k0);                        \
        cp_async16(bS[0] + _off, bG[0] + (size_t)_k0 * ldb);          \
        cp_async16(bS[1] + _off, bG[1] + (size_t)_k0 * ldb);          \
        cp_async16(bS[2] + _off, bG[2] + (size_t)_k0 * ldb);          \
        cp_async16(bS[3] + _off, bG[3] + (size_t)_k0 * ldb);          \
        asm volatile("cp.async.commit_group;");                       \
    } while (0)

    ISSUE(0, 0);
    if (nT > 1) ISSUE(1, 1);
    if (nT > 2) ISSUE(2, 2);
    if (nT > 3) ISSUE(3, 3);

    int stC = 0, stI = 4;
    for (int i = 0; i < nT; i++) {
        const int rem = nT - 1 - i;
        if (rem >= 3)
            asm volatile("cp.async.wait_group 3;");
        else if (rem == 2)
            asm volatile("cp.async.wait_group 2;");
        else if (rem == 1)
            asm volatile("cp.async.wait_group 1;");
        else
            asm volatile("cp.async.wait_group 0;");
        __syncthreads();
        if (i + 4 < nT) {
            ISSUE(i + 4, stI);
            stI = (stI == 4) ? 0 : stI + 1;
        }

        const uint32_t* Asb = (const uint32_t*)(smem + stOff[stC]);
        const uint32_t* Bsb = (const uint32_t*)(smem + stOff[stC] + A_STAGE_B);
        stC = (stC == 4) ? 0 : stC + 1;
#pragma unroll
        for (int kk = 0; kk < 16; kk += 8) {
            uint32_t a[4][4], b[8][2];
#pragma unroll
            for (int mt = 0; mt < 4; mt++) {
                int mrow = warpM * 64 + mt * 16;
                a[mt][0] = Asb[(mrow + g) * APADF + kk + t4];
                a[mt][1] = Asb[(mrow + g + 8) * APADF + kk + t4];
                a[mt][2] = Asb[(mrow + g) * APADF + kk + t4 + 4];
                a[mt][3] = Asb[(mrow + g + 8) * APADF + kk + t4 + 4];
            }
#pragma unroll
            for (int nt = 0; nt < 8; nt++) {
                int ncol = warpN * 64 + nt * 8;
                b[nt][0] = Bsb[(kk + t4) * BPADF + ncol + g];
                b[nt][1] = Bsb[(kk + t4 + 4) * BPADF + ncol + g];
            }
#pragma unroll
            for (int mt = 0; mt < 4; mt++)
#pragma unroll
                for (int nt = 0; nt < 8; nt++)
                    mma_tf32(acc[mt][nt], a[mt], b[nt]);
        }
    }
#undef ISSUE

#pragma unroll
    for (int mt = 0; mt < 4; mt++) {
        int rBase = row0 + warpM * 64 + mt * 16 + g;
#pragma unroll
        for (int half = 0; half < 2; half++) {
            int r = rBase + half * 8;
            if (r >= mEff) continue;
            float* cp = C + (size_t)r * ldc;
#pragma unroll
            for (int nt = 0; nt < 8; nt++) {
                int col = col0 + warpN * 64 + nt * 8 + t4 * 2;
                cp[col] = acc[mt][nt][half * 2 + 0];
                cp[col + 1] = acc[mt][nt][half * 2 + 1];
            }
        }
    }
}

// ================= 3xTF32 mma GEMM (QKV / wo) ==========
#define X_APAD 12
#define X_BPAD 136
#define X_A_B (128 * X_APAD * 4)
#define X_B_B (8 * X_BPAD * 4)
#define X_STAGE (2 * X_A_B + 2 * X_B_B)
#define X_SMEM (X_STAGE * 4)

__global__ __launch_bounds__(128, 2)
void mma3x_kernel(const float* __restrict__ Ahi, const float* __restrict__ Alo,
                  int lda,
                  const float* __restrict__ B0h, const float* __restrict__ B0l,
                  const float* __restrict__ B1h, const float* __restrict__ B1l,
                  const float* __restrict__ B2h, const float* __restrict__ B2l,
                  int ldb,
                  const float* __restrict__ bias0,
                  const float* __restrict__ bias1,
                  const float* __restrict__ bias2,
                  float* __restrict__ C0, float* __restrict__ C1,
                  float* __restrict__ C2, float* __restrict__ C2lo, int ldc,
                  const float* __restrict__ residual,
                  int K) {
    extern __shared__ char smem[];
    const uint32_t sb = smem_to_u32(smem);
    const int z = blockIdx.z;
    const float* Bh = (z == 0) ? B0h : (z == 1 ? B1h : B2h);
    const float* Bl = (z == 0) ? B0l : (z == 1 ? B1l : B2l);
    const float* bias = (z == 0) ? bias0 : (z == 1 ? bias1 : bias2);
    float* C = (z == 0) ? C0 : (z == 1 ? C1 : C2);
    float* Clo = (z == 2) ? C2lo : nullptr;

    const int row0 = blockIdx.y * 128;
    const int col0 = blockIdx.x * 128;

    const int tid = threadIdx.x;
    const int wid = tid >> 5;
    const int lane = tid & 31;
    const int g = lane >> 2;
    const int t4 = lane & 3;
    const int warpM = wid >> 1;
    const int warpN = wid & 1;

    const long long aLoD = Alo - Ahi;
    const long long bLoD = Bl - Bh;

    const float* aGh[2];
    uint32_t aSh[2];
#pragma unroll
    for (int j = 0; j < 2; j++) {
        int u = tid + 128 * j;
        int m = u >> 1, c4 = u & 1;
        aGh[j] = Ahi + (size_t)(row0 + m) * lda + c4 * 4;
        aSh[j] = sb + (uint32_t)(m * X_APAD + c4 * 4) * 4u;
    }
    const float* bGh[2];
    uint32_t bSh[2];
#pragma unroll
    for (int j = 0; j < 2; j++) {
        int u = tid + 128 * j;
        int kk = u >> 5, n4 = u & 31;
        bGh[j] = Bh + (size_t)kk * ldb + col0 + n4 * 4;
        bSh[j] = sb + (uint32_t)(2 * X_A_B) +
                 (uint32_t)(kk * X_BPAD + n4 * 4) * 4u;
    }

    float acc[4][8][4];
#pragma unroll
    for (int mt = 0; mt < 4; mt++)
#pragma unroll
        for (int nt = 0; nt < 8; nt++)
#pragma unroll
            for (int r = 0; r < 4; r++) acc[mt][nt][r] = 0.f;

    const int nT = K / 8;

#define XISSUE(i)                                                       \
    do {                                                                \
        uint32_t _off = (uint32_t)((i) & 3) * X_STAGE;                  \
        int _k0 = (i) * 8;                                              \
        cp_async16(aSh[0] + _off, aGh[0] + _k0);                        \
        cp_async16(aSh[1] + _off, aGh[1] + _k0);                        \
        cp_async16(aSh[0] + X_A_B + _off, aGh[0] + aLoD + _k0);         \
        cp_async16(aSh[1] + X_A_B + _off, aGh[1] + aLoD + _k0);         \
        cp_async16(bSh[0] + _off, bGh[0] + (size_t)_k0 * ldb);          \
        cp_async16(bSh[1] + _off, bGh[1] + (size_t)_k0 * ldb);          \
        cp_async16(bSh[0] + X_B_B + _off, bGh[0] + bLoD + (size_t)_k0 * ldb); \
        cp_async16(bSh[1] + X_B_B + _off, bGh[1] + bLoD + (size_t)_k0 * ldb); \
        asm volatile("cp.async.commit_group;");                         \
    } while (0)

    XISSUE(0);
    XISSUE(1);
    XISSUE(2);

    for (int i = 0; i < nT; i++) {
        const int rem = nT - 1 - i;
        if (rem >= 2)
            asm volatile("cp.async.wait_group 2;");
        else if (rem == 1)
            asm volatile("cp.async.wait_group 1;");
        else
            asm volatile("cp.async.wait_group 0;");
        __syncthreads();
        if (i + 3 < nT) XISSUE(i + 3);

        const uint32_t* Ah = (const uint32_t*)(smem + (size_t)(i & 3) * X_STAGE);
        const uint32_t* Al = Ah + (X_A_B / 4);
        const uint32_t* Bhs =
            (const uint32_t*)(smem + (size_t)(i & 3) * X_STAGE + 2 * X_A_B);
        const uint32_t* Bls = Bhs + (X_B_B / 4);

        uint32_t ah[4][4], al[4][4], bh[8][2], bl[8][2];
#pragma unroll
        for (int mt = 0; mt < 4; mt++) {
            int mrow = warpM * 64 + mt * 16;
            ah[mt][0] = Ah[(mrow + g) * X_APAD + t4];
            ah[mt][1] = Ah[(mrow + g + 8) * X_APAD + t4];
            ah[mt][2] = Ah[(mrow + g) * X_APAD + t4 + 4];
            ah[mt][3] = Ah[(mrow + g + 8) * X_APAD + t4 + 4];
            al[mt][0] = Al[(mrow + g) * X_APAD + t4];
            al[mt][1] = Al[(mrow + g + 8) * X_APAD + t4];
            al[mt][2] = Al[(mrow + g) * X_APAD + t4 + 4];
            al[mt][3] = Al[(mrow + g + 8) * X_APAD + t4 + 4];
        }
#pragma unroll
        for (int nt = 0; nt < 8; nt++) {
            int ncol = warpN * 64 + nt * 8;
            bh[nt][0] = Bhs[t4 * X_BPAD + ncol + g];
            bh[nt][1] = Bhs[(t4 + 4) * X_BPAD + ncol + g];
            bl[nt][0] = Bls[t4 * X_BPAD + ncol + g];
            bl[nt][1] = Bls[(t4 + 4) * X_BPAD + ncol + g];
        }
#pragma unroll
        for (int mt = 0; mt < 4; mt++)
#pragma unroll
            for (int nt = 0; nt < 8; nt++) {
                mma_tf32(acc[mt][nt], ah[mt], bh[nt]);
                mma_tf32(acc[mt][nt], ah[mt], bl[nt]);
                mma_tf32(acc[mt][nt], al[mt], bh[nt]);
            }
    }
#undef XISSUE

#pragma unroll
    for (int mt = 0; mt < 4; mt++) {
        int rBase = row0 + warpM * 64 + mt * 16 + g;
#pragma unroll
        for (int half = 0; half < 2; half++) {
            int r = rBase + half * 8;
            float* cp = C + (size_t)r * ldc;
            float* cl = Clo ? Clo + (size_t)r * ldc : nullptr;
            const float* rp = residual ? residual + (size_t)r * ldc : nullptr;
#pragma unroll
            for (int nt = 0; nt < 8; nt++) {
                int col = col0 + warpN * 64 + nt * 8 + t4 * 2;
                float v0 = acc[mt][nt][half * 2 + 0];
                float v1 = acc[mt][nt][half * 2 + 1];
                if (bias) {
                    v0 += bias[col];
                    v1 += bias[col + 1];
                }
                if (rp) {
                    v0 += rp[col];
                    v1 += rp[col + 1];
                }
                if (cl) {
                    float h0 = f2tf32f(v0), h1 = f2tf32f(v1);
                    cp[col] = h0;
                    cp[col + 1] = h1;
                    cl[col] = f2tf32f(v0 - h0);
                    cl[col + 1] = f2tf32f(v1 - h1);
                } else {
                    cp[col] = v0;
                    cp[col + 1] = v1;
                }
            }
        }
    }
}

// ================= 3xTF32 scores kernel (Q·K^T, causal) =======================
#define SC_HALF (128 * X_APAD * 4)
#define SC_STAGE (4 * SC_HALF)
#define SC_SMEM (SC_STAGE * 3)

__global__ __launch_bounds__(128, 2)
void sc3x_kernel(const float* __restrict__ qhi, const float* __restrict__ qlo,
                 const float* __restrict__ khi, const float* __restrict__ klo,
                 float* __restrict__ scores, float scale) {
    extern __shared__ char smem[];
    const uint32_t sb = smem_to_u32(smem);
    const int h = blockIdx.z;
    const int row0 = blockIdx.y * 128;
    const int col0 = blockIdx.x * 128;
    if (col0 > row0) return;

    const int lda = NH * D;
    const float* Ah = qhi + (size_t)h * D;
    const float* Bh = khi + (size_t)h * D;
    const long long aLoD = qlo - qhi;
    const long long bLoD = klo - khi;

    const int tid = threadIdx.x;
    const int wid = tid >> 5;
    const int lane = tid & 31;
    const int g = lane >> 2;
    const int t4 = lane & 3;
    const int warpM = wid >> 1;
    const int warpN = wid & 1;

    const float* aGh[2];
    uint32_t aSh[2];
    const float* bGh[2];
    uint32_t bSh[2];
#pragma unroll
    for (int j = 0; j < 2; j++) {
        int u = tid + 128 * j;
        int m = u >> 1, c4 = u & 1;
        aGh[j] = Ah + (size_t)(row0 + m) * lda + c4 * 4;
        aSh[j] = sb + (uint32_t)(m * X_APAD + c4 * 4) * 4u;
        bGh[j] = Bh + (size_t)(col0 + m) * lda + c4 * 4;
        bSh[j] = sb + (uint32_t)(2 * SC_HALF) +
                 (uint32_t)(m * X_APAD + c4 * 4) * 4u;
    }

    float acc[4][8][4];
#pragma unroll
    for (int mt = 0; mt < 4; mt++)
#pragma unroll
        for (int nt = 0; nt < 8; nt++)
#pragma unroll
            for (int r = 0; r < 4; r++) acc[mt][nt][r] = 0.f;

    const int nT = D / 8;
    const uint32_t stOff[3] = {0u, SC_STAGE, 2u * SC_STAGE};

#define SISSUE(i, st)                                                  \
    do {                                                               \
        uint32_t _off = stOff[st];                                     \
        int _k0 = (i) * 8;                                             \
        cp_async16(aSh[0] + _off, aGh[0] + _k0);                       \
        cp_async16(aSh[1] + _off, aGh[1] + _k0);                       \
        cp_async16(aSh[0] + SC_HALF + _off, aGh[0] + aLoD + _k0);      \
        cp_async16(aSh[1] + SC_HALF + _off, aGh[1] + aLoD + _k0);      \
        cp_async16(bSh[0] + _off, bGh[0] + _k0);                       \
        cp_async16(bSh[1] + _off, bGh[1] + _k0);                       \
        cp_async16(bSh[0] + SC_HALF + _off, bGh[0] + bLoD + _k0);      \
        cp_async16(bSh[1] + SC_HALF + _off, bGh[1] + bLoD + _k0);      \
        asm volatile("cp.async.commit_group;");                        \
    } while (0)

    SISSUE(0, 0);
    SISSUE(1, 1);

    int stC = 0, stI = 2;
    for (int i = 0; i < nT; i++) {
        if (i + 1 < nT)
            asm volatile("cp.async.wait_group 1;");
        else
            asm volatile("cp.async.wait_group 0;");
        __syncthreads();
        if (i + 2 < nT) {
            SISSUE(i + 2, stI);
            stI = (stI == 2) ? 0 : stI + 1;
        }
        const uint32_t* Ah2 = (const uint32_t*)(smem + stOff[stC]);
        const uint32_t* Al2 = Ah2 + (SC_HALF / 4);
        const uint32_t* Bh2 = (const uint32_t*)(smem + stOff[stC] + 2 * SC_HALF);
        const uint32_t* Bl2 = Bh2 + (SC_HALF / 4);
        stC = (stC == 2) ? 0 : stC + 1;

        uint32_t ah[4][4], al[4][4], bh[8][2], bl[8][2];
#pragma unroll
        for (int mt = 0; mt < 4; mt++) {
            int mrow = warpM * 64 + mt * 16;
            ah[mt][0] = Ah2[(mrow + g) * X_APAD + t4];
            ah[mt][1] = Ah2[(mrow + g + 8) * X_APAD + t4];
            ah[mt][2] = Ah2[(mrow + g) * X_APAD + t4 + 4];
            ah[mt][3] = Ah2[(mrow + g + 8) * X_APAD + t4 + 4];
            al[mt][0] = Al2[(mrow + g) * X_APAD + t4];
            al[mt][1] = Al2[(mrow + g + 8) * X_APAD + t4];
            al[mt][2] = Al2[(mrow + g) * X_APAD + t4 + 4];
            al[mt][3] = Al2[(mrow + g + 8) * X_APAD + t4 + 4];
        }
#pragma unroll
        for (int nt = 0; nt < 8; nt++) {
            int ncol = warpN * 64 + nt * 8;
            bh[nt][0] = Bh2[(ncol + g) * X_APAD + t4];
            bh[nt][1] = Bh2[(ncol + g) * X_APAD + t4 + 4];
            bl[nt][0] = Bl2[(ncol + g) * X_APAD + t4];
            bl[nt][1] = Bl2[(ncol + g) * X_APAD + t4 + 4];
        }
#pragma unroll
        for (int mt = 0; mt < 4; mt++)
#pragma unroll
            for (int nt = 0; nt < 8; nt++) {
                mma_tf32(acc[mt][nt], ah[mt], bh[nt]);
                mma_tf32(acc[mt][nt], ah[mt], bl[nt]);
                mma_tf32(acc[mt][nt], al[mt], bh[nt]);
            }
    }
#undef SISSUE

    float* Cbase = scores + (size_t)h * S * S;
#pragma unroll
    for (int mt = 0; mt < 4; mt++) {
        int rBase = row0 + warpM * 64 + mt * 16 + g;
#pragma unroll
        for (int half = 0; half < 2; half++) {
            int r = rBase + half * 8;
            float* cp = Cbase + (size_t)r * S;
#pragma unroll
            for (int nt = 0; nt < 8; nt++) {
                int col = col0 + warpN * 64 + nt * 8 + t4 * 2;
                float v0 = acc[mt][nt][half * 2 + 0] * scale;
                float v1 = acc[mt][nt][half * 2 + 1] * scale;
                if (col > r) v0 = -3.4028234663852886e38f;
                if (col + 1 > r) v1 = -3.4028234663852886e38f;
                cp[col] = v0;
                cp[col + 1] = v1;
            }
        }
    }
}

// ================= 3xTF32 PV kernel (probs·V, kLimit, split output) ===========
__global__ __launch_bounds__(128, 2)
void pv3x_kernel(const float* __restrict__ phi, const float* __restrict__ plo,
                 const float* __restrict__ vhi, const float* __restrict__ vlo,
                 float* __restrict__ ahiOut, float* __restrict__ aloOut) {
    extern __shared__ char smem[];
    const uint32_t sb = smem_to_u32(smem);
    const int h = blockIdx.z;
    const int row0 = blockIdx.y * 128;

    const int lda = S;
    const int ldb = NH * D;
    const float* Ah = phi + (size_t)h * S * S;
    const float* Bh = vhi + (size_t)h * D;
    const long long aLoD = plo - phi;
    const long long bLoD = vlo - vhi;

    const int tid = threadIdx.x;
    const int wid = tid >> 5;
    const int lane = tid & 31;
    const int g = lane >> 2;
    const int t4 = lane & 3;
    const int warpM = wid >> 1;
    const int warpN = wid & 1;

    const float* aGh[2];
    uint32_t aSh[2];
#pragma unroll
    for (int j = 0; j < 2; j++) {
        int u = tid + 128 * j;
        int m = u >> 1, c4 = u & 1;
        aGh[j] = Ah + (size_t)(row0 + m) * lda + c4 * 4;
        aSh[j] = sb + (uint32_t)(m * X_APAD + c4 * 4) * 4u;
    }
    const float* bGh[2];
    uint32_t bSh[2];
#pragma unroll
    for (int j = 0; j < 2; j++) {
        int u = tid + 128 * j;
        int kk = u >> 5, n4 = u & 31;
        bGh[j] = Bh + (size_t)kk * ldb + n4 * 4;
        bSh[j] = sb + (uint32_t)(2 * X_A_B) +
                 (uint32_t)(kk * X_BPAD + n4 * 4) * 4u;
    }

    float acc[4][8][4];
#pragma unroll
    for (int mt = 0; mt < 4; mt++)
#pragma unroll
        for (int nt = 0; nt < 8; nt++)
#pragma unroll
            for (int r = 0; r < 4; r++) acc[mt][nt][r] = 0.f;

    const int nT = (row0 + 128) / 8;

#define PISSUE(i)                                                       \
    do {                                                                \
        uint32_t _off = (uint32_t)((i) & 3) * X_STAGE;                  \
        int _k0 = (i) * 8;                                              \
        cp_async16(aSh[0] + _off, aGh[0] + _k0);                        \
        cp_async16(aSh[1] + _off, aGh[1] + _k0);                        \
        cp_async16(aSh[0] + X_A_B + _off, aGh[0] + aLoD + _k0);         \
        cp_async16(aSh[1] + X_A_B + _off, aGh[1] + aLoD + _k0);         \
        cp_async16(bSh[0] + _off, bGh[0] + (size_t)_k0 * ldb);          \
        cp_async16(bSh[1] + _off, bGh[1] + (size_t)_k0 * ldb);          \
        cp_async16(bSh[0] + X_B_B + _off, bGh[0] + bLoD + (size_t)_k0 * ldb); \
        cp_async16(bSh[1] + X_B_B + _off, bGh[1] + bLoD + (size_t)_k0 * ldb); \
        asm volatile("cp.async.commit_group;");                         \
    } while (0)

    PISSUE(0);
    PISSUE(1);
    PISSUE(2);

    for (int i = 0; i < nT; i++) {
        const int rem = nT - 1 - i;
        if (rem >= 2)
            asm volatile("cp.async.wait_group 2;");
        else if (rem == 1)
            asm volatile("cp.async.wait_group 1;");
        else
            asm volatile("cp.async.wait_group 0;");
        __syncthreads();
        if (i + 3 < nT) PISSUE(i + 3);

        const uint32_t* Ah2 = (const uint32_t*)(smem + (size_t)(i & 3) * X_STAGE);
        const uint32_t* Al2 = Ah2 + (X_A_B / 4);
        const uint32_t* Bh2 =
            (const uint32_t*)(smem + (size_t)(i & 3) * X_STAGE + 2 * X_A_B);
        const uint32_t* Bl2 = Bh2 + (X_B_B / 4);

        uint32_t ah[4][4], al[4][4], bh[8][2], bl[8][2];
#pragma unroll
        for (int mt = 0; mt < 4; mt++) {
            int mrow = warpM * 64 + mt * 16;
            ah[mt][0] = Ah2[(mrow + g) * X_APAD + t4];
            ah[mt][1] = Ah2[(mrow + g + 8) * X_APAD + t4];
            ah[mt][2] = Ah2[(mrow + g) * X_APAD + t4 + 4];
            ah[mt][3] = Ah2[(mrow + g + 8) * X_APAD + t4 + 4];
            al[mt][0] = Al2[(mrow + g) * X_APAD + t4];
            al[mt][1] = Al2[(mrow + g + 8) * X_APAD + t4];
            al[mt][2] = Al2[(mrow + g) * X_APAD + t4 + 4];
            al[mt][3] = Al2[(mrow + g + 8) * X_APAD + t4 + 4];
        }
#pragma unroll
        for (int nt = 0; nt < 8; nt++) {
            int ncol = warpN * 64 + nt * 8;
            bh[nt][0] = Bh2[t4 * X_BPAD + ncol + g];
            bh[nt][1] = Bh2[(t4 + 4) * X_BPAD + ncol + g];
            bl[nt][0] = Bl2[t4 * X_BPAD + ncol + g];
            bl[nt][1] = Bl2[(t4 + 4) * X_BPAD + ncol + g];
        }
#pragma unroll
        for (int mt = 0; mt < 4; mt++)
#pragma unroll
            for (int nt = 0; nt < 8; nt++) {
                mma_tf32(acc[mt][nt], ah[mt], bh[nt]);
                mma_tf32(acc[mt][nt], ah[mt], bl[nt]);
                mma_tf32(acc[mt][nt], al[mt], bh[nt]);
            }
    }
#undef PISSUE

    float* ChiB = ahiOut + (size_t)h * D;
    float* CloB = aloOut + (size_t)h * D;
#pragma unroll
    for (int mt = 0; mt < 4; mt++) {
        int rBase = row0 + warpM * 64 + mt * 16 + g;
#pragma unroll
        for (int half = 0; half < 2; half++) {
            int r = rBase + half * 8;
            float* cph = ChiB + (size_t)r * (NH * D);
            float* cpl = CloB + (size_t)r * (NH * D);
#pragma unroll
            for (int nt = 0; nt < 8; nt++) {
                int col = warpN * 64 + nt * 8 + t4 * 2;
                float v0 = acc[mt][nt][half * 2 + 0];
                float v1 = acc[mt][nt][half * 2 + 1];
                float h0 = f2tf32f(v0), h1 = f2tf32f(v1);
                cph[col] = h0;
                cph[col + 1] = h1;
                cpl[col] = f2tf32f(v0 - h0);
                cpl[col + 1] = f2tf32f(v1 - h1);
            }
        }
    }
}

// ---------------- weight prep ----------------
__global__ void prep_kernel(const float4* eg, float4* ceg,
                            const float4* eu, float4* ceu,
                            const float4* ed, float4* ced,
                            const float4* sg, float4* csg,
                            const float4* su, float4* csu,
                            const float4* sd, float4* csd,
                            const float4* wq, const float4* wk,
                            const float4* wv, const float4* wo,
                            float4* wsp) {
    const long long nEG = (long long)E * H * IE / 4;
    const long long nED = (long long)E * IE * H / 4;
    const long long nSG = (long long)H * IS / 4;
    const long long nSD = (long long)IS * H / 4;
    const long long nWW = (long long)H * H / 4;
    long long i = (long long)blockIdx.x * 256 + threadIdx.x;
    int y = blockIdx.y;
    if (y < 6) {
        const float4* src;
        float4* dst;
        long long n;
        switch (y) {
            case 0: src = eg; dst = ceg; n = nEG; break;
            case 1: src = eu; dst = ceu; n = nEG; break;
            case 2: src = ed; dst = ced; n = nED; break;
            case 3: src = sg; dst = csg; n = nSG; break;
            case 4: src = su; dst = csu; n = nSG; break;
            default: src = sd; dst = csd; n = nSD; break;
        }
        if (i < n) {
            float4 v = src[i];
            v.x = f2tf32f(v.x);
            v.y = f2tf32f(v.y);
            v.z = f2tf32f(v.z);
            v.w = f2tf32f(v.w);
            dst[i] = v;
        }
    } else {
        const float4* src = (y == 6) ? wq : (y == 7) ? wk : (y == 8) ? wv : wo;
        float4* hi = wsp + (size_t)(2 * (y - 6)) * nWW;
        float4* lo = hi + nWW;
        if (i < nWW) {
            float4 v = src[i];
            float4 hv, lv;
            hv.x = f2tf32f(v.x); lv.x = f2tf32f(v.x - hv.x);
            hv.y = f2tf32f(v.y); lv.y = f2tf32f(v.y - hv.y);
            hv.z = f2tf32f(v.z); lv.z = f2tf32f(v.z - hv.z);
            hv.w = f2tf32f(v.w); lv.w = f2tf32f(v.w - hv.w);
            hi[i] = hv;
            lo[i] = lv;
        }
    }
}

// ---------------- RMSNorm: hi+lo split or tf32 copy ----------------
__global__ void rmsnorm_kernel(const float* __restrict__ x,
                               const float* __restrict__ w,
                               float* __restrict__ out,
                               float* __restrict__ outTf,
                               float* __restrict__ outLo) {
    const float* xr = x + (long long)blockIdx.x * H;
    float* orow = out + (long long)blockIdx.x * H;
    __shared__ float red[256];
    float s = 0.f;
    for (int j = threadIdx.x; j < H; j += 256) {
        float v = xr[j];
        s += v * v;
    }
    red[threadIdx.x] = s;
    __syncthreads();
    for (int st = 128; st > 0; st >>= 1) {
        if (threadIdx.x < st) red[threadIdx.x] += red[threadIdx.x + st];
        __syncthreads();
    }
    float inv = 1.0f / sqrtf(red[0] / (float)H + 1e-6f);
    if (outLo) {
        float* lrow = outLo + (long long)blockIdx.x * H;
        for (int j = threadIdx.x; j < H; j += 256) {
            float v = w[j] * xr[j] * inv;
            float hi = f2tf32f(v);
            orow[j] = hi;
            lrow[j] = f2tf32f(v - hi);
        }
    } else if (outTf) {
        float* trow = outTf + (long long)blockIdx.x * H;
        for (int j = threadIdx.x; j < H; j += 256) {
            float v = w[j] * xr[j] * inv;
            orow[j] = v;
            trow[j] = f2tf32f(v);
        }
    } else {
        for (int j = threadIdx.x; j < H; j += 256) orow[j] = w[j] * xr[j] * inv;
    }
}

// ---------------- RoPE: rotate + hi/lo split ----------------
__global__ void rope_kernel(const float* __restrict__ q,
                            const float* __restrict__ k,
                            float* __restrict__ qhi, float* __restrict__ qlo,
                            float* __restrict__ khi, float* __restrict__ klo) {
    int s = blockIdx.x;
    int h = blockIdx.y;
    int j = threadIdx.x;
    float inv = exp2f(-(float)j * 0.31143075889569023f);
    float ang = (float)s * inv;
    float c, sn;
    sincosf(ang, &sn, &c);
    long long base = ((long long)s * NH + h) * D;
    float q1 = q[base + j], q2 = q[base + j + 64];
    float k1 = k[base + j], k2 = k[base + j + 64];
    float qa = q1 * c - q2 * sn;
    float qb = q2 * c + q1 * sn;
    float ka = k1 * c - k2 * sn;
    float kb = k2 * c + k1 * sn;
    float t;
    t = f2tf32f(qa); qhi[base + j] = t; qlo[base + j] = f2tf32f(qa - t);
    t = f2tf32f(qb); qhi[base + j + 64] = t; qlo[base + j + 64] = f2tf32f(qb - t);
    t = f2tf32f(ka); khi[base + j] = t; klo[base + j] = f2tf32f(ka - t);
    t = f2tf32f(kb); khi[base + j + 64] = t; klo[base + j + 64] = f2tf32f(kb - t);
}

// ---------------- causal row softmax, hi/lo output ----------------
__global__ void softmax_kernel(float* __restrict__ scores,
                               float* __restrict__ slo) {
    int r = blockIdx.x;
    float* row = scores + ((size_t)blockIdx.y * S + r) * S;
    float* lrow = slo + ((size_t)blockIdx.y * S + r) * S;
    const int limit = r + 1;
    const int rBlk = ((r >> 7) + 1) << 7;
    __shared__ float red[256];
    int tid = threadIdx.x;
    float m = -FLT_MAX;
    for (int j = tid; j < limit; j += 256) m = fmaxf(m, row[j]);
    red[tid] = m;
    __syncthreads();
    for (int st = 128; st > 0; st >>= 1) {
        if (tid < st) red[tid] = fmaxf(red[tid], red[tid + st]);
        __syncthreads();
    }
    m = red[0];
    __syncthreads();
    float sum = 0.f;
    for (int j = tid; j < limit; j += 256) {
        float e = expf(row[j] - m);
        row[j] = e;
        sum += e;
    }
    red[tid] = sum;
    __syncthreads();
    for (int st = 128; st > 0; st >>= 1) {
        if (tid < st) red[tid] += red[tid + st];
        __syncthreads();
    }
    float inv = 1.0f / red[0];
    for (int j = tid; j < limit; j += 256) {
        float p = row[j] * inv;
        float hi = f2tf32f(p);
        row[j] = hi;
        lrow[j] = f2tf32f(p - hi);
    }
    for (int j = limit + tid; j < rBlk; j += 256) {
        row[j] = 0.f;
        lrow[j] = 0.f;
    }
}

// ---------------- router ----------------
__global__ void router_kernel(const float* __restrict__ h2,
                              const float* __restrict__ gate_w,
                              float* __restrict__ logits_out,
                              int* __restrict__ idxbuf,
                              int* __restrict__ cnt,
                              int* __restrict__ tokmap,
                              float* __restrict__ tokw) {
    int s = blockIdx.x;
    const float* hr = h2 + (long long)s * H;
    __shared__ float red[256][E];
    float p[E];
#pragma unroll
    for (int e = 0; e < E; e++) p[e] = 0.f;
    for (int j = threadIdx.x; j < H; j += 256) {
        float hv = hr[j];
#pragma unroll
        for (int e = 0; e < E; e++) p[e] += hv * gate_w[j * E + e];
    }
#pragma unroll
    for (int e = 0; e < E; e++) red[threadIdx.x][e] = p[e];
    __syncthreads();
    for (int st = 128; st > 0; st >>= 1) {
        if (threadIdx.x < st)
#pragma unroll
            for (int e = 0; e < E; e++) red[threadIdx.x][e] += red[threadIdx.x + st][e];
        __syncthreads();
    }
    if (threadIdx.x == 0) {
        float logit[E];
        float m = -FLT_MAX;
#pragma unroll
        for (int e = 0; e < E; e++) {
            logit[e] = red[0][e];
            logits_out[(long long)s * E + e] = logit[e];
            m = fmaxf(m, logit[e]);
        }
        float sum = 0.f, rw[E];
#pragma unroll
        for (int e = 0; e < E; e++) {
            rw[e] = expf(logit[e] - m);
            sum += rw[e];
        }
        float inv = 1.0f / sum;
#pragma unroll
        for (int e = 0; e < E; e++) rw[e] *= inv;
        bool used[E];
#pragma unroll
        for (int e = 0; e < E; e++) used[e] = false;
        for (int k = 0; k < TOPK; k++) {
            int best = -1;
            float bvv = -FLT_MAX;
            for (int e = 0; e < E; e++)
                if (!used[e] && rw[e] > bvv) { bvv = rw[e]; best = e; }
            used[best] = true;
            int pos = atomicAdd(&cnt[best], 1);
            idxbuf[best * S + pos] = s;
            tokmap[s * TOPK + k] = best * S + pos;
            tokw[s * TOPK + k] = bvv;
        }
    }
}

// ---------------- h2 . sgate ----------------
__global__ void rowdot_kernel(const float* __restrict__ h2,
                              const float* __restrict__ sgate,
                              float* __restrict__ gatev) {
    int s = blockIdx.x;
    const float* hr = h2 + (long long)s * H;
    __shared__ float red[256];
    float acc = 0.f;
    for (int j = threadIdx.x; j < H; j += 256) acc += hr[j] * sgate[j];
    red[threadIdx.x] = acc;
    __syncthreads();
    for (int st = 128; st > 0; st >>= 1) {
        if (threadIdx.x < st) red[threadIdx.x] += red[threadIdx.x + st];
        __syncthreads();
    }
    if (threadIdx.x == 0) gatev[s] = red[0];
}

// ---------------- silu kernels ----------------
__global__ void silu_mul_expert_kernel(float* __restrict__ gb,
                                       const float* __restrict__ ub,
                                       const int* __restrict__ cnt) {
    int e = blockIdx.y;
    long long i = (long long)blockIdx.x * 256 + threadIdx.x;
    long long lim = (long long)cnt[e] * IE;
    if (i >= lim) return;
    size_t o = (size_t)e * S * IE + i;
    float x = gb[o];
    float sg = 1.0f / (1.0f + expf(-x));
    gb[o] = f2tf32f(x * sg * ub[o]);
}
__global__ void silu_mul_kernel(float* __restrict__ g, const float* __restrict__ u,
                                long long n) {
    long long i = (long long)blockIdx.x * 256 + threadIdx.x;
    if (i < n) {
        float x = g[i];
        float sg = 1.0f / (1.0f + expf(-x));
        g[i] = f2tf32f(x * sg * u[i]);
    }
}

// ---------------- final combine ----------------
__global__ void final_kernel(const float* __restrict__ x1,
                             const float* __restrict__ eo,
                             const int* __restrict__ tokmap,
                             const float* __restrict__ tokw,
                             const float* __restrict__ sdwn,
                             const float* __restrict__ gatev,
                             float* __restrict__ out) {
    long long i = (long long)blockIdx.x * 256 + threadIdx.x;
    int s = (int)(i / H);
    int c = (int)(i % H);
    float gv = 1.0f / (1.0f + expf(-gatev[s]));
    float acc = x1[i] + gv * sdwn[i];
#pragma unroll
    for (int j = 0; j < TOPK; j++) {
        int row = tokmap[s * TOPK + j];
        acc += tokw[s * TOPK + j] * eo[(size_t)row * H + c];
    }
    out[i] = acc;
}

// ---------------- host ----------------
static void launch_mma(const float* A, int lda, long long aStrE,
                       const float* B0, const float* B1, int ldb, long long bStrE,
                       float* C0, float* C1, int ldc, long long cStrE,
                       int M, int N, int K,
                       const int* gidx, int gstr, const int* cnt, int eShift,
                       int nz) {
    dim3 grid(N / 128, (M + 127) / 128, nz);
    mma_gemm_kernel<<<grid, 128, MMA_SMEM>>>(A, lda, aStrE, B0, B1, ldb, bStrE,
                                             C0, C1, ldc, cStrE, M, N, K,
                                             gidx, gstr, cnt, eShift);
}

extern "C" void kernel_launch(void* const* d_in, const int* in_sizes, int n_in,
                              void* d_out, int out_size) {
    (void)in_sizes; (void)n_in; (void)out_size;
    const float* x     = (const float*)d_in[0];
    const float* ln1   = (const float*)d_in[1];
    const float* ln2   = (const float*)d_in[2];
    const float* wq    = (const float*)d_in[3];
    const float* bq    = (const float*)d_in[4];
    const float* wk    = (const float*)d_in[5];
    const float* bk    = (const float*)d_in[6];
    const float* wv    = (const float*)d_in[7];
    const float* bv    = (const float*)d_in[8];
    const float* wo    = (const float*)d_in[9];
    const float* gatew = (const float*)d_in[10];
    const float* eg    = (const float*)d_in[11];
    const float* eu    = (const float*)d_in[12];
    const float* ed    = (const float*)d_in[13];
    const float* sg    = (const float*)d_in[14];
    const float* su    = (const float*)d_in[15];
    const float* sd    = (const float*)d_in[16];
    const float* sgate = (const float*)d_in[17];
    float* out = (float*)d_out;

    cudaFuncSetAttribute(mma_gemm_kernel,
                         cudaFuncAttributeMaxDynamicSharedMemorySize, MMA_SMEM);
    cudaFuncSetAttribute(mma3x_kernel,
                         cudaFuncAttributeMaxDynamicSharedMemorySize, X_SMEM);
    cudaFuncSetAttribute(sc3x_kernel,
                         cudaFuncAttributeMaxDynamicSharedMemorySize, SC_SMEM);
    cudaFuncSetAttribute(pv3x_kernel,
                         cudaFuncAttributeMaxDynamicSharedMemorySize, X_SMEM);

    float *hhi, *hlo, *q, *k, *qhi, *qlo, *khi, *klo, *vhi, *vlo, *scores,
        *slo, *ahi, *alo, *x1, *h2, *ch2, *gb, *ub, *eo, *sgb, *sub,
        *sdwn, *gatev, *tokw, *wsp;
    float *ceg, *ceu, *ced, *csg, *csu, *csd;
    int *idx, *cnt, *tokmap;
    cudaGetSymbolAddress((void**)&hhi, g_hhi);
    cudaGetSymbolAddress((void**)&hlo, g_hlo);
    cudaGetSymbolAddress((void**)&q, g_q);
    cudaGetSymbolAddress((void**)&k, g_k);
    cudaGetSymbolAddress((void**)&qhi, g_qhi);
    cudaGetSymbolAddress((void**)&qlo, g_qlo);
    cudaGetSymbolAddress((void**)&khi, g_khi);
    cudaGetSymbolAddress((void**)&klo, g_klo);
    cudaGetSymbolAddress((void**)&vhi, g_vhi);
    cudaGetSymbolAddress((void**)&vlo, g_vlo);
    cudaGetSymbolAddress((void**)&scores, g_scores);
    cudaGetSymbolAddress((void**)&slo, g_slo);
    cudaGetSymbolAddress((void**)&ahi, g_ahi);
    cudaGetSymbolAddress((void**)&alo, g_alo);
    cudaGetSymbolAddress((void**)&x1, g_x1);
    cudaGetSymbolAddress((void**)&h2, g_h2);
    cudaGetSymbolAddress((void**)&ch2, g_ch2);
    cudaGetSymbolAddress((void**)&gb, g_gb);
    cudaGetSymbolAddress((void**)&ub, g_ub);
    cudaGetSymbolAddress((void**)&eo, g_eo);
    cudaGetSymbolAddress((void**)&sgb, g_sgb);
    cudaGetSymbolAddress((void**)&sub, g_sub);
    cudaGetSymbolAddress((void**)&sdwn, g_sdwn);
    cudaGetSymbolAddress((void**)&gatev, g_gatev);
    cudaGetSymbolAddress((void**)&idx, g_idx);
    cudaGetSymbolAddress((void**)&cnt, g_cnt);
    cudaGetSymbolAddress((void**)&tokmap, g_tokmap);
    cudaGetSymbolAddress((void**)&tokw, g_tokw);
    cudaGetSymbolAddress((void**)&ceg, g_ceg);
    cudaGetSymbolAddress((void**)&ceu, g_ceu);
    cudaGetSymbolAddress((void**)&ced, g_ced);
    cudaGetSymbolAddress((void**)&csg, g_csg);
    cudaGetSymbolAddress((void**)&csu, g_csu);
    cudaGetSymbolAddress((void**)&csd, g_csd);
    cudaGetSymbolAddress((void**)&wsp, g_wsp);

    const size_t WW = (size_t)H * H;
    const float* wqh = wsp;
    const float* wql = wsp + WW;
    const float* wkh = wsp + 2 * WW;
    const float* wkl = wsp + 3 * WW;
    const float* wvh = wsp + 4 * WW;
    const float* wvl = wsp + 5 * WW;
    const float* woh = wsp + 6 * WW;
    const float* wol = wsp + 7 * WW;

    const float ascale = 0.08838834764831845f;

    // 0. weight prep (one launch)
    {
        long long nEG = (long long)E * H * IE / 4;
        unsigned gx = (unsigned)((nEG + 255) / 256);
        dim3 grid(gx, 10);
        prep_kernel<<<grid, 256>>>(
            (const float4*)eg, (float4*)ceg, (const float4*)eu, (float4*)ceu,
            (const float4*)ed, (float4*)ced, (const float4*)sg, (float4*)csg,
            (const float4*)su, (float4*)csu, (const float4*)sd, (float4*)csd,
            (const float4*)wq, (const float4*)wk, (const float4*)wv,
            (const float4*)wo, (float4*)wsp);
    }

    // 1. h = rmsnorm(x, ln1), hi/lo split
    rmsnorm_kernel<<<S, 256>>>(x, ln1, hhi, nullptr, hlo);

    // 2. q,k,v via 3xTF32; v written pre-split (hi->vhi, lo->vlo)
    {
        dim3 grid(16, 16, 3);
        mma3x_kernel<<<grid, 128, X_SMEM>>>(
            hhi, hlo, H, wqh, wql, wkh, wkl, wvh, wvl, NH * D,
            bq, bk, bv, q, k, vhi, vlo, NH * D, nullptr, H);
    }

    // 3. RoPE + q/k hi-lo split
    rope_kernel<<<dim3(S, NH), 64>>>(q, k, qhi, qlo, khi, klo);

    // 4. scores via 3xTF32 (causal blocks only)
    {
        dim3 grid(S / 128, S / 128, NH);
        sc3x_kernel<<<grid, 128, SC_SMEM>>>(qhi, qlo, khi, klo, scores, ascale);
    }

    // 5. softmax -> probs hi (in place) + lo
    softmax_kernel<<<dim3(S, NH), 256>>>(scores, slo);

    // 6. attn = probs @ v via 3xTF32 (K bounded at diagonal); writes ahi/alo
    {
        dim3 grid(1, S / 128, NH);
        pv3x_kernel<<<grid, 128, X_SMEM>>>(scores, slo, vhi, vlo, ahi, alo);
    }

    // 7. x1 = x + attn @ wo via 3xTF32
    {
        dim3 grid(16, 16, 1);
        mma3x_kernel<<<grid, 128, X_SMEM>>>(
            ahi, alo, NH * D, woh, wol, nullptr, nullptr, nullptr, nullptr, H,
            nullptr, nullptr, nullptr, x1, nullptr, nullptr, nullptr, H, x,
            NH * D);
    }

    // 8. h2 = rmsnorm(x1, ln2) + tf32 copy
    rmsnorm_kernel<<<S, 256>>>(x1, ln2, h2, ch2, nullptr);

    // 9. router
    cudaMemsetAsync(cnt, 0, E * sizeof(int));
    router_kernel<<<S, 256>>>(h2, gatew, out + (long long)S * H, idx, cnt,
                              tokmap, tokw);

    // 10. MoE gate+up
    launch_mma(ch2, H, 0, ceg, ceu, IE, (long long)H * IE,
               gb, ub, IE, (long long)S * IE, S, IE, H, idx, S, cnt, 1, 2 * E);

    // 11. silu
    {
        dim3 grid((unsigned)(((long long)S * IE + 255) / 256), E);
        silu_mul_expert_kernel<<<grid, 256>>>(gb, ub, cnt);
    }

    // 12. MoE down
    launch_mma(gb, IE, (long long)S * IE, ced, nullptr, H, (long long)IE * H,
               eo, nullptr, H, (long long)S * H, S, H, IE, nullptr, 0, cnt, 0, E);

    // 13. shared expert
    launch_mma(ch2, H, 0, csg, csu, IS, 0, sgb, sub, IS, 0, S, IS, H,
               nullptr, 0, nullptr, 1, 2);
    {
        long long n = (long long)S * IS;
        silu_mul_kernel<<<(unsigned)((n + 255) / 256), 256>>>(sgb, sub, n);
    }
    launch_mma(sgb, IS, 0, csd, nullptr, H, 0, sdwn, nullptr, H, 0, S, H, IS,
               nullptr, 0, nullptr, 0, 1);

    // 14. gate scalar
    rowdot_kernel<<<S, 256>>>(h2, sgate, gatev);

    // 15. combine
    final_kernel<<<(S * H) / 256, 256>>>(x1, eo, tokmap, tokw, sdwn, gatev, out);
}

// round 14
// speedup vs baseline: 1.1073x; 1.1073x over previous
#include <cuda_runtime.h>
#include <cuda_bf16.h>
#include <math.h>
#include <float.h>
#include <stdint.h>

#define S 2048
#define H 2048
#define NH 16
#define D 128
#define E 8
#define TOPK 4
#define IE 1408
#define IS 5632

// ---------------- scratch ----------------
__device__ float g_hhi[S * H];
__device__ float g_hlo[S * H];
__device__ float g_q[S * H];
__device__ float g_k[S * H];
__device__ float g_qhi[S * H];
__device__ float g_qlo[S * H];
__device__ float g_khi[S * H];
__device__ float g_klo[S * H];
__device__ float g_vhi[S * H];
__device__ float g_vlo[S * H];
__device__ float g_scores[(size_t)NH * S * S];
__device__ float g_slo[(size_t)NH * S * S];
__device__ float g_ahi[S * H];
__device__ float g_alo[S * H];
__device__ float g_x1[S * H];
__device__ float g_h2[S * H];
__device__ float g_ch2[S * H];
__device__ float g_gb[(size_t)E * S * IE];
__device__ float g_ub[(size_t)E * S * IE];
__device__ float g_eo[(size_t)E * S * H];
__device__ float g_sgb[S * IS];
__device__ float g_sub[S * IS];
__device__ float g_sdwn[S * H];
__device__ float g_gatev[S];
__device__ int g_idx[E * S];
__device__ int g_cnt[E];
__device__ int g_tokmap[S * TOPK];
__device__ float g_tokw[S * TOPK];
__device__ float g_ceg[(size_t)E * H * IE];
__device__ float g_ceu[(size_t)E * H * IE];
__device__ float g_ced[(size_t)E * IE * H];
__device__ float g_csg[(size_t)H * IS];
__device__ float g_csu[(size_t)H * IS];
__device__ float g_csd[(size_t)IS * H];
__device__ float g_wsp[(size_t)8 * H * H];

// ================= helpers =================
__device__ __forceinline__ uint32_t smem_to_u32(const void* p) {
    uint32_t a;
    asm("{ .reg .u64 t; cvta.to.shared.u64 t, %1; cvt.u32.u64 %0, t; }"
        : "=r"(a) : "l"(p));
    return a;
}
__device__ __forceinline__ float f2tf32f(float f) {
    uint32_t r;
    asm("cvt.rna.tf32.f32 %0, %1;" : "=r"(r) : "f"(f));
    return __uint_as_float(r);
}
__device__ __forceinline__ void mma_tf32(float* d, const uint32_t* a,
                                         const uint32_t* b) {
    asm volatile(
        "mma.sync.aligned.m16n8k8.row.col.f32.tf32.tf32.f32 "
        "{%0,%1,%2,%3}, {%4,%5,%6,%7}, {%8,%9}, {%0,%1,%2,%3};"
        : "+f"(d[0]), "+f"(d[1]), "+f"(d[2]), "+f"(d[3])
        : "r"(a[0]), "r"(a[1]), "r"(a[2]), "r"(a[3]), "r"(b[0]), "r"(b[1]));
}
__device__ __forceinline__ void cp_async16(uint32_t dst, const void* src) {
    asm volatile("cp.async.ca.shared.global [%0], [%1], 16;"
                 :: "r"(dst), "l"(src));
}

// ================= tf32 mma GEMM v3 (MoE path, 4-stage — round-11 exact) ======
#define APADF 20
#define BPADF 136
#define A_STAGE_B (128 * APADF * 4)
#define B_STAGE_B (16 * BPADF * 4)
#define STAGE_B (A_STAGE_B + B_STAGE_B)
#define MMA_SMEM (STAGE_B * 4)

__global__ __launch_bounds__(128, 2)
void mma_gemm_kernel(const float* __restrict__ A, int lda, long long aStrE,
                     const float* __restrict__ B0, const float* __restrict__ B1,
                     int ldb, long long bStrE,
                     float* __restrict__ C0, float* __restrict__ C1,
                     int ldc, long long cStrE,
                     int M, int N, int K,
                     const int* __restrict__ gidxBase, int gidxStr,
                     const int* __restrict__ cntBase, int eShift) {
    extern __shared__ char smem[];
    const uint32_t sb = smem_to_u32(smem);
    const int z = blockIdx.z;
    const int e = z >> eShift;
    const int which = z & ((1 << eShift) - 1);
    const float* B = (which ? B1 : B0) + (long long)e * bStrE;
    float* C = (which ? C1 : C0) + (long long)e * cStrE;
    A += (long long)e * aStrE;

    const int cnt = cntBase ? cntBase[e] : M;
    const int mEff = min(M, cnt);
    const int row0 = blockIdx.y * 128;
    const int col0 = blockIdx.x * 128;
    if (row0 >= mEff) return;
    const int* gidx = gidxBase ? gidxBase + (long long)e * gidxStr : nullptr;

    const int tid = threadIdx.x;
    const int wid = tid >> 5;
    const int lane = tid & 31;
    const int g = lane >> 2;
    const int t4 = lane & 3;
    const int warpM = wid >> 1;
    const int warpN = wid & 1;

    const float* aG[4];
    uint32_t aS[4];
#pragma unroll
    for (int j = 0; j < 4; j++) {
        int u = tid + 128 * j;
        int m = u >> 2, c4 = u & 3;
        int arow = row0 + m;
        int src;
        if (gidx) src = (arow < cnt) ? gidx[arow] : 0;
        else src = min(arow, M - 1);
        aG[j] = A + (size_t)src * lda + c4 * 4;
        aS[j] = sb + (uint32_t)(m * APADF + c4 * 4) * 4u;
    }
    const float* bG[4];
    uint32_t bS[4];
#pragma unroll
    for (int j = 0; j < 4; j++) {
        int u = tid + 128 * j;
        int n4 = u & 31, kk = u >> 5;
        bG[j] = B + (size_t)kk * ldb + col0 + n4 * 4;
        bS[j] = sb + A_STAGE_B + (uint32_t)(kk * BPADF + n4 * 4) * 4u;
    }

    float acc[4][8][4];
#pragma unroll
    for (int mt = 0; mt < 4; mt++)
#pragma unroll
        for (int nt = 0; nt < 8; nt++)
#pragma unroll
            for (int r = 0; r < 4; r++) acc[mt][nt][r] = 0.f;

    const int nT = K / 16;

#define ISSUE(i)                                                      \
    do {                                                              \
        uint32_t _off = (uint32_t)((i) & 3) * STAGE_B;                \
        int _k0 = (i) * 16;                                           \
        cp_async16(aS[0] + _off, aG[0] + _k0);                        \
        cp_async16(aS[1] + _off, aG[1] + _k0);                        \
        cp_async16(aS[2] + _off, aG[2] + _k0);                        \
        cp_async16(aS[3] + _off, aG[3] + _k0);                        \
        cp_async16(bS[0] + _off, bG[0] + (size_t)_k0 * ldb);          \
        cp_async16(bS[1] + _off, bG[1] + (size_t)_k0 * ldb);          \
        cp_async16(bS[2] + _off, bG[2] + (size_t)_k0 * ldb);          \
        cp_async16(bS[3] + _off, bG[3] + (size_t)_k0 * ldb);          \
        asm volatile("cp.async.commit_group;");                       \
    } while (0)

    ISSUE(0);
    if (nT > 1) ISSUE(1);
    if (nT > 2) ISSUE(2);

    for (int i = 0; i < nT; i++) {
        const int rem = nT - 1 - i;
        if (rem >= 2)
            asm volatile("cp.async.wait_group 2;");
        else if (rem == 1)
            asm volatile("cp.async.wait_group 1;");
        else
            asm volatile("cp.async.wait_group 0;");
        __syncthreads();
        if (i + 3 < nT) ISSUE(i + 3);

        const uint32_t* Asb =
            (const uint32_t*)(smem + (size_t)(i & 3) * STAGE_B);
        const uint32_t* Bsb =
            (const uint32_t*)(smem + (size_t)(i & 3) * STAGE_B + A_STAGE_B);
#pragma unroll
        for (int kk = 0; kk < 16; kk += 8) {
            uint32_t a[4][4], b[8][2];
#pragma unroll
            for (int mt = 0; mt < 4; mt++) {
                int mrow = warpM * 64 + mt * 16;
                a[mt][0] = Asb[(mrow + g) * APADF + kk + t4];
                a[mt][1] = Asb[(mrow + g + 8) * APADF + kk + t4];
                a[mt][2] = Asb[(mrow + g) * APADF + kk + t4 + 4];
                a[mt][3] = Asb[(mrow + g + 8) * APADF + kk + t4 + 4];
            }
#pragma unroll
            for (int nt = 0; nt < 8; nt++) {
                int ncol = warpN * 64 + nt * 8;
                b[nt][0] = Bsb[(kk + t4) * BPADF + ncol + g];
                b[nt][1] = Bsb[(kk + t4 + 4) * BPADF + ncol + g];
            }
#pragma unroll
            for (int mt = 0; mt < 4; mt++)
#pragma unroll
                for (int nt = 0; nt < 8; nt++)
                    mma_tf32(acc[mt][nt], a[mt], b[nt]);
        }
    }
#undef ISSUE

#pragma unroll
    for (int mt = 0; mt < 4; mt++) {
        int rBase = row0 + warpM * 64 + mt * 16 + g;
#pragma unroll
        for (int half = 0; half < 2; half++) {
            int r = rBase + half * 8;
            if (r >= mEff) continue;
            float* cp = C + (size_t)r * ldc;
#pragma unroll
            for (int nt = 0; nt < 8; nt++) {
                int col = col0 + warpN * 64 + nt * 8 + t4 * 2;
                cp[col] = acc[mt][nt][half * 2 + 0];
                cp[col + 1] = acc[mt][nt][half * 2 + 1];
            }
        }
    }
}

// ================= 3xTF32 mma GEMM (QKV / wo) ==========
#define X_APAD 12
#define X_BPAD 136
#define X_A_B (128 * X_APAD * 4)
#define X_B_B (8 * X_BPAD * 4)
#define X_STAGE (2 * X_A_B + 2 * X_B_B)
#define X_SMEM (X_STAGE * 4)

__global__ __launch_bounds__(128, 2)
void mma3x_kernel(const float* __restrict__ Ahi, const float* __restrict__ Alo,
                  int lda,
                  const float* __restrict__ B0h, const float* __restrict__ B0l,
                  const float* __restrict__ B1h, const float* __restrict__ B1l,
                  const float* __restrict__ B2h, const float* __restrict__ B2l,
                  int ldb,
                  const float* __restrict__ bias0,
                  const float* __restrict__ bias1,
                  const float* __restrict__ bias2,
                  float* __restrict__ C0, float* __restrict__ C1,
                  float* __restrict__ C2, float* __restrict__ C2lo, int ldc,
                  const float* __restrict__ residual,
                  int K) {
    extern __shared__ char smem[];
    const uint32_t sb = smem_to_u32(smem);
    const int z = blockIdx.z;
    const float* Bh = (z == 0) ? B0h : (z == 1 ? B1h : B2h);
    const float* Bl = (z == 0) ? B0l : (z == 1 ? B1l : B2l);
    const float* bias = (z == 0) ? bias0 : (z == 1 ? bias1 : bias2);
    float* C = (z == 0) ? C0 : (z == 1 ? C1 : C2);
    float* Clo = (z == 2) ? C2lo : nullptr;

    const int row0 = blockIdx.y * 128;
    const int col0 = blockIdx.x * 128;

    const int tid = threadIdx.x;
    const int wid = tid >> 5;
    const int lane = tid & 31;
    const int g = lane >> 2;
    const int t4 = lane & 3;
    const int warpM = wid >> 1;
    const int warpN = wid & 1;

    const long long aLoD = Alo - Ahi;
    const long long bLoD = Bl - Bh;

    const float* aGh[2];
    uint32_t aSh[2];
#pragma unroll
    for (int j = 0; j < 2; j++) {
        int u = tid + 128 * j;
        int m = u >> 1, c4 = u & 1;
        aGh[j] = Ahi + (size_t)(row0 + m) * lda + c4 * 4;
        aSh[j] = sb + (uint32_t)(m * X_APAD + c4 * 4) * 4u;
    }
    const float* bGh[2];
    uint32_t bSh[2];
#pragma unroll
    for (int j = 0; j < 2; j++) {
        int u = tid + 128 * j;
        int kk = u >> 5, n4 = u & 31;
        bGh[j] = Bh + (size_t)kk * ldb + col0 + n4 * 4;
        bSh[j] = sb + (uint32_t)(2 * X_A_B) +
                 (uint32_t)(kk * X_BPAD + n4 * 4) * 4u;
    }

    float acc[4][8][4];
#pragma unroll
    for (int mt = 0; mt < 4; mt++)
#pragma unroll
        for (int nt = 0; nt < 8; nt++)
#pragma unroll
            for (int r = 0; r < 4; r++) acc[mt][nt][r] = 0.f;

    const int nT = K / 8;

#define XISSUE(i)                                                       \
    do {                                                                \
        uint32_t _off = (uint32_t)((i) & 3) * X_STAGE;                  \
        int _k0 = (i) * 8;                                              \
        cp_async16(aSh[0] + _off, aGh[0] + _k0);                        \
        cp_async16(aSh[1] + _off, aGh[1] + _k0);                        \
        cp_async16(aSh[0] + X_A_B + _off, aGh[0] + aLoD + _k0);         \
        cp_async16(aSh[1] + X_A_B + _off, aGh[1] + aLoD + _k0);         \
        cp_async16(bSh[0] + _off, bGh[0] + (size_t)_k0 * ldb);          \
        cp_async16(bSh[1] + _off, bGh[1] + (size_t)_k0 * ldb);          \
        cp_async16(bSh[0] + X_B_B + _off, bGh[0] + bLoD + (size_t)_k0 * ldb); \
        cp_async16(bSh[1] + X_B_B + _off, bGh[1] + bLoD + (size_t)_k0 * ldb); \
        asm volatile("cp.async.commit_group;");                         \
    } while (0)

    XISSUE(0);
    XISSUE(1);
    XISSUE(2);

    for (int i = 0; i < nT; i++) {
        const int rem = nT - 1 - i;
        if (rem >= 2)
            asm volatile("cp.async.wait_group 2;");
        else if (rem == 1)
            asm volatile("cp.async.wait_group 1;");
        else
            asm volatile("cp.async.wait_group 0;");
        __syncthreads();
        if (i + 3 < nT) XISSUE(i + 3);

        const uint32_t* Ah = (const uint32_t*)(smem + (size_t)(i & 3) * X_STAGE);
        const uint32_t* Al = Ah + (X_A_B / 4);
        const uint32_t* Bhs =
            (const uint32_t*)(smem + (size_t)(i & 3) * X_STAGE + 2 * X_A_B);
        const uint32_t* Bls = Bhs + (X_B_B / 4);

        uint32_t ah[4][4], al[4][4], bh[8][2], bl[8][2];
#pragma unroll
        for (int mt = 0; mt < 4; mt++) {
            int mrow = warpM * 64 + mt * 16;
            ah[mt][0] = Ah[(mrow + g) * X_APAD + t4];
            ah[mt][1] = Ah[(mrow + g + 8) * X_APAD + t4];
            ah[mt][2] = Ah[(mrow + g) * X_APAD + t4 + 4];
            ah[mt][3] = Ah[(mrow + g + 8) * X_APAD + t4 + 4];
            al[mt][0] = Al[(mrow + g) * X_APAD + t4];
            al[mt][1] = Al[(mrow + g + 8) * X_APAD + t4];
            al[mt][2] = Al[(mrow + g) * X_APAD + t4 + 4];
            al[mt][3] = Al[(mrow + g + 8) * X_APAD + t4 + 4];
        }
#pragma unroll
        for (int nt = 0; nt < 8; nt++) {
            int ncol = warpN * 64 + nt * 8;
            bh[nt][0] = Bhs[t4 * X_BPAD + ncol + g];
            bh[nt][1] = Bhs[(t4 + 4) * X_BPAD + ncol + g];
            bl[nt][0] = Bls[t4 * X_BPAD + ncol + g];
            bl[nt][1] = Bls[(t4 + 4) * X_BPAD + ncol + g];
        }
#pragma unroll
        for (int mt = 0; mt < 4; mt++)
#pragma unroll
            for (int nt = 0; nt < 8; nt++) {
                mma_tf32(acc[mt][nt], ah[mt], bh[nt]);
                mma_tf32(acc[mt][nt], ah[mt], bl[nt]);
                mma_tf32(acc[mt][nt], al[mt], bh[nt]);
            }
    }
#undef XISSUE

#pragma unroll
    for (int mt = 0; mt < 4; mt++) {
        int rBase = row0 + warpM * 64 + mt * 16 + g;
#pragma unroll
        for (int half = 0; half < 2; half++) {
            int r = rBase + half * 8;
            float* cp = C + (size_t)r * ldc;
            float* cl = Clo ? Clo + (size_t)r * ldc : nullptr;
            const float* rp = residual ? residual + (size_t)r * ldc : nullptr;
#pragma unroll
            for (int nt = 0; nt < 8; nt++) {
                int col = col0 + warpN * 64 + nt * 8 + t4 * 2;
                float v0 = acc[mt][nt][half * 2 + 0];
                float v1 = acc[mt][nt][half * 2 + 1];
                if (bias) {
                    v0 += bias[col];
                    v1 += bias[col + 1];
                }
                if (rp) {
                    v0 += rp[col];
                    v1 += rp[col + 1];
                }
                if (cl) {
                    float h0 = f2tf32f(v0), h1 = f2tf32f(v1);
                    cp[col] = h0;
                    cp[col + 1] = h1;
                    cl[col] = f2tf32f(v0 - h0);
                    cl[col + 1] = f2tf32f(v1 - h1);
                } else {
                    cp[col] = v0;
                    cp[col + 1] = v1;
                }
            }
        }
    }
}

// ================= 3xTF32 scores kernel (Q·K^T, causal) =======================
#define SC_HALF (128 * X_APAD * 4)
#define SC_STAGE (4 * SC_HALF)
#define SC_SMEM (SC_STAGE * 3)

__global__ __launch_bounds__(128, 2)
void sc3x_kernel(const float* __restrict__ qhi, const float* __restrict__ qlo,
                 const float* __restrict__ khi, const float* __restrict__ klo,
                 float* __restrict__ scores, float scale) {
    extern __shared__ char smem[];
    const uint32_t sb = smem_to_u32(smem);
    const int h = blockIdx.z;
    const int row0 = blockIdx.y * 128;
    const int col0 = blockIdx.x * 128;
    if (col0 > row0) return;

    const int lda = NH * D;
    const float* Ah = qhi + (size_t)h * D;
    const float* Bh = khi + (size_t)h * D;
    const long long aLoD = qlo - qhi;
    const long long bLoD = klo - khi;

    const int tid = threadIdx.x;
    const int wid = tid >> 5;
    const int lane = tid & 31;
    const int g = lane >> 2;
    const int t4 = lane & 3;
    const int warpM = wid >> 1;
    const int warpN = wid & 1;

    const float* aGh[2];
    uint32_t aSh[2];
    const float* bGh[2];
    uint32_t bSh[2];
#pragma unroll
    for (int j = 0; j < 2; j++) {
        int u = tid + 128 * j;
        int m = u >> 1, c4 = u & 1;
        aGh[j] = Ah + (size_t)(row0 + m) * lda + c4 * 4;
        aSh[j] = sb + (uint32_t)(m * X_APAD + c4 * 4) * 4u;
        bGh[j] = Bh + (size_t)(col0 + m) * lda + c4 * 4;
        bSh[j] = sb + (uint32_t)(2 * SC_HALF) +
                 (uint32_t)(m * X_APAD + c4 * 4) * 4u;
    }

    float acc[4][8][4];
#pragma unroll
    for (int mt = 0; mt < 4; mt++)
#pragma unroll
        for (int nt = 0; nt < 8; nt++)
#pragma unroll
            for (int r = 0; r < 4; r++) acc[mt][nt][r] = 0.f;

    const int nT = D / 8;
    const uint32_t stOff[3] = {0u, SC_STAGE, 2u * SC_STAGE};

#define SISSUE(i, st)                                                  \
    do {                                                               \
        uint32_t _off = stOff[st];                                     \
        int _k0 = (i) * 8;                                             \
        cp_async16(aSh[0] + _off, aGh[0] + _k0);                       \
        cp_async16(aSh[1] + _off, aGh[1] + _k0);                       \
        cp_async16(aSh[0] + SC_HALF + _off, aGh[0] + aLoD + _k0);      \
        cp_async16(aSh[1] + SC_HALF + _off, aGh[1] + aLoD + _k0);      \
        cp_async16(bSh[0] + _off, bGh[0] + _k0);                       \
        cp_async16(bSh[1] + _off, bGh[1] + _k0);                       \
        cp_async16(bSh[0] + SC_HALF + _off, bGh[0] + bLoD + _k0);      \
        cp_async16(bSh[1] + SC_HALF + _off, bGh[1] + bLoD + _k0);      \
        asm volatile("cp.async.commit_group;");                        \
    } while (0)

    SISSUE(0, 0);
    SISSUE(1, 1);

    int stC = 0, stI = 2;
    for (int i = 0; i < nT; i++) {
        if (i + 1 < nT)
            asm volatile("cp.async.wait_group 1;");
        else
            asm volatile("cp.async.wait_group 0;");
        __syncthreads();
        if (i + 2 < nT) {
            SISSUE(i + 2, stI);
            stI = (stI == 2) ? 0 : stI + 1;
        }
        const uint32_t* Ah2 = (const uint32_t*)(smem + stOff[stC]);
        const uint32_t* Al2 = Ah2 + (SC_HALF / 4);
        const uint32_t* Bh2 = (const uint32_t*)(smem + stOff[stC] + 2 * SC_HALF);
        const uint32_t* Bl2 = Bh2 + (SC_HALF / 4);
        stC = (stC == 2) ? 0 : stC + 1;

        uint32_t ah[4][4], al[4][4], bh[8][2], bl[8][2];
#pragma unroll
        for (int mt = 0; mt < 4; mt++) {
            int mrow = warpM * 64 + mt * 16;
            ah[mt][0] = Ah2[(mrow + g) * X_APAD + t4];
            ah[mt][1] = Ah2[(mrow + g + 8) * X_APAD + t4];
            ah[mt][2] = Ah2[(mrow + g) * X_APAD + t4 + 4];
            ah[mt][3] = Ah2[(mrow + g + 8) * X_APAD + t4 + 4];
            al[mt][0] = Al2[(mrow + g) * X_APAD + t4];
            al[mt][1] = Al2[(mrow + g + 8) * X_APAD + t4];
            al[mt][2] = Al2[(mrow + g) * X_APAD + t4 + 4];
            al[mt][3] = Al2[(mrow + g + 8) * X_APAD + t4 + 4];
        }
#pragma unroll
        for (int nt = 0; nt < 8; nt++) {
            int ncol = warpN * 64 + nt * 8;
            bh[nt][0] = Bh2[(ncol + g) * X_APAD + t4];
            bh[nt][1] = Bh2[(ncol + g) * X_APAD + t4 + 4];
            bl[nt][0] = Bl2[(ncol + g) * X_APAD + t4];
            bl[nt][1] = Bl2[(ncol + g) * X_APAD + t4 + 4];
        }
#pragma unroll
        for (int mt = 0; mt < 4; mt++)
#pragma unroll
            for (int nt = 0; nt < 8; nt++) {
                mma_tf32(acc[mt][nt], ah[mt], bh[nt]);
                mma_tf32(acc[mt][nt], ah[mt], bl[nt]);
                mma_tf32(acc[mt][nt], al[mt], bh[nt]);
            }
    }
#undef SISSUE

    float* Cbase = scores + (size_t)h * S * S;
#pragma unroll
    for (int mt = 0; mt < 4; mt++) {
        int rBase = row0 + warpM * 64 + mt * 16 + g;
#pragma unroll
        for (int half = 0; half < 2; half++) {
            int r = rBase + half * 8;
            float* cp = Cbase + (size_t)r * S;
#pragma unroll
            for (int nt = 0; nt < 8; nt++) {
                int col = col0 + warpN * 64 + nt * 8 + t4 * 2;
                float v0 = acc[mt][nt][half * 2 + 0] * scale;
                float v1 = acc[mt][nt][half * 2 + 1] * scale;
                if (col > r) v0 = -3.4028234663852886e38f;
                if (col + 1 > r) v1 = -3.4028234663852886e38f;
                cp[col] = v0;
                cp[col + 1] = v1;
            }
        }
    }
}

// ================= 3xTF32 PV kernel (probs·V, kLimit, split output) ===========
__global__ __launch_bounds__(128, 2)
void pv3x_kernel(const float* __restrict__ phi, const float* __restrict__ plo,
                 const float* __restrict__ vhi, const float* __restrict__ vlo,
                 float* __restrict__ ahiOut, float* __restrict__ aloOut) {
    extern __shared__ char smem[];
    const uint32_t sb = smem_to_u32(smem);
    const int h = blockIdx.z;
    const int row0 = blockIdx.y * 128;

    const int lda = S;
    const int ldb = NH * D;
    const float* Ah = phi + (size_t)h * S * S;
    const float* Bh = vhi + (size_t)h * D;
    const long long aLoD = plo - phi;
    const long long bLoD = vlo - vhi;

    const int tid = threadIdx.x;
    const int wid = tid >> 5;
    const int lane = tid & 31;
    const int g = lane >> 2;
    const int t4 = lane & 3;
    const int warpM = wid >> 1;
    const int warpN = wid & 1;

    const float* aGh[2];
    uint32_t aSh[2];
#pragma unroll
    for (int j = 0; j < 2; j++) {
        int u = tid + 128 * j;
        int m = u >> 1, c4 = u & 1;
        aGh[j] = Ah + (size_t)(row0 + m) * lda + c4 * 4;
        aSh[j] = sb + (uint32_t)(m * X_APAD + c4 * 4) * 4u;
    }
    const float* bGh[2];
    uint32_t bSh[2];
#pragma unroll
    for (int j = 0; j < 2; j++) {
        int u = tid + 128 * j;
        int kk = u >> 5, n4 = u & 31;
        bGh[j] = Bh + (size_t)kk * ldb + n4 * 4;
        bSh[j] = sb + (uint32_t)(2 * X_A_B) +
                 (uint32_t)(kk * X_BPAD + n4 * 4) * 4u;
    }

    float acc[4][8][4];
#pragma unroll
    for (int mt = 0; mt < 4; mt++)
#pragma unroll
        for (int nt = 0; nt < 8; nt++)
#pragma unroll
            for (int r = 0; r < 4; r++) acc[mt][nt][r] = 0.f;

    const int nT = (row0 + 128) / 8;

#define PISSUE(i)                                                       \
    do {                                                                \
        uint32_t _off = (uint32_t)((i) & 3) * X_STAGE;                  \
        int _k0 = (i) * 8;                                              \
        cp_async16(aSh[0] + _off, aGh[0] + _k0);                        \
        cp_async16(aSh[1] + _off, aGh[1] + _k0);                        \
        cp_async16(aSh[0] + X_A_B + _off, aGh[0] + aLoD + _k0);         \
        cp_async16(aSh[1] + X_A_B + _off, aGh[1] + aLoD + _k0);         \
        cp_async16(bSh[0] + _off, bGh[0] + (size_t)_k0 * ldb);          \
        cp_async16(bSh[1] + _off, bGh[1] + (size_t)_k0 * ldb);          \
        cp_async16(bSh[0] + X_B_B + _off, bGh[0] + bLoD + (size_t)_k0 * ldb); \
        cp_async16(bSh[1] + X_B_B + _off, bGh[1] + bLoD + (size_t)_k0 * ldb); \
        asm volatile("cp.async.commit_group;");                         \
    } while (0)

    PISSUE(0);
    PISSUE(1);
    PISSUE(2);

    for (int i = 0; i < nT; i++) {
        const int rem = nT - 1 - i;
        if (rem >= 2)
            asm volatile("cp.async.wait_group 2;");
        else if (rem == 1)
            asm volatile("cp.async.wait_group 1;");
        else
            asm volatile("cp.async.wait_group 0;");
        __syncthreads();
        if (i + 3 < nT) PISSUE(i + 3);

        const uint32_t* Ah2 = (const uint32_t*)(smem + (size_t)(i & 3) * X_STAGE);
        const uint32_t* Al2 = Ah2 + (X_A_B / 4);
        const uint32_t* Bh2 =
            (const uint32_t*)(smem + (size_t)(i & 3) * X_STAGE + 2 * X_A_B);
        const uint32_t* Bl2 = Bh2 + (X_B_B / 4);

        uint32_t ah[4][4], al[4][4], bh[8][2], bl[8][2];
#pragma unroll
        for (int mt = 0; mt < 4; mt++) {
            int mrow = warpM * 64 + mt * 16;
            ah[mt][0] = Ah2[(mrow + g) * X_APAD + t4];
            ah[mt][1] = Ah2[(mrow + g + 8) * X_APAD + t4];
            ah[mt][2] = Ah2[(mrow + g) * X_APAD + t4 + 4];
            ah[mt][3] = Ah2[(mrow + g + 8) * X_APAD + t4 + 4];
            al[mt][0] = Al2[(mrow + g) * X_APAD + t4];
            al[mt][1] = Al2[(mrow + g + 8) * X_APAD + t4];
            al[mt][2] = Al2[(mrow + g) * X_APAD + t4 + 4];
            al[mt][3] = Al2[(mrow + g + 8) * X_APAD + t4 + 4];
        }
#pragma unroll
        for (int nt = 0; nt < 8; nt++) {
            int ncol = warpN * 64 + nt * 8;
            bh[nt][0] = Bh2[t4 * X_BPAD + ncol + g];
            bh[nt][1] = Bh2[(t4 + 4) * X_BPAD + ncol + g];
            bl[nt][0] = Bl2[t4 * X_BPAD + ncol + g];
            bl[nt][1] = Bl2[(t4 + 4) * X_BPAD + ncol + g];
        }
#pragma unroll
        for (int mt = 0; mt < 4; mt++)
#pragma unroll
            for (int nt = 0; nt < 8; nt++) {
                mma_tf32(acc[mt][nt], ah[mt], bh[nt]);
                mma_tf32(acc[mt][nt], ah[mt], bl[nt]);
                mma_tf32(acc[mt][nt], al[mt], bh[nt]);
            }
    }
#undef PISSUE

    float* ChiB = ahiOut + (size_t)h * D;
    float* CloB = aloOut + (size_t)h * D;
#pragma unroll
    for (int mt = 0; mt < 4; mt++) {
        int rBase = row0 + warpM * 64 + mt * 16 + g;
#pragma unroll
        for (int half = 0; half < 2; half++) {
            int r = rBase + half * 8;
            float* cph = ChiB + (size_t)r * (NH * D);
            float* cpl = CloB + (size_t)r * (NH * D);
#pragma unroll
            for (int nt = 0; nt < 8; nt++) {
                int col = warpN * 64 + nt * 8 + t4 * 2;
                float v0 = acc[mt][nt][half * 2 + 0];
                float v1 = acc[mt][nt][half * 2 + 1];
                float h0 = f2tf32f(v0), h1 = f2tf32f(v1);
                cph[col] = h0;
                cph[col + 1] = h1;
                cpl[col] = f2tf32f(v0 - h0);
                cpl[col + 1] = f2tf32f(v1 - h1);
            }
        }
    }
}

// ---------------- weight prep ----------------
__global__ void prep_kernel(const float4* eg, float4* ceg,
                            const float4* eu, float4* ceu,
                            const float4* ed, float4* ced,
                            const float4* sg, float4* csg,
                            const float4* su, float4* csu,
                            const float4* sd, float4* csd,
                            const float4* wq, const float4* wk,
                            const float4* wv, const float4* wo,
                            float4* wsp) {
    const long long nEG = (long long)E * H * IE / 4;
    const long long nED = (long long)E * IE * H / 4;
    const long long nSG = (long long)H * IS / 4;
    const long long nSD = (long long)IS * H / 4;
    const long long nWW = (long long)H * H / 4;
    long long i = (long long)blockIdx.x * 256 + threadIdx.x;
    int y = blockIdx.y;
    if (y < 6) {
        const float4* src;
        float4* dst;
        long long n;
        switch (y) {
            case 0: src = eg; dst = ceg; n = nEG; break;
            case 1: src = eu; dst = ceu; n = nEG; break;
            case 2: src = ed; dst = ced; n = nED; break;
            case 3: src = sg; dst = csg; n = nSG; break;
            case 4: src = su; dst = csu; n = nSG; break;
            default: src = sd; dst = csd; n = nSD; break;
        }
        if (i < n) {
            float4 v = src[i];
            v.x = f2tf32f(v.x);
            v.y = f2tf32f(v.y);
            v.z = f2tf32f(v.z);
            v.w = f2tf32f(v.w);
            dst[i] = v;
        }
    } else {
        const float4* src = (y == 6) ? wq : (y == 7) ? wk : (y == 8) ? wv : wo;
        float4* hi = wsp + (size_t)(2 * (y - 6)) * nWW;
        float4* lo = hi + nWW;
        if (i < nWW) {
            float4 v = src[i];
            float4 hv, lv;
            hv.x = f2tf32f(v.x); lv.x = f2tf32f(v.x - hv.x);
            hv.y = f2tf32f(v.y); lv.y = f2tf32f(v.y - hv.y);
            hv.z = f2tf32f(v.z); lv.z = f2tf32f(v.z - hv.z);
            hv.w = f2tf32f(v.w); lv.w = f2tf32f(v.w - hv.w);
            hi[i] = hv;
            lo[i] = lv;
        }
    }
}

// ---------------- RMSNorm: hi+lo split or tf32 copy ----------------
__global__ void rmsnorm_kernel(const float* __restrict__ x,
                               const float* __restrict__ w,
                               float* __restrict__ out,
                               float* __restrict__ outTf,
                               float* __restrict__ outLo) {
    const float* xr = x + (long long)blockIdx.x * H;
    float* orow = out + (long long)blockIdx.x * H;
    __shared__ float red[256];
    float s = 0.f;
    for (int j = threadIdx.x; j < H; j += 256) {
        float v = xr[j];
        s += v * v;
    }
    red[threadIdx.x] = s;
    __syncthreads();
    for (int st = 128; st > 0; st >>= 1) {
        if (threadIdx.x < st) red[threadIdx.x] += red[threadIdx.x + st];
        __syncthreads();
    }
    float inv = 1.0f / sqrtf(red[0] / (float)H + 1e-6f);
    if (outLo) {
        float* lrow = outLo + (long long)blockIdx.x * H;
        for (int j = threadIdx.x; j < H; j += 256) {
            float v = w[j] * xr[j] * inv;
            float hi = f2tf32f(v);
            orow[j] = hi;
            lrow[j] = f2tf32f(v - hi);
        }
    } else if (outTf) {
        float* trow = outTf + (long long)blockIdx.x * H;
        for (int j = threadIdx.x; j < H; j += 256) {
            float v = w[j] * xr[j] * inv;
            orow[j] = v;
            trow[j] = f2tf32f(v);
        }
    } else {
        for (int j = threadIdx.x; j < H; j += 256) orow[j] = w[j] * xr[j] * inv;
    }
}

// ---------------- RoPE: rotate + hi/lo split ----------------
__global__ void rope_kernel(const float* __restrict__ q,
                            const float* __restrict__ k,
                            float* __restrict__ qhi, float* __restrict__ qlo,
                            float* __restrict__ khi, float* __restrict__ klo) {
    int s = blockIdx.x;
    int h = blockIdx.y;
    int j = threadIdx.x;
    float inv = exp2f(-(float)j * 0.31143075889569023f);
    float ang = (float)s * inv;
    float c, sn;
    sincosf(ang, &sn, &c);
    long long base = ((long long)s * NH + h) * D;
    float q1 = q[base + j], q2 = q[base + j + 64];
    float k1 = k[base + j], k2 = k[base + j + 64];
    float qa = q1 * c - q2 * sn;
    float qb = q2 * c + q1 * sn;
    float ka = k1 * c - k2 * sn;
    float kb = k2 * c + k1 * sn;
    float t;
    t = f2tf32f(qa); qhi[base + j] = t; qlo[base + j] = f2tf32f(qa - t);
    t = f2tf32f(qb); qhi[base + j + 64] = t; qlo[base + j + 64] = f2tf32f(qb - t);
    t = f2tf32f(ka); khi[base + j] = t; klo[base + j] = f2tf32f(ka - t);
    t = f2tf32f(kb); khi[base + j + 64] = t; klo[base + j + 64] = f2tf32f(kb - t);
}

// ---------------- causal row softmax, hi/lo output ----------------
__global__ void softmax_kernel(float* __restrict__ scores,
                               float* __restrict__ slo) {
    int r = blockIdx.x;
    float* row = scores + ((size_t)blockIdx.y * S + r) * S;
    float* lrow = slo + ((size_t)blockIdx.y * S + r) * S;
    const int limit = r + 1;
    const int rBlk = ((r >> 7) + 1) << 7;
    __shared__ float red[256];
    int tid = threadIdx.x;
    float m = -FLT_MAX;
    for (int j = tid; j < limit; j += 256) m = fmaxf(m, row[j]);
    red[tid] = m;
    __syncthreads();
    for (int st = 128; st > 0; st >>= 1) {
        if (tid < st) red[tid] = fmaxf(red[tid], red[tid + st]);
        __syncthreads();
    }
    m = red[0];
    __syncthreads();
    float sum = 0.f;
    for (int j = tid; j < limit; j += 256) {
        float e = expf(row[j] - m);
        row[j] = e;
        sum += e;
    }
    red[tid] = sum;
    __syncthreads();
    for (int st = 128; st > 0; st >>= 1) {
        if (tid < st) red[tid] += red[tid + st];
        __syncthreads();
    }
    float inv = 1.0f / red[0];
    for (int j = tid; j < limit; j += 256) {
        float p = row[j] * inv;
        float hi = f2tf32f(p);
        row[j] = hi;
        lrow[j] = f2tf32f(p - hi);
    }
    for (int j = limit + tid; j < rBlk; j += 256) {
        row[j] = 0.f;
        lrow[j] = 0.f;
    }
}

// ---------------- router ----------------
__global__ void router_kernel(const float* __restrict__ h2,
                              const float* __restrict__ gate_w,
                              float* __restrict__ logits_out,
                              int* __restrict__ idxbuf,
                              int* __restrict__ cnt,
                              int* __restrict__ tokmap,
                              float* __restrict__ tokw) {
    int s = blockIdx.x;
    const float* hr = h2 + (long long)s * H;
    __shared__ float red[256][E];
    float p[E];
#pragma unroll
    for (int e = 0; e < E; e++) p[e] = 0.f;
    for (int j = threadIdx.x; j < H; j += 256) {
        float hv = hr[j];
#pragma unroll
        for (int e = 0; e < E; e++) p[e] += hv * gate_w[j * E + e];
    }
#pragma unroll
    for (int e = 0; e < E; e++) red[threadIdx.x][e] = p[e];
    __syncthreads();
    for (int st = 128; st > 0; st >>= 1) {
        if (threadIdx.x < st)
#pragma unroll
            for (int e = 0; e < E; e++) red[threadIdx.x][e] += red[threadIdx.x + st][e];
        __syncthreads();
    }
    if (threadIdx.x == 0) {
        float logit[E];
        float m = -FLT_MAX;
#pragma unroll
        for (int e = 0; e < E; e++) {
            logit[e] = red[0][e];
            logits_out[(long long)s * E + e] = logit[e];
            m = fmaxf(m, logit[e]);
        }
        float sum = 0.f, rw[E];
#pragma unroll
        for (int e = 0; e < E; e++) {
            rw[e] = expf(logit[e] - m);
            sum += rw[e];
        }
        float inv = 1.0f / sum;
#pragma unroll
        for (int e = 0; e < E; e++) rw[e] *= inv;
        bool used[E];
#pragma unroll
        for (int e = 0; e < E; e++) used[e] = false;
        for (int k = 0; k < TOPK; k++) {
            int best = -1;
            float bvv = -FLT_MAX;
            for (int e = 0; e < E; e++)
                if (!used[e] && rw[e] > bvv) { bvv = rw[e]; best = e; }
            used[best] = true;
            int pos = atomicAdd(&cnt[best], 1);
            idxbuf[best * S + pos] = s;
            tokmap[s * TOPK + k] = best * S + pos;
            tokw[s * TOPK + k] = bvv;
        }
    }
}

// ---------------- h2 . sgate ----------------
__global__ void rowdot_kernel(const float* __restrict__ h2,
                              const float* __restrict__ sgate,
                              float* __restrict__ gatev) {
    int s = blockIdx.x;
    const float* hr = h2 + (long long)s * H;
    __shared__ float red[256];
    float acc = 0.f;
    for (int j = threadIdx.x; j < H; j += 256) acc += hr[j] * sgate[j];
    red[threadIdx.x] = acc;
    __syncthreads();
    for (int st = 128; st > 0; st >>= 1) {
        if (threadIdx.x < st) red[threadIdx.x] += red[threadIdx.x + st];
        __syncthreads();
    }
    if (threadIdx.x == 0) gatev[s] = red[0];
}

// ---------------- silu kernels ----------------
__global__ void silu_mul_expert_kernel(float* __restrict__ gb,
                                       const float* __restrict__ ub,
                                       const int* __restrict__ cnt) {
    int e = blockIdx.y;
    long long i = (long long)blockIdx.x * 256 + threadIdx.x;
    long long lim = (long long)cnt[e] * IE;
    if (i >= lim) return;
    size_t o = (size_t)e * S * IE + i;
    float x = gb[o];
    float sg = 1.0f / (1.0f + expf(-x));
    gb[o] = f2tf32f(x * sg * ub[o]);
}
__global__ void silu_mul_kernel(float* __restrict__ g, const float* __restrict__ u,
                                long long n) {
    long long i = (long long)blockIdx.x * 256 + threadIdx.x;
    if (i < n) {
        float x = g[i];
        float sg = 1.0f / (1.0f + expf(-x));
        g[i] = f2tf32f(x * sg * u[i]);
    }
}

// ---------------- final combine ----------------
__global__ void final_kernel(const float* __restrict__ x1,
                             const float* __restrict__ eo,
                             const int* __restrict__ tokmap,
                             const float* __restrict__ tokw,
                             const float* __restrict__ sdwn,
                             const float* __restrict__ gatev,
                             float* __restrict__ out) {
    long long i = (long long)blockIdx.x * 256 + threadIdx.x;
    int s = (int)(i / H);
    int c = (int)(i % H);
    float gv = 1.0f / (1.0f + expf(-gatev[s]));
    float acc = x1[i] + gv * sdwn[i];
#pragma unroll
    for (int j = 0; j < TOPK; j++) {
        int row = tokmap[s * TOPK + j];
        acc += tokw[s * TOPK + j] * eo[(size_t)row * H + c];
    }
    out[i] = acc;
}

// ---------------- host ----------------
static void launch_mma(const float* A, int lda, long long aStrE,
                       const float* B0, const float* B1, int ldb, long long bStrE,
                       float* C0, float* C1, int ldc, long long cStrE,
                       int M, int N, int K,
                       const int* gidx, int gstr, const int* cnt, int eShift,
                       int nz) {
    dim3 grid(N / 128, (M + 127) / 128, nz);
    mma_gemm_kernel<<<grid, 128, MMA_SMEM>>>(A, lda, aStrE, B0, B1, ldb, bStrE,
                                             C0, C1, ldc, cStrE, M, N, K,
                                             gidx, gstr, cnt, eShift);
}

extern "C" void kernel_launch(void* const* d_in, const int* in_sizes, int n_in,
                              void* d_out, int out_size) {
    (void)in_sizes; (void)n_in; (void)out_size;
    const float* x     = (const float*)d_in[0];
    const float* ln1   = (const float*)d_in[1];
    const float* ln2   = (const float*)d_in[2];
    const float* wq    = (const float*)d_in[3];
    const float* bq    = (const float*)d_in[4];
    const float* wk    = (const float*)d_in[5];
    const float* bk    = (const float*)d_in[6];
    const float* wv    = (const float*)d_in[7];
    const float* bv    = (const float*)d_in[8];
    const float* wo    = (const float*)d_in[9];
    const float* gatew = (const float*)d_in[10];
    const float* eg    = (const float*)d_in[11];
    const float* eu    = (const float*)d_in[12];
    const float* ed    = (const float*)d_in[13];
    const float* sg    = (const float*)d_in[14];
    const float* su    = (const float*)d_in[15];
    const float* sd    = (const float*)d_in[16];
    const float* sgate = (const float*)d_in[17];
    float* out = (float*)d_out;

    cudaFuncSetAttribute(mma_gemm_kernel,
                         cudaFuncAttributeMaxDynamicSharedMemorySize, MMA_SMEM);
    cudaFuncSetAttribute(mma3x_kernel,
                         cudaFuncAttributeMaxDynamicSharedMemorySize, X_SMEM);
    cudaFuncSetAttribute(sc3x_kernel,
                         cudaFuncAttributeMaxDynamicSharedMemorySize, SC_SMEM);
    cudaFuncSetAttribute(pv3x_kernel,
                         cudaFuncAttributeMaxDynamicSharedMemorySize, X_SMEM);

    float *hhi, *hlo, *q, *k, *qhi, *qlo, *khi, *klo, *vhi, *vlo, *scores,
        *slo, *ahi, *alo, *x1, *h2, *ch2, *gb, *ub, *eo, *sgb, *sub,
        *sdwn, *gatev, *tokw, *wsp;
    float *ceg, *ceu, *ced, *csg, *csu, *csd;
    int *idx, *cnt, *tokmap;
    cudaGetSymbolAddress((void**)&hhi, g_hhi);
    cudaGetSymbolAddress((void**)&hlo, g_hlo);
    cudaGetSymbolAddress((void**)&q, g_q);
    cudaGetSymbolAddress((void**)&k, g_k);
    cudaGetSymbolAddress((void**)&qhi, g_qhi);
    cudaGetSymbolAddress((void**)&qlo, g_qlo);
    cudaGetSymbolAddress((void**)&khi, g_khi);
    cudaGetSymbolAddress((void**)&klo, g_klo);
    cudaGetSymbolAddress((void**)&vhi, g_vhi);
    cudaGetSymbolAddress((void**)&vlo, g_vlo);
    cudaGetSymbolAddress((void**)&scores, g_scores);
    cudaGetSymbolAddress((void**)&slo, g_slo);
    cudaGetSymbolAddress((void**)&ahi, g_ahi);
    cudaGetSymbolAddress((void**)&alo, g_alo);
    cudaGetSymbolAddress((void**)&x1, g_x1);
    cudaGetSymbolAddress((void**)&h2, g_h2);
    cudaGetSymbolAddress((void**)&ch2, g_ch2);
    cudaGetSymbolAddress((void**)&gb, g_gb);
    cudaGetSymbolAddress((void**)&ub, g_ub);
    cudaGetSymbolAddress((void**)&eo, g_eo);
    cudaGetSymbolAddress((void**)&sgb, g_sgb);
    cudaGetSymbolAddress((void**)&sub, g_sub);
    cudaGetSymbolAddress((void**)&sdwn, g_sdwn);
    cudaGetSymbolAddress((void**)&gatev, g_gatev);
    cudaGetSymbolAddress((void**)&idx, g_idx);
    cudaGetSymbolAddress((void**)&cnt, g_cnt);
    cudaGetSymbolAddress((void**)&tokmap, g_tokmap);
    cudaGetSymbolAddress((void**)&tokw, g_tokw);
    cudaGetSymbolAddress((void**)&ceg, g_ceg);
    cudaGetSymbolAddress((void**)&ceu, g_ceu);
    cudaGetSymbolAddress((void**)&ced, g_ced);
    cudaGetSymbolAddress((void**)&csg, g_csg);
    cudaGetSymbolAddress((void**)&csu, g_csu);
    cudaGetSymbolAddress((void**)&csd, g_csd);
    cudaGetSymbolAddress((void**)&wsp, g_wsp);

    const size_t WW = (size_t)H * H;
    const float* wqh = wsp;
    const float* wql = wsp + WW;
    const float* wkh = wsp + 2 * WW;
    const float* wkl = wsp + 3 * WW;
    const float* wvh = wsp + 4 * WW;
    const float* wvl = wsp + 5 * WW;
    const float* woh = wsp + 6 * WW;
    const float* wol = wsp + 7 * WW;

    const float ascale = 0.08838834764831845f;

    // 0. weight prep (one launch)
    {
        long long nEG = (long long)E * H * IE / 4;
        unsigned gx = (unsigned)((nEG + 255) / 256);
        dim3 grid(gx, 10);
        prep_kernel<<<grid, 256>>>(
            (const float4*)eg, (float4*)ceg, (const float4*)eu, (float4*)ceu,
            (const float4*)ed, (float4*)ced, (const float4*)sg, (float4*)csg,
            (const float4*)su, (float4*)csu, (const float4*)sd, (float4*)csd,
            (const float4*)wq, (const float4*)wk, (const float4*)wv,
            (const float4*)wo, (float4*)wsp);
    }

    // 1. h = rmsnorm(x, ln1), hi/lo split
    rmsnorm_kernel<<<S, 256>>>(x, ln1, hhi, nullptr, hlo);

    // 2. q,k,v via 3xTF32; v written pre-split (hi->vhi, lo->vlo)
    {
        dim3 grid(16, 16, 3);
        mma3x_kernel<<<grid, 128, X_SMEM>>>(
            hhi, hlo, H, wqh, wql, wkh, wkl, wvh, wvl, NH * D,
            bq, bk, bv, q, k, vhi, vlo, NH * D, nullptr, H);
    }

    // 3. RoPE + q/k hi-lo split
    rope_kernel<<<dim3(S, NH), 64>>>(q, k, qhi, qlo, khi, klo);

    // 4. scores via 3xTF32 (causal blocks only)
    {
        dim3 grid(S / 128, S / 128, NH);
        sc3x_kernel<<<grid, 128, SC_SMEM>>>(qhi, qlo, khi, klo, scores, ascale);
    }

    // 5. softmax -> probs hi (in place) + lo
    softmax_kernel<<<dim3(S, NH), 256>>>(scores, slo);

    // 6. attn = probs @ v via 3xTF32 (K bounded at diagonal); writes ahi/alo
    {
        dim3 grid(1, S / 128, NH);
        pv3x_kernel<<<grid, 128, X_SMEM>>>(scores, slo, vhi, vlo, ahi, alo);
    }

    // 7. x1 = x + attn @ wo via 3xTF32
    {
        dim3 grid(16, 16, 1);
        mma3x_kernel<<<grid, 128, X_SMEM>>>(
            ahi, alo, NH * D, woh, wol, nullptr, nullptr, nullptr, nullptr, H,
            nullptr, nullptr, nullptr, x1, nullptr, nullptr, nullptr, H, x,
            NH * D);
    }

    // 8. h2 = rmsnorm(x1, ln2) + tf32 copy
    rmsnorm_kernel<<<S, 256>>>(x1, ln2, h2, ch2, nullptr);

    // 9. router
    cudaMemsetAsync(cnt, 0, E * sizeof(int));
    router_kernel<<<S, 256>>>(h2, gatew, out + (long long)S * H, idx, cnt,
                              tokmap, tokw);

    // 10. MoE gate+up
    launch_mma(ch2, H, 0, ceg, ceu, IE, (long long)H * IE,
               gb, ub, IE, (long long)S * IE, S, IE, H, idx, S, cnt, 1, 2 * E);

    // 11. silu
    {
        dim3 grid((unsigned)(((long long)S * IE + 255) / 256), E);
        silu_mul_expert_kernel<<<grid, 256>>>(gb, ub, cnt);
    }

    // 12. MoE down
    launch_mma(gb, IE, (long long)S * IE, ced, nullptr, H, (long long)IE * H,
               eo, nullptr, H, (long long)S * H, S, H, IE, nullptr, 0, cnt, 0, E);

    // 13. shared expert
    launch_mma(ch2, H, 0, csg, csu, IS, 0, sgb, sub, IS, 0, S, IS, H,
               nullptr, 0, nullptr, 1, 2);
    {
        long long n = (long long)S * IS;
        silu_mul_kernel<<<(unsigned)((n + 255) / 256), 256>>>(sgb, sub, n);
    }
    launch_mma(sgb, IS, 0, csd, nullptr, H, 0, sdwn, nullptr, H, 0, S, H, IS,
               nullptr, 0, nullptr, 0, 1);

    // 14. gate scalar
    rowdot_kernel<<<S, 256>>>(h2, sgate, gatev);

    // 15. combine
    final_kernel<<<(S * H) / 256, 256>>>(x1, eo, tokmap, tokw, sdwn, gatev, out);
}

// round 15
// speedup vs baseline: 1.1513x; 1.0397x over previous
#include <cuda_runtime.h>
#include <cuda_bf16.h>
#include <math.h>
#include <float.h>
#include <stdint.h>

#define S 2048
#define H 2048
#define NH 16
#define D 128
#define E 8
#define TOPK 4
#define IE 1408
#define IS 5632

// ---------------- scratch ----------------
__device__ float g_hhi[S * H];
__device__ float g_hlo[S * H];
__device__ float g_q[S * H];
__device__ float g_k[S * H];
__device__ float g_qhi[S * H];
__device__ float g_qlo[S * H];
__device__ float g_khi[S * H];
__device__ float g_klo[S * H];
__device__ float g_vhi[S * H];
__device__ float g_vlo[S * H];
__device__ float g_scores[(size_t)NH * S * S];
__device__ float g_slo[(size_t)NH * S * S];
__device__ float g_ahi[S * H];
__device__ float g_alo[S * H];
__device__ float g_x1[S * H];
__device__ float g_h2[S * H];
__device__ float g_ch2[S * H];
__device__ float g_gb[(size_t)E * S * IE];
__device__ float g_ub[(size_t)E * S * IE];
__device__ float g_eo[(size_t)E * S * H];
__device__ float g_sgb[S * IS];
__device__ float g_sub[S * IS];
__device__ float g_sdwn[S * H];
__device__ float g_gatev[S];
__device__ int g_idx[E * S];
__device__ int g_cnt[E];
__device__ int g_tokmap[S * TOPK];
__device__ float g_tokw[S * TOPK];
__device__ float g_wsp[(size_t)8 * H * H];

// ================= helpers =================
__device__ __forceinline__ uint32_t smem_to_u32(const void* p) {
    uint32_t a;
    asm("{ .reg .u64 t; cvta.to.shared.u64 t, %1; cvt.u32.u64 %0, t; }"
        : "=r"(a) : "l"(p));
    return a;
}
__device__ __forceinline__ float f2tf32f(float f) {
    uint32_t r;
    asm("cvt.rna.tf32.f32 %0, %1;" : "=r"(r) : "f"(f));
    return __uint_as_float(r);
}
__device__ __forceinline__ void mma_tf32(float* d, const uint32_t* a,
                                         const uint32_t* b) {
    asm volatile(
        "mma.sync.aligned.m16n8k8.row.col.f32.tf32.tf32.f32 "
        "{%0,%1,%2,%3}, {%4,%5,%6,%7}, {%8,%9}, {%0,%1,%2,%3};"
        : "+f"(d[0]), "+f"(d[1]), "+f"(d[2]), "+f"(d[3])
        : "r"(a[0]), "r"(a[1]), "r"(a[2]), "r"(a[3]), "r"(b[0]), "r"(b[1]));
}
__device__ __forceinline__ void cp_async16(uint32_t dst, const void* src) {
    asm volatile("cp.async.ca.shared.global [%0], [%1], 16;"
                 :: "r"(dst), "l"(src));
}

// ================= tf32 mma GEMM v3 (MoE path, 4-stage) =======================
// B operands are raw fp32 (HW truncates to tf32); A operands RNA-pre-rounded.
#define APADF 20
#define BPADF 136
#define A_STAGE_B (128 * APADF * 4)
#define B_STAGE_B (16 * BPADF * 4)
#define STAGE_B (A_STAGE_B + B_STAGE_B)
#define MMA_SMEM (STAGE_B * 4)

__global__ __launch_bounds__(128, 2)
void mma_gemm_kernel(const float* __restrict__ A, int lda, long long aStrE,
                     const float* __restrict__ B0, const float* __restrict__ B1,
                     int ldb, long long bStrE,
                     float* __restrict__ C0, float* __restrict__ C1,
                     int ldc, long long cStrE,
                     int M, int N, int K,
                     const int* __restrict__ gidxBase, int gidxStr,
                     const int* __restrict__ cntBase, int eShift) {
    extern __shared__ char smem[];
    const uint32_t sb = smem_to_u32(smem);
    const int z = blockIdx.z;
    const int e = z >> eShift;
    const int which = z & ((1 << eShift) - 1);
    const float* B = (which ? B1 : B0) + (long long)e * bStrE;
    float* C = (which ? C1 : C0) + (long long)e * cStrE;
    A += (long long)e * aStrE;

    const int cnt = cntBase ? cntBase[e] : M;
    const int mEff = min(M, cnt);
    const int row0 = blockIdx.y * 128;
    const int col0 = blockIdx.x * 128;
    if (row0 >= mEff) return;
    const int* gidx = gidxBase ? gidxBase + (long long)e * gidxStr : nullptr;

    const int tid = threadIdx.x;
    const int wid = tid >> 5;
    const int lane = tid & 31;
    const int g = lane >> 2;
    const int t4 = lane & 3;
    const int warpM = wid >> 1;
    const int warpN = wid & 1;

    const float* aG[4];
    uint32_t aS[4];
#pragma unroll
    for (int j = 0; j < 4; j++) {
        int u = tid + 128 * j;
        int m = u >> 2, c4 = u & 3;
        int arow = row0 + m;
        int src;
        if (gidx) src = (arow < cnt) ? gidx[arow] : 0;
        else src = min(arow, M - 1);
        aG[j] = A + (size_t)src * lda + c4 * 4;
        aS[j] = sb + (uint32_t)(m * APADF + c4 * 4) * 4u;
    }
    const float* bG[4];
    uint32_t bS[4];
#pragma unroll
    for (int j = 0; j < 4; j++) {
        int u = tid + 128 * j;
        int n4 = u & 31, kk = u >> 5;
        bG[j] = B + (size_t)kk * ldb + col0 + n4 * 4;
        bS[j] = sb + A_STAGE_B + (uint32_t)(kk * BPADF + n4 * 4) * 4u;
    }

    float acc[4][8][4];
#pragma unroll
    for (int mt = 0; mt < 4; mt++)
#pragma unroll
        for (int nt = 0; nt < 8; nt++)
#pragma unroll
            for (int r = 0; r < 4; r++) acc[mt][nt][r] = 0.f;

    const int nT = K / 16;

#define ISSUE(i)                                                      \
    do {                                                              \
        uint32_t _off = (uint32_t)((i) & 3) * STAGE_B;                \
        int _k0 = (i) * 16;                                           \
        cp_async16(aS[0] + _off, aG[0] + _k0);                        \
        cp_async16(aS[1] + _off, aG[1] + _k0);                        \
        cp_async16(aS[2] + _off, aG[2] + _k0);                        \
        cp_async16(aS[3] + _off, aG[3] + _k0);                        \
        cp_async16(bS[0] + _off, bG[0] + (size_t)_k0 * ldb);          \
        cp_async16(bS[1] + _off, bG[1] + (size_t)_k0 * ldb);          \
        cp_async16(bS[2] + _off, bG[2] + (size_t)_k0 * ldb);          \
        cp_async16(bS[3] + _off, bG[3] + (size_t)_k0 * ldb);          \
        asm volatile("cp.async.commit_group;");                       \
    } while (0)

    ISSUE(0);
    if (nT > 1) ISSUE(1);
    if (nT > 2) ISSUE(2);

    for (int i = 0; i < nT; i++) {
        const int rem = nT - 1 - i;
        if (rem >= 2)
            asm volatile("cp.async.wait_group 2;");
        else if (rem == 1)
            asm volatile("cp.async.wait_group 1;");
        else
            asm volatile("cp.async.wait_group 0;");
        __syncthreads();
        if (i + 3 < nT) ISSUE(i + 3);

        const uint32_t* Asb =
            (const uint32_t*)(smem + (size_t)(i & 3) * STAGE_B);
        const uint32_t* Bsb =
            (const uint32_t*)(smem + (size_t)(i & 3) * STAGE_B + A_STAGE_B);
#pragma unroll
        for (int kk = 0; kk < 16; kk += 8) {
            uint32_t a[4][4], b[8][2];
#pragma unroll
            for (int mt = 0; mt < 4; mt++) {
                int mrow = warpM * 64 + mt * 16;
                a[mt][0] = Asb[(mrow + g) * APADF + kk + t4];
                a[mt][1] = Asb[(mrow + g + 8) * APADF + kk + t4];
                a[mt][2] = Asb[(mrow + g) * APADF + kk + t4 + 4];
                a[mt][3] = Asb[(mrow + g + 8) * APADF + kk + t4 + 4];
            }
#pragma unroll
            for (int nt = 0; nt < 8; nt++) {
                int ncol = warpN * 64 + nt * 8;
                b[nt][0] = Bsb[(kk + t4) * BPADF + ncol + g];
                b[nt][1] = Bsb[(kk + t4 + 4) * BPADF + ncol + g];
            }
#pragma unroll
            for (int mt = 0; mt < 4; mt++)
#pragma unroll
                for (int nt = 0; nt < 8; nt++)
                    mma_tf32(acc[mt][nt], a[mt], b[nt]);
        }
    }
#undef ISSUE

#pragma unroll
    for (int mt = 0; mt < 4; mt++) {
        int rBase = row0 + warpM * 64 + mt * 16 + g;
#pragma unroll
        for (int half = 0; half < 2; half++) {
            int r = rBase + half * 8;
            if (r >= mEff) continue;
            float* cp = C + (size_t)r * ldc;
#pragma unroll
            for (int nt = 0; nt < 8; nt++) {
                int col = col0 + warpN * 64 + nt * 8 + t4 * 2;
                cp[col] = acc[mt][nt][half * 2 + 0];
                cp[col + 1] = acc[mt][nt][half * 2 + 1];
            }
        }
    }
}

// ================= 3xTF32 mma GEMM (QKV / wo) ==========
#define X_APAD 12
#define X_BPAD 136
#define X_A_B (128 * X_APAD * 4)
#define X_B_B (8 * X_BPAD * 4)
#define X_STAGE (2 * X_A_B + 2 * X_B_B)
#define X_SMEM (X_STAGE * 4)

__global__ __launch_bounds__(128, 2)
void mma3x_kernel(const float* __restrict__ Ahi, const float* __restrict__ Alo,
                  int lda,
                  const float* __restrict__ B0h, const float* __restrict__ B0l,
                  const float* __restrict__ B1h, const float* __restrict__ B1l,
                  const float* __restrict__ B2h, const float* __restrict__ B2l,
                  int ldb,
                  const float* __restrict__ bias0,
                  const float* __restrict__ bias1,
                  const float* __restrict__ bias2,
                  float* __restrict__ C0, float* __restrict__ C1,
                  float* __restrict__ C2, float* __restrict__ C2lo, int ldc,
                  const float* __restrict__ residual,
                  int K) {
    extern __shared__ char smem[];
    const uint32_t sb = smem_to_u32(smem);
    const int z = blockIdx.z;
    const float* Bh = (z == 0) ? B0h : (z == 1 ? B1h : B2h);
    const float* Bl = (z == 0) ? B0l : (z == 1 ? B1l : B2l);
    const float* bias = (z == 0) ? bias0 : (z == 1 ? bias1 : bias2);
    float* C = (z == 0) ? C0 : (z == 1 ? C1 : C2);
    float* Clo = (z == 2) ? C2lo : nullptr;

    const int row0 = blockIdx.y * 128;
    const int col0 = blockIdx.x * 128;

    const int tid = threadIdx.x;
    const int wid = tid >> 5;
    const int lane = tid & 31;
    const int g = lane >> 2;
    const int t4 = lane & 3;
    const int warpM = wid >> 1;
    const int warpN = wid & 1;

    const long long aLoD = Alo - Ahi;
    const long long bLoD = Bl - Bh;

    const float* aGh[2];
    uint32_t aSh[2];
#pragma unroll
    for (int j = 0; j < 2; j++) {
        int u = tid + 128 * j;
        int m = u >> 1, c4 = u & 1;
        aGh[j] = Ahi + (size_t)(row0 + m) * lda + c4 * 4;
        aSh[j] = sb + (uint32_t)(m * X_APAD + c4 * 4) * 4u;
    }
    const float* bGh[2];
    uint32_t bSh[2];
#pragma unroll
    for (int j = 0; j < 2; j++) {
        int u = tid + 128 * j;
        int kk = u >> 5, n4 = u & 31;
        bGh[j] = Bh + (size_t)kk * ldb + col0 + n4 * 4;
        bSh[j] = sb + (uint32_t)(2 * X_A_B) +
                 (uint32_t)(kk * X_BPAD + n4 * 4) * 4u;
    }

    float acc[4][8][4];
#pragma unroll
    for (int mt = 0; mt < 4; mt++)
#pragma unroll
        for (int nt = 0; nt < 8; nt++)
#pragma unroll
            for (int r = 0; r < 4; r++) acc[mt][nt][r] = 0.f;

    const int nT = K / 8;

#define XISSUE(i)                                                       \
    do {                                                                \
        uint32_t _off = (uint32_t)((i) & 3) * X_STAGE;                  \
        int _k0 = (i) * 8;                                              \
        cp_async16(aSh[0] + _off, aGh[0] + _k0);                        \
        cp_async16(aSh[1] + _off, aGh[1] + _k0);                        \
        cp_async16(aSh[0] + X_A_B + _off, aGh[0] + aLoD + _k0);         \
        cp_async16(aSh[1] + X_A_B + _off, aGh[1] + aLoD + _k0);         \
        cp_async16(bSh[0] + _off, bGh[0] + (size_t)_k0 * ldb);          \
        cp_async16(bSh[1] + _off, bGh[1] + (size_t)_k0 * ldb);          \
        cp_async16(bSh[0] + X_B_B + _off, bGh[0] + bLoD + (size_t)_k0 * ldb); \
        cp_async16(bSh[1] + X_B_B + _off, bGh[1] + bLoD + (size_t)_k0 * ldb); \
        asm volatile("cp.async.commit_group;");                         \
    } while (0)

    XISSUE(0);
    XISSUE(1);
    XISSUE(2);

    for (int i = 0; i < nT; i++) {
        const int rem = nT - 1 - i;
        if (rem >= 2)
            asm volatile("cp.async.wait_group 2;");
        else if (rem == 1)
            asm volatile("cp.async.wait_group 1;");
        else
            asm volatile("cp.async.wait_group 0;");
        __syncthreads();
        if (i + 3 < nT) XISSUE(i + 3);

        const uint32_t* Ah = (const uint32_t*)(smem + (size_t)(i & 3) * X_STAGE);
        const uint32_t* Al = Ah + (X_A_B / 4);
        const uint32_t* Bhs =
            (const uint32_t*)(smem + (size_t)(i & 3) * X_STAGE + 2 * X_A_B);
        const uint32_t* Bls = Bhs + (X_B_B / 4);

        uint32_t ah[4][4], al[4][4], bh[8][2], bl[8][2];
#pragma unroll
        for (int mt = 0; mt < 4; mt++) {
            int mrow = warpM * 64 + mt * 16;
            ah[mt][0] = Ah[(mrow + g) * X_APAD + t4];
            ah[mt][1] = Ah[(mrow + g + 8) * X_APAD + t4];
            ah[mt][2] = Ah[(mrow + g) * X_APAD + t4 + 4];
            ah[mt][3] = Ah[(mrow + g + 8) * X_APAD + t4 + 4];
            al[mt][0] = Al[(mrow + g) * X_APAD + t4];
            al[mt][1] = Al[(mrow + g + 8) * X_APAD + t4];
            al[mt][2] = Al[(mrow + g) * X_APAD + t4 + 4];
            al[mt][3] = Al[(mrow + g + 8) * X_APAD + t4 + 4];
        }
#pragma unroll
        for (int nt = 0; nt < 8; nt++) {
            int ncol = warpN * 64 + nt * 8;
            bh[nt][0] = Bhs[t4 * X_BPAD + ncol + g];
            bh[nt][1] = Bhs[(t4 + 4) * X_BPAD + ncol + g];
            bl[nt][0] = Bls[t4 * X_BPAD + ncol + g];
            bl[nt][1] = Bls[(t4 + 4) * X_BPAD + ncol + g];
        }
#pragma unroll
        for (int mt = 0; mt < 4; mt++)
#pragma unroll
            for (int nt = 0; nt < 8; nt++) {
                mma_tf32(acc[mt][nt], ah[mt], bh[nt]);
                mma_tf32(acc[mt][nt], ah[mt], bl[nt]);
                mma_tf32(acc[mt][nt], al[mt], bh[nt]);
            }
    }
#undef XISSUE

#pragma unroll
    for (int mt = 0; mt < 4; mt++) {
        int rBase = row0 + warpM * 64 + mt * 16 + g;
#pragma unroll
        for (int half = 0; half < 2; half++) {
            int r = rBase + half * 8;
            float* cp = C + (size_t)r * ldc;
            float* cl = Clo ? Clo + (size_t)r * ldc : nullptr;
            const float* rp = residual ? residual + (size_t)r * ldc : nullptr;
#pragma unroll
            for (int nt = 0; nt < 8; nt++) {
                int col = col0 + warpN * 64 + nt * 8 + t4 * 2;
                float v0 = acc[mt][nt][half * 2 + 0];
                float v1 = acc[mt][nt][half * 2 + 1];
                if (bias) {
                    v0 += bias[col];
                    v1 += bias[col + 1];
                }
                if (rp) {
                    v0 += rp[col];
                    v1 += rp[col + 1];
                }
                if (cl) {
                    float h0 = f2tf32f(v0), h1 = f2tf32f(v1);
                    cp[col] = h0;
                    cp[col + 1] = h1;
                    cl[col] = f2tf32f(v0 - h0);
                    cl[col + 1] = f2tf32f(v1 - h1);
                } else {
                    cp[col] = v0;
                    cp[col + 1] = v1;
                }
            }
        }
    }
}

// ================= 3xTF32 scores kernel (Q·K^T, causal) =======================
#define SC_HALF (128 * X_APAD * 4)
#define SC_STAGE (4 * SC_HALF)
#define SC_SMEM (SC_STAGE * 3)

__global__ __launch_bounds__(128, 2)
void sc3x_kernel(const float* __restrict__ qhi, const float* __restrict__ qlo,
                 const float* __restrict__ khi, const float* __restrict__ klo,
                 float* __restrict__ scores, float scale) {
    extern __shared__ char smem[];
    const uint32_t sb = smem_to_u32(smem);
    const int h = blockIdx.z;
    const int row0 = blockIdx.y * 128;
    const int col0 = blockIdx.x * 128;
    if (col0 > row0) return;

    const int lda = NH * D;
    const float* Ah = qhi + (size_t)h * D;
    const float* Bh = khi + (size_t)h * D;
    const long long aLoD = qlo - qhi;
    const long long bLoD = klo - khi;

    const int tid = threadIdx.x;
    const int wid = tid >> 5;
    const int lane = tid & 31;
    const int g = lane >> 2;
    const int t4 = lane & 3;
    const int warpM = wid >> 1;
    const int warpN = wid & 1;

    const float* aGh[2];
    uint32_t aSh[2];
    const float* bGh[2];
    uint32_t bSh[2];
#pragma unroll
    for (int j = 0; j < 2; j++) {
        int u = tid + 128 * j;
        int m = u >> 1, c4 = u & 1;
        aGh[j] = Ah + (size_t)(row0 + m) * lda + c4 * 4;
        aSh[j] = sb + (uint32_t)(m * X_APAD + c4 * 4) * 4u;
        bGh[j] = Bh + (size_t)(col0 + m) * lda + c4 * 4;
        bSh[j] = sb + (uint32_t)(2 * SC_HALF) +
                 (uint32_t)(m * X_APAD + c4 * 4) * 4u;
    }

    float acc[4][8][4];
#pragma unroll
    for (int mt = 0; mt < 4; mt++)
#pragma unroll
        for (int nt = 0; nt < 8; nt++)
#pragma unroll
            for (int r = 0; r < 4; r++) acc[mt][nt][r] = 0.f;

    const int nT = D / 8;
    const uint32_t stOff[3] = {0u, SC_STAGE, 2u * SC_STAGE};

#define SISSUE(i, st)                                                  \
    do {                                                               \
        uint32_t _off = stOff[st];                                     \
        int _k0 = (i) * 8;                                             \
        cp_async16(aSh[0] + _off, aGh[0] + _k0);                       \
        cp_async16(aSh[1] + _off, aGh[1] + _k0);                       \
        cp_async16(aSh[0] + SC_HALF + _off, aGh[0] + aLoD + _k0);      \
        cp_async16(aSh[1] + SC_HALF + _off, aGh[1] + aLoD + _k0);      \
        cp_async16(bSh[0] + _off, bGh[0] + _k0);                       \
        cp_async16(bSh[1] + _off, bGh[1] + _k0);                       \
        cp_async16(bSh[0] + SC_HALF + _off, bGh[0] + bLoD + _k0);      \
        cp_async16(bSh[1] + SC_HALF + _off, bGh[1] + bLoD + _k0);      \
        asm volatile("cp.async.commit_group;");                        \
    } while (0)

    SISSUE(0, 0);
    SISSUE(1, 1);

    int stC = 0, stI = 2;
    for (int i = 0; i < nT; i++) {
        if (i + 1 < nT)
            asm volatile("cp.async.wait_group 1;");
        else
            asm volatile("cp.async.wait_group 0;");
        __syncthreads();
        if (i + 2 < nT) {
            SISSUE(i + 2, stI);
            stI = (stI == 2) ? 0 : stI + 1;
        }
        const uint32_t* Ah2 = (const uint32_t*)(smem + stOff[stC]);
        const uint32_t* Al2 = Ah2 + (SC_HALF / 4);
        const uint32_t* Bh2 = (const uint32_t*)(smem + stOff[stC] + 2 * SC_HALF);
        const uint32_t* Bl2 = Bh2 + (SC_HALF / 4);
        stC = (stC == 2) ? 0 : stC + 1;

        uint32_t ah[4][4], al[4][4], bh[8][2], bl[8][2];
#pragma unroll
        for (int mt = 0; mt < 4; mt++) {
            int mrow = warpM * 64 + mt * 16;
            ah[mt][0] = Ah2[(mrow + g) * X_APAD + t4];
            ah[mt][1] = Ah2[(mrow + g + 8) * X_APAD + t4];
            ah[mt][2] = Ah2[(mrow + g) * X_APAD + t4 + 4];
            ah[mt][3] = Ah2[(mrow + g + 8) * X_APAD + t4 + 4];
            al[mt][0] = Al2[(mrow + g) * X_APAD + t4];
            al[mt][1] = Al2[(mrow + g + 8) * X_APAD + t4];
            al[mt][2] = Al2[(mrow + g) * X_APAD + t4 + 4];
            al[mt][3] = Al2[(mrow + g + 8) * X_APAD + t4 + 4];
        }
#pragma unroll
        for (int nt = 0; nt < 8; nt++) {
            int ncol = warpN * 64 + nt * 8;
            bh[nt][0] = Bh2[(ncol + g) * X_APAD + t4];
            bh[nt][1] = Bh2[(ncol + g) * X_APAD + t4 + 4];
            bl[nt][0] = Bl2[(ncol + g) * X_APAD + t4];
            bl[nt][1] = Bl2[(ncol + g) * X_APAD + t4 + 4];
        }
#pragma unroll
        for (int mt = 0; mt < 4; mt++)
#pragma unroll
            for (int nt = 0; nt < 8; nt++) {
                mma_tf32(acc[mt][nt], ah[mt], bh[nt]);
                mma_tf32(acc[mt][nt], ah[mt], bl[nt]);
                mma_tf32(acc[mt][nt], al[mt], bh[nt]);
            }
    }
#undef SISSUE

    float* Cbase = scores + (size_t)h * S * S;
#pragma unroll
    for (int mt = 0; mt < 4; mt++) {
        int rBase = row0 + warpM * 64 + mt * 16 + g;
#pragma unroll
        for (int half = 0; half < 2; half++) {
            int r = rBase + half * 8;
            float* cp = Cbase + (size_t)r * S;
#pragma unroll
            for (int nt = 0; nt < 8; nt++) {
                int col = col0 + warpN * 64 + nt * 8 + t4 * 2;
                float v0 = acc[mt][nt][half * 2 + 0] * scale;
                float v1 = acc[mt][nt][half * 2 + 1] * scale;
                if (col > r) v0 = -3.4028234663852886e38f;
                if (col + 1 > r) v1 = -3.4028234663852886e38f;
                cp[col] = v0;
                cp[col + 1] = v1;
            }
        }
    }
}

// ================= 3xTF32 PV kernel (probs·V, kLimit, split output) ===========
__global__ __launch_bounds__(128, 2)
void pv3x_kernel(const float* __restrict__ phi, const float* __restrict__ plo,
                 const float* __restrict__ vhi, const float* __restrict__ vlo,
                 float* __restrict__ ahiOut, float* __restrict__ aloOut) {
    extern __shared__ char smem[];
    const uint32_t sb = smem_to_u32(smem);
    const int h = blockIdx.z;
    const int row0 = blockIdx.y * 128;

    const int lda = S;
    const int ldb = NH * D;
    const float* Ah = phi + (size_t)h * S * S;
    const float* Bh = vhi + (size_t)h * D;
    const long long aLoD = plo - phi;
    const long long bLoD = vlo - vhi;

    const int tid = threadIdx.x;
    const int wid = tid >> 5;
    const int lane = tid & 31;
    const int g = lane >> 2;
    const int t4 = lane & 3;
    const int warpM = wid >> 1;
    const int warpN = wid & 1;

    const float* aGh[2];
    uint32_t aSh[2];
#pragma unroll
    for (int j = 0; j < 2; j++) {
        int u = tid + 128 * j;
        int m = u >> 1, c4 = u & 1;
        aGh[j] = Ah + (size_t)(row0 + m) * lda + c4 * 4;
        aSh[j] = sb + (uint32_t)(m * X_APAD + c4 * 4) * 4u;
    }
    const float* bGh[2];
    uint32_t bSh[2];
#pragma unroll
    for (int j = 0; j < 2; j++) {
        int u = tid + 128 * j;
        int kk = u >> 5, n4 = u & 31;
        bGh[j] = Bh + (size_t)kk * ldb + n4 * 4;
        bSh[j] = sb + (uint32_t)(2 * X_A_B) +
                 (uint32_t)(kk * X_BPAD + n4 * 4) * 4u;
    }

    float acc[4][8][4];
#pragma unroll
    for (int mt = 0; mt < 4; mt++)
#pragma unroll
        for (int nt = 0; nt < 8; nt++)
#pragma unroll
            for (int r = 0; r < 4; r++) acc[mt][nt][r] = 0.f;

    const int nT = (row0 + 128) / 8;

#define PISSUE(i)                                                       \
    do {                                                                \
        uint32_t _off = (uint32_t)((i) & 3) * X_STAGE;                  \
        int _k0 = (i) * 8;                                              \
        cp_async16(aSh[0] + _off, aGh[0] + _k0);                        \
        cp_async16(aSh[1] + _off, aGh[1] + _k0);                        \
        cp_async16(aSh[0] + X_A_B + _off, aGh[0] + aLoD + _k0);         \
        cp_async16(aSh[1] + X_A_B + _off, aGh[1] + aLoD + _k0);         \
        cp_async16(bSh[0] + _off, bGh[0] + (size_t)_k0 * ldb);          \
        cp_async16(bSh[1] + _off, bGh[1] + (size_t)_k0 * ldb);          \
        cp_async16(bSh[0] + X_B_B + _off, bGh[0] + bLoD + (size_t)_k0 * ldb); \
        cp_async16(bSh[1] + X_B_B + _off, bGh[1] + bLoD + (size_t)_k0 * ldb); \
        asm volatile("cp.async.commit_group;");                         \
    } while (0)

    PISSUE(0);
    PISSUE(1);
    PISSUE(2);

    for (int i = 0; i < nT; i++) {
        const int rem = nT - 1 - i;
        if (rem >= 2)
            asm volatile("cp.async.wait_group 2;");
        else if (rem == 1)
            asm volatile("cp.async.wait_group 1;");
        else
            asm volatile("cp.async.wait_group 0;");
        __syncthreads();
        if (i + 3 < nT) PISSUE(i + 3);

        const uint32_t* Ah2 = (const uint32_t*)(smem + (size_t)(i & 3) * X_STAGE);
        const uint32_t* Al2 = Ah2 + (X_A_B / 4);
        const uint32_t* Bh2 =
            (const uint32_t*)(smem + (size_t)(i & 3) * X_STAGE + 2 * X_A_B);
        const uint32_t* Bl2 = Bh2 + (X_B_B / 4);

        uint32_t ah[4][4], al[4][4], bh[8][2], bl[8][2];
#pragma unroll
        for (int mt = 0; mt < 4; mt++) {
            int mrow = warpM * 64 + mt * 16;
            ah[mt][0] = Ah2[(mrow + g) * X_APAD + t4];
            ah[mt][1] = Ah2[(mrow + g + 8) * X_APAD + t4];
            ah[mt][2] = Ah2[(mrow + g) * X_APAD + t4 + 4];
            ah[mt][3] = Ah2[(mrow + g + 8) * X_APAD + t4 + 4];
            al[mt][0] = Al2[(mrow + g) * X_APAD + t4];
            al[mt][1] = Al2[(mrow + g + 8) * X_APAD + t4];
            al[mt][2] = Al2[(mrow + g) * X_APAD + t4 + 4];
            al[mt][3] = Al2[(mrow + g + 8) * X_APAD + t4 + 4];
        }
#pragma unroll
        for (int nt = 0; nt < 8; nt++) {
            int ncol = warpN * 64 + nt * 8;
            bh[nt][0] = Bh2[t4 * X_BPAD + ncol + g];
            bh[nt][1] = Bh2[(t4 + 4) * X_BPAD + ncol + g];
            bl[nt][0] = Bl2[t4 * X_BPAD + ncol + g];
            bl[nt][1] = Bl2[(t4 + 4) * X_BPAD + ncol + g];
        }
#pragma unroll
        for (int mt = 0; mt < 4; mt++)
#pragma unroll
            for (int nt = 0; nt < 8; nt++) {
                mma_tf32(acc[mt][nt], ah[mt], bh[nt]);
                mma_tf32(acc[mt][nt], ah[mt], bl[nt]);
                mma_tf32(acc[mt][nt], al[mt], bh[nt]);
            }
    }
#undef PISSUE

    float* ChiB = ahiOut + (size_t)h * D;
    float* CloB = aloOut + (size_t)h * D;
#pragma unroll
    for (int mt = 0; mt < 4; mt++) {
        int rBase = row0 + warpM * 64 + mt * 16 + g;
#pragma unroll
        for (int half = 0; half < 2; half++) {
            int r = rBase + half * 8;
            float* cph = ChiB + (size_t)r * (NH * D);
            float* cpl = CloB + (size_t)r * (NH * D);
#pragma unroll
            for (int nt = 0; nt < 8; nt++) {
                int col = warpN * 64 + nt * 8 + t4 * 2;
                float v0 = acc[mt][nt][half * 2 + 0];
                float v1 = acc[mt][nt][half * 2 + 1];
                float h0 = f2tf32f(v0), h1 = f2tf32f(v1);
                cph[col] = h0;
                cph[col + 1] = h1;
                cpl[col] = f2tf32f(v0 - h0);
                cpl[col + 1] = f2tf32f(v1 - h1);
            }
        }
    }
}

// ---------------- weight prep: hi/lo split of 4 attention weights only -------
__global__ void prep_kernel(const float4* wq, const float4* wk,
                            const float4* wv, const float4* wo,
                            float4* wsp) {
    const long long nWW = (long long)H * H / 4;
    long long i = (long long)blockIdx.x * 256 + threadIdx.x;
    int y = blockIdx.y;
    const float4* src = (y == 0) ? wq : (y == 1) ? wk : (y == 2) ? wv : wo;
    float4* hi = wsp + (size_t)(2 * y) * nWW;
    float4* lo = hi + nWW;
    if (i < nWW) {
        float4 v = src[i];
        float4 hv, lv;
        hv.x = f2tf32f(v.x); lv.x = f2tf32f(v.x - hv.x);
        hv.y = f2tf32f(v.y); lv.y = f2tf32f(v.y - hv.y);
        hv.z = f2tf32f(v.z); lv.z = f2tf32f(v.z - hv.z);
        hv.w = f2tf32f(v.w); lv.w = f2tf32f(v.w - hv.w);
        hi[i] = hv;
        lo[i] = lv;
    }
}

// ---------------- RMSNorm: hi+lo split or tf32 copy ----------------
__global__ void rmsnorm_kernel(const float* __restrict__ x,
                               const float* __restrict__ w,
                               float* __restrict__ out,
                               float* __restrict__ outTf,
                               float* __restrict__ outLo) {
    const float* xr = x + (long long)blockIdx.x * H;
    float* orow = out + (long long)blockIdx.x * H;
    __shared__ float red[256];
    float s = 0.f;
    for (int j = threadIdx.x; j < H; j += 256) {
        float v = xr[j];
        s += v * v;
    }
    red[threadIdx.x] = s;
    __syncthreads();
    for (int st = 128; st > 0; st >>= 1) {
        if (threadIdx.x < st) red[threadIdx.x] += red[threadIdx.x + st];
        __syncthreads();
    }
    float inv = 1.0f / sqrtf(red[0] / (float)H + 1e-6f);
    if (outLo) {
        float* lrow = outLo + (long long)blockIdx.x * H;
        for (int j = threadIdx.x; j < H; j += 256) {
            float v = w[j] * xr[j] * inv;
            float hi = f2tf32f(v);
            orow[j] = hi;
            lrow[j] = f2tf32f(v - hi);
        }
    } else if (outTf) {
        float* trow = outTf + (long long)blockIdx.x * H;
        for (int j = threadIdx.x; j < H; j += 256) {
            float v = w[j] * xr[j] * inv;
            orow[j] = v;
            trow[j] = f2tf32f(v);
        }
    } else {
        for (int j = threadIdx.x; j < H; j += 256) orow[j] = w[j] * xr[j] * inv;
    }
}

// ---------------- RoPE: rotate + hi/lo split ----------------
__global__ void rope_kernel(const float* __restrict__ q,
                            const float* __restrict__ k,
                            float* __restrict__ qhi, float* __restrict__ qlo,
                            float* __restrict__ khi, float* __restrict__ klo) {
    int s = blockIdx.x;
    int h = blockIdx.y;
    int j = threadIdx.x;
    float inv = exp2f(-(float)j * 0.31143075889569023f);
    float ang = (float)s * inv;
    float c, sn;
    sincosf(ang, &sn, &c);
    long long base = ((long long)s * NH + h) * D;
    float q1 = q[base + j], q2 = q[base + j + 64];
    float k1 = k[base + j], k2 = k[base + j + 64];
    float qa = q1 * c - q2 * sn;
    float qb = q2 * c + q1 * sn;
    float ka = k1 * c - k2 * sn;
    float kb = k2 * c + k1 * sn;
    float t;
    t = f2tf32f(qa); qhi[base + j] = t; qlo[base + j] = f2tf32f(qa - t);
    t = f2tf32f(qb); qhi[base + j + 64] = t; qlo[base + j + 64] = f2tf32f(qb - t);
    t = f2tf32f(ka); khi[base + j] = t; klo[base + j] = f2tf32f(ka - t);
    t = f2tf32f(kb); khi[base + j + 64] = t; klo[base + j + 64] = f2tf32f(kb - t);
}

// ---------------- causal row softmax, hi/lo output ----------------
__global__ void softmax_kernel(float* __restrict__ scores,
                               float* __restrict__ slo) {
    int r = blockIdx.x;
    float* row = scores + ((size_t)blockIdx.y * S + r) * S;
    float* lrow = slo + ((size_t)blockIdx.y * S + r) * S;
    const int limit = r + 1;
    const int rBlk = ((r >> 7) + 1) << 7;
    __shared__ float red[256];
    int tid = threadIdx.x;
    float m = -FLT_MAX;
    for (int j = tid; j < limit; j += 256) m = fmaxf(m, row[j]);
    red[tid] = m;
    __syncthreads();
    for (int st = 128; st > 0; st >>= 1) {
        if (tid < st) red[tid] = fmaxf(red[tid], red[tid + st]);
        __syncthreads();
    }
    m = red[0];
    __syncthreads();
    float sum = 0.f;
    for (int j = tid; j < limit; j += 256) {
        float e = expf(row[j] - m);
        row[j] = e;
        sum += e;
    }
    red[tid] = sum;
    __syncthreads();
    for (int st = 128; st > 0; st >>= 1) {
        if (tid < st) red[tid] += red[tid + st];
        __syncthreads();
    }
    float inv = 1.0f / red[0];
    for (int j = tid; j < limit; j += 256) {
        float p = row[j] * inv;
        float hi = f2tf32f(p);
        row[j] = hi;
        lrow[j] = f2tf32f(p - hi);
    }
    for (int j = limit + tid; j < rBlk; j += 256) {
        row[j] = 0.f;
        lrow[j] = 0.f;
    }
}

// ---------------- router ----------------
__global__ void router_kernel(const float* __restrict__ h2,
                              const float* __restrict__ gate_w,
                              float* __restrict__ logits_out,
                              int* __restrict__ idxbuf,
                              int* __restrict__ cnt,
                              int* __restrict__ tokmap,
                              float* __restrict__ tokw) {
    int s = blockIdx.x;
    const float* hr = h2 + (long long)s * H;
    __shared__ float red[256][E];
    float p[E];
#pragma unroll
    for (int e = 0; e < E; e++) p[e] = 0.f;
    for (int j = threadIdx.x; j < H; j += 256) {
        float hv = hr[j];
#pragma unroll
        for (int e = 0; e < E; e++) p[e] += hv * gate_w[j * E + e];
    }
#pragma unroll
    for (int e = 0; e < E; e++) red[threadIdx.x][e] = p[e];
    __syncthreads();
    for (int st = 128; st > 0; st >>= 1) {
        if (threadIdx.x < st)
#pragma unroll
            for (int e = 0; e < E; e++) red[threadIdx.x][e] += red[threadIdx.x + st][e];
        __syncthreads();
    }
    if (threadIdx.x == 0) {
        float logit[E];
        float m = -FLT_MAX;
#pragma unroll
        for (int e = 0; e < E; e++) {
            logit[e] = red[0][e];
            logits_out[(long long)s * E + e] = logit[e];
            m = fmaxf(m, logit[e]);
        }
        float sum = 0.f, rw[E];
#pragma unroll
        for (int e = 0; e < E; e++) {
            rw[e] = expf(logit[e] - m);
            sum += rw[e];
        }
        float inv = 1.0f / sum;
#pragma unroll
        for (int e = 0; e < E; e++) rw[e] *= inv;
        bool used[E];
#pragma unroll
        for (int e = 0; e < E; e++) used[e] = false;
        for (int k = 0; k < TOPK; k++) {
            int best = -1;
            float bvv = -FLT_MAX;
            for (int e = 0; e < E; e++)
                if (!used[e] && rw[e] > bvv) { bvv = rw[e]; best = e; }
            used[best] = true;
            int pos = atomicAdd(&cnt[best], 1);
            idxbuf[best * S + pos] = s;
            tokmap[s * TOPK + k] = best * S + pos;
            tokw[s * TOPK + k] = bvv;
        }
    }
}

// ---------------- h2 . sgate ----------------
__global__ void rowdot_kernel(const float* __restrict__ h2,
                              const float* __restrict__ sgate,
                              float* __restrict__ gatev) {
    int s = blockIdx.x;
    const float* hr = h2 + (long long)s * H;
    __shared__ float red[256];
    float acc = 0.f;
    for (int j = threadIdx.x; j < H; j += 256) acc += hr[j] * sgate[j];
    red[threadIdx.x] = acc;
    __syncthreads();
    for (int st = 128; st > 0; st >>= 1) {
        if (threadIdx.x < st) red[threadIdx.x] += red[threadIdx.x + st];
        __syncthreads();
    }
    if (threadIdx.x == 0) gatev[s] = red[0];
}

// ---------------- silu kernels ----------------
__global__ void silu_mul_expert_kernel(float* __restrict__ gb,
                                       const float* __restrict__ ub,
                                       const int* __restrict__ cnt) {
    int e = blockIdx.y;
    long long i = (long long)blockIdx.x * 256 + threadIdx.x;
    long long lim = (long long)cnt[e] * IE;
    if (i >= lim) return;
    size_t o = (size_t)e * S * IE + i;
    float x = gb[o];
    float sg = 1.0f / (1.0f + expf(-x));
    gb[o] = f2tf32f(x * sg * ub[o]);
}
__global__ void silu_mul_kernel(float* __restrict__ g, const float* __restrict__ u,
                                long long n) {
    long long i = (long long)blockIdx.x * 256 + threadIdx.x;
    if (i < n) {
        float x = g[i];
        float sg = 1.0f / (1.0f + expf(-x));
        g[i] = f2tf32f(x * sg * u[i]);
    }
}

// ---------------- final combine ----------------
__global__ void final_kernel(const float* __restrict__ x1,
                             const float* __restrict__ eo,
                             const int* __restrict__ tokmap,
                             const float* __restrict__ tokw,
                             const float* __restrict__ sdwn,
                             const float* __restrict__ gatev,
                             float* __restrict__ out) {
    long long i = (long long)blockIdx.x * 256 + threadIdx.x;
    int s = (int)(i / H);
    int c = (int)(i % H);
    float gv = 1.0f / (1.0f + expf(-gatev[s]));
    float acc = x1[i] + gv * sdwn[i];
#pragma unroll
    for (int j = 0; j < TOPK; j++) {
        int row = tokmap[s * TOPK + j];
        acc += tokw[s * TOPK + j] * eo[(size_t)row * H + c];
    }
    out[i] = acc;
}

// ---------------- host ----------------
static void launch_mma(const float* A, int lda, long long aStrE,
                       const float* B0, const float* B1, int ldb, long long bStrE,
                       float* C0, float* C1, int ldc, long long cStrE,
                       int M, int N, int K,
                       const int* gidx, int gstr, const int* cnt, int eShift,
                       int nz) {
    dim3 grid(N / 128, (M + 127) / 128, nz);
    mma_gemm_kernel<<<grid, 128, MMA_SMEM>>>(A, lda, aStrE, B0, B1, ldb, bStrE,
                                             C0, C1, ldc, cStrE, M, N, K,
                                             gidx, gstr, cnt, eShift);
}

extern "C" void kernel_launch(void* const* d_in, const int* in_sizes, int n_in,
                              void* d_out, int out_size) {
    (void)in_sizes; (void)n_in; (void)out_size;
    const float* x     = (const float*)d_in[0];
    const float* ln1   = (const float*)d_in[1];
    const float* ln2   = (const float*)d_in[2];
    const float* wq    = (const float*)d_in[3];
    const float* bq    = (const float*)d_in[4];
    const float* wk    = (const float*)d_in[5];
    const float* bk    = (const float*)d_in[6];
    const float* wv    = (const float*)d_in[7];
    const float* bv    = (const float*)d_in[8];
    const float* wo    = (const float*)d_in[9];
    const float* gatew = (const float*)d_in[10];
    const float* eg    = (const float*)d_in[11];
    const float* eu    = (const float*)d_in[12];
    const float* ed    = (const float*)d_in[13];
    const float* sg    = (const float*)d_in[14];
    const float* su    = (const float*)d_in[15];
    const float* sd    = (const float*)d_in[16];
    const float* sgate = (const float*)d_in[17];
    float* out = (float*)d_out;

    cudaFuncSetAttribute(mma_gemm_kernel,
                         cudaFuncAttributeMaxDynamicSharedMemorySize, MMA_SMEM);
    cudaFuncSetAttribute(mma3x_kernel,
                         cudaFuncAttributeMaxDynamicSharedMemorySize, X_SMEM);
    cudaFuncSetAttribute(sc3x_kernel,
                         cudaFuncAttributeMaxDynamicSharedMemorySize, SC_SMEM);
    cudaFuncSetAttribute(pv3x_kernel,
                         cudaFuncAttributeMaxDynamicSharedMemorySize, X_SMEM);

    float *hhi, *hlo, *q, *k, *qhi, *qlo, *khi, *klo, *vhi, *vlo, *scores,
        *slo, *ahi, *alo, *x1, *h2, *ch2, *gb, *ub, *eo, *sgb, *sub,
        *sdwn, *gatev, *tokw, *wsp;
    int *idx, *cnt, *tokmap;
    cudaGetSymbolAddress((void**)&hhi, g_hhi);
    cudaGetSymbolAddress((void**)&hlo, g_hlo);
    cudaGetSymbolAddress((void**)&q, g_q);
    cudaGetSymbolAddress((void**)&k, g_k);
    cudaGetSymbolAddress((void**)&qhi, g_qhi);
    cudaGetSymbolAddress((void**)&qlo, g_qlo);
    cudaGetSymbolAddress((void**)&khi, g_khi);
    cudaGetSymbolAddress((void**)&klo, g_klo);
    cudaGetSymbolAddress((void**)&vhi, g_vhi);
    cudaGetSymbolAddress((void**)&vlo, g_vlo);
    cudaGetSymbolAddress((void**)&scores, g_scores);
    cudaGetSymbolAddress((void**)&slo, g_slo);
    cudaGetSymbolAddress((void**)&ahi, g_ahi);
    cudaGetSymbolAddress((void**)&alo, g_alo);
    cudaGetSymbolAddress((void**)&x1, g_x1);
    cudaGetSymbolAddress((void**)&h2, g_h2);
    cudaGetSymbolAddress((void**)&ch2, g_ch2);
    cudaGetSymbolAddress((void**)&gb, g_gb);
    cudaGetSymbolAddress((void**)&ub, g_ub);
    cudaGetSymbolAddress((void**)&eo, g_eo);
    cudaGetSymbolAddress((void**)&sgb, g_sgb);
    cudaGetSymbolAddress((void**)&sub, g_sub);
    cudaGetSymbolAddress((void**)&sdwn, g_sdwn);
    cudaGetSymbolAddress((void**)&gatev, g_gatev);
    cudaGetSymbolAddress((void**)&idx, g_idx);
    cudaGetSymbolAddress((void**)&cnt, g_cnt);
    cudaGetSymbolAddress((void**)&tokmap, g_tokmap);
    cudaGetSymbolAddress((void**)&tokw, g_tokw);
    cudaGetSymbolAddress((void**)&wsp, g_wsp);

    const size_t WW = (size_t)H * H;
    const float* wqh = wsp;
    const float* wql = wsp + WW;
    const float* wkh = wsp + 2 * WW;
    const float* wkl = wsp + 3 * WW;
    const float* wvh = wsp + 4 * WW;
    const float* wvl = wsp + 5 * WW;
    const float* woh = wsp + 6 * WW;
    const float* wol = wsp + 7 * WW;

    const float ascale = 0.08838834764831845f;

    // 0. weight prep: only attention hi/lo splits (MoE weights fed raw;
    //    tensor-core HW truncates fp32->tf32)
    {
        unsigned gx = (unsigned)((WW / 4 + 255) / 256);
        dim3 grid(gx, 4);
        prep_kernel<<<grid, 256>>>((const float4*)wq, (const float4*)wk,
                                   (const float4*)wv, (const float4*)wo,
                                   (float4*)wsp);
    }

    // 1. h = rmsnorm(x, ln1), hi/lo split
    rmsnorm_kernel<<<S, 256>>>(x, ln1, hhi, nullptr, hlo);

    // 2. q,k,v via 3xTF32; v written pre-split (hi->vhi, lo->vlo)
    {
        dim3 grid(16, 16, 3);
        mma3x_kernel<<<grid, 128, X_SMEM>>>(
            hhi, hlo, H, wqh, wql, wkh, wkl, wvh, wvl, NH * D,
            bq, bk, bv, q, k, vhi, vlo, NH * D, nullptr, H);
    }

    // 3. RoPE + q/k hi-lo split
    rope_kernel<<<dim3(S, NH), 64>>>(q, k, qhi, qlo, khi, klo);

    // 4. scores via 3xTF32 (causal blocks only)
    {
        dim3 grid(S / 128, S / 128, NH);
        sc3x_kernel<<<grid, 128, SC_SMEM>>>(qhi, qlo, khi, klo, scores, ascale);
    }

    // 5. softmax -> probs hi (in place) + lo
    softmax_kernel<<<dim3(S, NH), 256>>>(scores, slo);

    // 6. attn = probs @ v via 3xTF32 (K bounded at diagonal); writes ahi/alo
    {
        dim3 grid(1, S / 128, NH);
        pv3x_kernel<<<grid, 128, X_SMEM>>>(scores, slo, vhi, vlo, ahi, alo);
    }

    // 7. x1 = x + attn @ wo via 3xTF32
    {
        dim3 grid(16, 16, 1);
        mma3x_kernel<<<grid, 128, X_SMEM>>>(
            ahi, alo, NH * D, woh, wol, nullptr, nullptr, nullptr, nullptr, H,
            nullptr, nullptr, nullptr, x1, nullptr, nullptr, nullptr, H, x,
            NH * D);
    }

    // 8. h2 = rmsnorm(x1, ln2) + tf32 copy (activations stay RNA-rounded)
    rmsnorm_kernel<<<S, 256>>>(x1, ln2, h2, ch2, nullptr);

    // 9. router
    cudaMemsetAsync(cnt, 0, E * sizeof(int));
    router_kernel<<<S, 256>>>(h2, gatew, out + (long long)S * H, idx, cnt,
                              tokmap, tokw);

    // 10. MoE gate+up (raw fp32 weights)
    launch_mma(ch2, H, 0, eg, eu, IE, (long long)H * IE,
               gb, ub, IE, (long long)S * IE, S, IE, H, idx, S, cnt, 1, 2 * E);

    // 11. silu
    {
        dim3 grid((unsigned)(((long long)S * IE + 255) / 256), E);
        silu_mul_expert_kernel<<<grid, 256>>>(gb, ub, cnt);
    }

    // 12. MoE down (raw fp32 weights)
    launch_mma(gb, IE, (long long)S * IE, ed, nullptr, H, (long long)IE * H,
               eo, nullptr, H, (long long)S * H, S, H, IE, nullptr, 0, cnt, 0, E);

    // 13. shared expert (raw fp32 weights)
    launch_mma(ch2, H, 0, sg, su, IS, 0, sgb, sub, IS, 0, S, IS, H,
               nullptr, 0, nullptr, 1, 2);
    {
        long long n = (long long)S * IS;
        silu_mul_kernel<<<(unsigned)((n + 255) / 256), 256>>>(sgb, sub, n);
    }
    launch_mma(sgb, IS, 0, sd, nullptr, H, 0, sdwn, nullptr, H, 0, S, H, IS,
               nullptr, 0, nullptr, 0, 1);

    // 14. gate scalar
    rowdot_kernel<<<S, 256>>>(h2, sgate, gatev);

    // 15. combine
    final_kernel<<<(S * H) / 256, 256>>>(x1, eo, tokmap, tokw, sdwn, gatev, out);
}

// round 16
// speedup vs baseline: 1.1914x; 1.0349x over previous
#include <cuda_runtime.h>
#include <cuda_bf16.h>
#include <math.h>
#include <float.h>
#include <stdint.h>

#define S 2048
#define H 2048
#define NH 16
#define D 128
#define E 8
#define TOPK 4
#define IE 1408
#define IS 5632

// ---------------- scratch ----------------
__device__ float g_hhi[S * H];
__device__ float g_hlo[S * H];
__device__ float g_q[S * H];
__device__ float g_k[S * H];
__device__ float g_qhi[S * H];
__device__ float g_qlo[S * H];
__device__ float g_khi[S * H];
__device__ float g_klo[S * H];
__device__ float g_vhi[S * H];
__device__ float g_vlo[S * H];
__device__ float g_scores[(size_t)NH * S * S];
__device__ float g_slo[(size_t)NH * S * S];
__device__ float g_pvpart[(size_t)4 * S * H];
__device__ float g_ahi[S * H];
__device__ float g_alo[S * H];
__device__ float g_x1[S * H];
__device__ float g_h2[S * H];
__device__ float g_ch2[S * H];
__device__ float g_gb[(size_t)E * S * IE];
__device__ float g_ub[(size_t)E * S * IE];
__device__ float g_eo[(size_t)E * S * H];
__device__ float g_sgb[S * IS];
__device__ float g_sub[S * IS];
__device__ float g_sdwn[S * H];
__device__ float g_gatev[S];
__device__ int g_idx[E * S];
__device__ int g_cnt[E];
__device__ int g_tokmap[S * TOPK];
__device__ float g_tokw[S * TOPK];
__device__ float g_wsp[(size_t)8 * H * H];

// ================= helpers =================
__device__ __forceinline__ uint32_t smem_to_u32(const void* p) {
    uint32_t a;
    asm("{ .reg .u64 t; cvta.to.shared.u64 t, %1; cvt.u32.u64 %0, t; }"
        : "=r"(a) : "l"(p));
    return a;
}
__device__ __forceinline__ float f2tf32f(float f) {
    uint32_t r;
    asm("cvt.rna.tf32.f32 %0, %1;" : "=r"(r) : "f"(f));
    return __uint_as_float(r);
}
__device__ __forceinline__ void mma_tf32(float* d, const uint32_t* a,
                                         const uint32_t* b) {
    asm volatile(
        "mma.sync.aligned.m16n8k8.row.col.f32.tf32.tf32.f32 "
        "{%0,%1,%2,%3}, {%4,%5,%6,%7}, {%8,%9}, {%0,%1,%2,%3};"
        : "+f"(d[0]), "+f"(d[1]), "+f"(d[2]), "+f"(d[3])
        : "r"(a[0]), "r"(a[1]), "r"(a[2]), "r"(a[3]), "r"(b[0]), "r"(b[1]));
}
__device__ __forceinline__ void cp_async16(uint32_t dst, const void* src) {
    asm volatile("cp.async.ca.shared.global [%0], [%1], 16;"
                 :: "r"(dst), "l"(src));
}

// ================= tf32 mma GEMM v3 (MoE path, 4-stage) =======================
// B operands are raw fp32 (HW truncates to tf32); A operands RNA-pre-rounded.
#define APADF 20
#define BPADF 136
#define A_STAGE_B (128 * APADF * 4)
#define B_STAGE_B (16 * BPADF * 4)
#define STAGE_B (A_STAGE_B + B_STAGE_B)
#define MMA_SMEM (STAGE_B * 4)

__global__ __launch_bounds__(128, 2)
void mma_gemm_kernel(const float* __restrict__ A, int lda, long long aStrE,
                     const float* __restrict__ B0, const float* __restrict__ B1,
                     int ldb, long long bStrE,
                     float* __restrict__ C0, float* __restrict__ C1,
                     int ldc, long long cStrE,
                     int M, int N, int K,
                     const int* __restrict__ gidxBase, int gidxStr,
                     const int* __restrict__ cntBase, int eShift) {
    extern __shared__ char smem[];
    const uint32_t sb = smem_to_u32(smem);
    const int z = blockIdx.z;
    const int e = z >> eShift;
    const int which = z & ((1 << eShift) - 1);
    const float* B = (which ? B1 : B0) + (long long)e * bStrE;
    float* C = (which ? C1 : C0) + (long long)e * cStrE;
    A += (long long)e * aStrE;

    const int cnt = cntBase ? cntBase[e] : M;
    const int mEff = min(M, cnt);
    const int row0 = blockIdx.y * 128;
    const int col0 = blockIdx.x * 128;
    if (row0 >= mEff) return;
    const int* gidx = gidxBase ? gidxBase + (long long)e * gidxStr : nullptr;

    const int tid = threadIdx.x;
    const int wid = tid >> 5;
    const int lane = tid & 31;
    const int g = lane >> 2;
    const int t4 = lane & 3;
    const int warpM = wid >> 1;
    const int warpN = wid & 1;

    const float* aG[4];
    uint32_t aS[4];
#pragma unroll
    for (int j = 0; j < 4; j++) {
        int u = tid + 128 * j;
        int m = u >> 2, c4 = u & 3;
        int arow = row0 + m;
        int src;
        if (gidx) src = (arow < cnt) ? gidx[arow] : 0;
        else src = min(arow, M - 1);
        aG[j] = A + (size_t)src * lda + c4 * 4;
        aS[j] = sb + (uint32_t)(m * APADF + c4 * 4) * 4u;
    }
    const float* bG[4];
    uint32_t bS[4];
#pragma unroll
    for (int j = 0; j < 4; j++) {
        int u = tid + 128 * j;
        int n4 = u & 31, kk = u >> 5;
        bG[j] = B + (size_t)kk * ldb + col0 + n4 * 4;
        bS[j] = sb + A_STAGE_B + (uint32_t)(kk * BPADF + n4 * 4) * 4u;
    }

    float acc[4][8][4];
#pragma unroll
    for (int mt = 0; mt < 4; mt++)
#pragma unroll
        for (int nt = 0; nt < 8; nt++)
#pragma unroll
            for (int r = 0; r < 4; r++) acc[mt][nt][r] = 0.f;

    const int nT = K / 16;

#define ISSUE(i)                                                      \
    do {                                                              \
        uint32_t _off = (uint32_t)((i) & 3) * STAGE_B;                \
        int _k0 = (i) * 16;                                           \
        cp_async16(aS[0] + _off, aG[0] + _k0);                        \
        cp_async16(aS[1] + _off, aG[1] + _k0);                        \
        cp_async16(aS[2] + _off, aG[2] + _k0);                        \
        cp_async16(aS[3] + _off, aG[3] + _k0);                        \
        cp_async16(bS[0] + _off, bG[0] + (size_t)_k0 * ldb);          \
        cp_async16(bS[1] + _off, bG[1] + (size_t)_k0 * ldb);          \
        cp_async16(bS[2] + _off, bG[2] + (size_t)_k0 * ldb);          \
        cp_async16(bS[3] + _off, bG[3] + (size_t)_k0 * ldb);          \
        asm volatile("cp.async.commit_group;");                       \
    } while (0)

    ISSUE(0);
    if (nT > 1) ISSUE(1);
    if (nT > 2) ISSUE(2);

    for (int i = 0; i < nT; i++) {
        const int rem = nT - 1 - i;
        if (rem >= 2)
            asm volatile("cp.async.wait_group 2;");
        else if (rem == 1)
            asm volatile("cp.async.wait_group 1;");
        else
            asm volatile("cp.async.wait_group 0;");
        __syncthreads();
        if (i + 3 < nT) ISSUE(i + 3);

        const uint32_t* Asb =
            (const uint32_t*)(smem + (size_t)(i & 3) * STAGE_B);
        const uint32_t* Bsb =
            (const uint32_t*)(smem + (size_t)(i & 3) * STAGE_B + A_STAGE_B);
#pragma unroll
        for (int kk = 0; kk < 16; kk += 8) {
            uint32_t a[4][4], b[8][2];
#pragma unroll
            for (int mt = 0; mt < 4; mt++) {
                int mrow = warpM * 64 + mt * 16;
                a[mt][0] = Asb[(mrow + g) * APADF + kk + t4];
                a[mt][1] = Asb[(mrow + g + 8) * APADF + kk + t4];
                a[mt][2] = Asb[(mrow + g) * APADF + kk + t4 + 4];
                a[mt][3] = Asb[(mrow + g + 8) * APADF + kk + t4 + 4];
            }
#pragma unroll
            for (int nt = 0; nt < 8; nt++) {
                int ncol = warpN * 64 + nt * 8;
                b[nt][0] = Bsb[(kk + t4) * BPADF + ncol + g];
                b[nt][1] = Bsb[(kk + t4 + 4) * BPADF + ncol + g];
            }
#pragma unroll
            for (int mt = 0; mt < 4; mt++)
#pragma unroll
                for (int nt = 0; nt < 8; nt++)
                    mma_tf32(acc[mt][nt], a[mt], b[nt]);
        }
    }
#undef ISSUE

#pragma unroll
    for (int mt = 0; mt < 4; mt++) {
        int rBase = row0 + warpM * 64 + mt * 16 + g;
#pragma unroll
        for (int half = 0; half < 2; half++) {
            int r = rBase + half * 8;
            if (r >= mEff) continue;
            float* cp = C + (size_t)r * ldc;
#pragma unroll
            for (int nt = 0; nt < 8; nt++) {
                int col = col0 + warpN * 64 + nt * 8 + t4 * 2;
                cp[col] = acc[mt][nt][half * 2 + 0];
                cp[col + 1] = acc[mt][nt][half * 2 + 1];
            }
        }
    }
}

// ================= 3xTF32 mma GEMM (QKV / wo) ==========
#define X_APAD 12
#define X_BPAD 136
#define X_A_B (128 * X_APAD * 4)
#define X_B_B (8 * X_BPAD * 4)
#define X_STAGE (2 * X_A_B + 2 * X_B_B)
#define X_SMEM (X_STAGE * 4)

__global__ __launch_bounds__(128, 2)
void mma3x_kernel(const float* __restrict__ Ahi, const float* __restrict__ Alo,
                  int lda,
                  const float* __restrict__ B0h, const float* __restrict__ B0l,
                  const float* __restrict__ B1h, const float* __restrict__ B1l,
                  const float* __restrict__ B2h, const float* __restrict__ B2l,
                  int ldb,
                  const float* __restrict__ bias0,
                  const float* __restrict__ bias1,
                  const float* __restrict__ bias2,
                  float* __restrict__ C0, float* __restrict__ C1,
                  float* __restrict__ C2, float* __restrict__ C2lo, int ldc,
                  const float* __restrict__ residual,
                  int K) {
    extern __shared__ char smem[];
    const uint32_t sb = smem_to_u32(smem);
    const int z = blockIdx.z;
    const float* Bh = (z == 0) ? B0h : (z == 1 ? B1h : B2h);
    const float* Bl = (z == 0) ? B0l : (z == 1 ? B1l : B2l);
    const float* bias = (z == 0) ? bias0 : (z == 1 ? bias1 : bias2);
    float* C = (z == 0) ? C0 : (z == 1 ? C1 : C2);
    float* Clo = (z == 2) ? C2lo : nullptr;

    const int row0 = blockIdx.y * 128;
    const int col0 = blockIdx.x * 128;

    const int tid = threadIdx.x;
    const int wid = tid >> 5;
    const int lane = tid & 31;
    const int g = lane >> 2;
    const int t4 = lane & 3;
    const int warpM = wid >> 1;
    const int warpN = wid & 1;

    const long long aLoD = Alo - Ahi;
    const long long bLoD = Bl - Bh;

    const float* aGh[2];
    uint32_t aSh[2];
#pragma unroll
    for (int j = 0; j < 2; j++) {
        int u = tid + 128 * j;
        int m = u >> 1, c4 = u & 1;
        aGh[j] = Ahi + (size_t)(row0 + m) * lda + c4 * 4;
        aSh[j] = sb + (uint32_t)(m * X_APAD + c4 * 4) * 4u;
    }
    const float* bGh[2];
    uint32_t bSh[2];
#pragma unroll
    for (int j = 0; j < 2; j++) {
        int u = tid + 128 * j;
        int kk = u >> 5, n4 = u & 31;
        bGh[j] = Bh + (size_t)kk * ldb + col0 + n4 * 4;
        bSh[j] = sb + (uint32_t)(2 * X_A_B) +
                 (uint32_t)(kk * X_BPAD + n4 * 4) * 4u;
    }

    float acc[4][8][4];
#pragma unroll
    for (int mt = 0; mt < 4; mt++)
#pragma unroll
        for (int nt = 0; nt < 8; nt++)
#pragma unroll
            for (int r = 0; r < 4; r++) acc[mt][nt][r] = 0.f;

    const int nT = K / 8;

#define XISSUE(i)                                                       \
    do {                                                                \
        uint32_t _off = (uint32_t)((i) & 3) * X_STAGE;                  \
        int _k0 = (i) * 8;                                              \
        cp_async16(aSh[0] + _off, aGh[0] + _k0);                        \
        cp_async16(aSh[1] + _off, aGh[1] + _k0);                        \
        cp_async16(aSh[0] + X_A_B + _off, aGh[0] + aLoD + _k0);         \
        cp_async16(aSh[1] + X_A_B + _off, aGh[1] + aLoD + _k0);         \
        cp_async16(bSh[0] + _off, bGh[0] + (size_t)_k0 * ldb);          \
        cp_async16(bSh[1] + _off, bGh[1] + (size_t)_k0 * ldb);          \
        cp_async16(bSh[0] + X_B_B + _off, bGh[0] + bLoD + (size_t)_k0 * ldb); \
        cp_async16(bSh[1] + X_B_B + _off, bGh[1] + bLoD + (size_t)_k0 * ldb); \
        asm volatile("cp.async.commit_group;");                         \
    } while (0)

    XISSUE(0);
    XISSUE(1);
    XISSUE(2);

    for (int i = 0; i < nT; i++) {
        const int rem = nT - 1 - i;
        if (rem >= 2)
            asm volatile("cp.async.wait_group 2;");
        else if (rem == 1)
            asm volatile("cp.async.wait_group 1;");
        else
            asm volatile("cp.async.wait_group 0;");
        __syncthreads();
        if (i + 3 < nT) XISSUE(i + 3);

        const uint32_t* Ah = (const uint32_t*)(smem + (size_t)(i & 3) * X_STAGE);
        const uint32_t* Al = Ah + (X_A_B / 4);
        const uint32_t* Bhs =
            (const uint32_t*)(smem + (size_t)(i & 3) * X_STAGE + 2 * X_A_B);
        const uint32_t* Bls = Bhs + (X_B_B / 4);

        uint32_t ah[4][4], al[4][4], bh[8][2], bl[8][2];
#pragma unroll
        for (int mt = 0; mt < 4; mt++) {
            int mrow = warpM * 64 + mt * 16;
            ah[mt][0] = Ah[(mrow + g) * X_APAD + t4];
            ah[mt][1] = Ah[(mrow + g + 8) * X_APAD + t4];
            ah[mt][2] = Ah[(mrow + g) * X_APAD + t4 + 4];
            ah[mt][3] = Ah[(mrow + g + 8) * X_APAD + t4 + 4];
            al[mt][0] = Al[(mrow + g) * X_APAD + t4];
            al[mt][1] = Al[(mrow + g + 8) * X_APAD + t4];
            al[mt][2] = Al[(mrow + g) * X_APAD + t4 + 4];
            al[mt][3] = Al[(mrow + g + 8) * X_APAD + t4 + 4];
        }
#pragma unroll
        for (int nt = 0; nt < 8; nt++) {
            int ncol = warpN * 64 + nt * 8;
            bh[nt][0] = Bhs[t4 * X_BPAD + ncol + g];
            bh[nt][1] = Bhs[(t4 + 4) * X_BPAD + ncol + g];
            bl[nt][0] = Bls[t4 * X_BPAD + ncol + g];
            bl[nt][1] = Bls[(t4 + 4) * X_BPAD + ncol + g];
        }
#pragma unroll
        for (int mt = 0; mt < 4; mt++)
#pragma unroll
            for (int nt = 0; nt < 8; nt++) {
                mma_tf32(acc[mt][nt], ah[mt], bh[nt]);
                mma_tf32(acc[mt][nt], ah[mt], bl[nt]);
                mma_tf32(acc[mt][nt], al[mt], bh[nt]);
            }
    }
#undef XISSUE

#pragma unroll
    for (int mt = 0; mt < 4; mt++) {
        int rBase = row0 + warpM * 64 + mt * 16 + g;
#pragma unroll
        for (int half = 0; half < 2; half++) {
            int r = rBase + half * 8;
            float* cp = C + (size_t)r * ldc;
            float* cl = Clo ? Clo + (size_t)r * ldc : nullptr;
            const float* rp = residual ? residual + (size_t)r * ldc : nullptr;
#pragma unroll
            for (int nt = 0; nt < 8; nt++) {
                int col = col0 + warpN * 64 + nt * 8 + t4 * 2;
                float v0 = acc[mt][nt][half * 2 + 0];
                float v1 = acc[mt][nt][half * 2 + 1];
                if (bias) {
                    v0 += bias[col];
                    v1 += bias[col + 1];
                }
                if (rp) {
                    v0 += rp[col];
                    v1 += rp[col + 1];
                }
                if (cl) {
                    float h0 = f2tf32f(v0), h1 = f2tf32f(v1);
                    cp[col] = h0;
                    cp[col + 1] = h1;
                    cl[col] = f2tf32f(v0 - h0);
                    cl[col + 1] = f2tf32f(v1 - h1);
                } else {
                    cp[col] = v0;
                    cp[col + 1] = v1;
                }
            }
        }
    }
}

// ================= 3xTF32 scores kernel (Q·K^T, causal) =======================
#define SC_HALF (128 * X_APAD * 4)
#define SC_STAGE (4 * SC_HALF)
#define SC_SMEM (SC_STAGE * 3)

__global__ __launch_bounds__(128, 2)
void sc3x_kernel(const float* __restrict__ qhi, const float* __restrict__ qlo,
                 const float* __restrict__ khi, const float* __restrict__ klo,
                 float* __restrict__ scores, float scale) {
    extern __shared__ char smem[];
    const uint32_t sb = smem_to_u32(smem);
    const int h = blockIdx.z;
    const int row0 = blockIdx.y * 128;
    const int col0 = blockIdx.x * 128;
    if (col0 > row0) return;

    const int lda = NH * D;
    const float* Ah = qhi + (size_t)h * D;
    const float* Bh = khi + (size_t)h * D;
    const long long aLoD = qlo - qhi;
    const long long bLoD = klo - khi;

    const int tid = threadIdx.x;
    const int wid = tid >> 5;
    const int lane = tid & 31;
    const int g = lane >> 2;
    const int t4 = lane & 3;
    const int warpM = wid >> 1;
    const int warpN = wid & 1;

    const float* aGh[2];
    uint32_t aSh[2];
    const float* bGh[2];
    uint32_t bSh[2];
#pragma unroll
    for (int j = 0; j < 2; j++) {
        int u = tid + 128 * j;
        int m = u >> 1, c4 = u & 1;
        aGh[j] = Ah + (size_t)(row0 + m) * lda + c4 * 4;
        aSh[j] = sb + (uint32_t)(m * X_APAD + c4 * 4) * 4u;
        bGh[j] = Bh + (size_t)(col0 + m) * lda + c4 * 4;
        bSh[j] = sb + (uint32_t)(2 * SC_HALF) +
                 (uint32_t)(m * X_APAD + c4 * 4) * 4u;
    }

    float acc[4][8][4];
#pragma unroll
    for (int mt = 0; mt < 4; mt++)
#pragma unroll
        for (int nt = 0; nt < 8; nt++)
#pragma unroll
            for (int r = 0; r < 4; r++) acc[mt][nt][r] = 0.f;

    const int nT = D / 8;
    const uint32_t stOff[3] = {0u, SC_STAGE, 2u * SC_STAGE};

#define SISSUE(i, st)                                                  \
    do {                                                               \
        uint32_t _off = stOff[st];                                     \
        int _k0 = (i) * 8;                                             \
        cp_async16(aSh[0] + _off, aGh[0] + _k0);                       \
        cp_async16(aSh[1] + _off, aGh[1] + _k0);                       \
        cp_async16(aSh[0] + SC_HALF + _off, aGh[0] + aLoD + _k0);      \
        cp_async16(aSh[1] + SC_HALF + _off, aGh[1] + aLoD + _k0);      \
        cp_async16(bSh[0] + _off, bGh[0] + _k0);                       \
        cp_async16(bSh[1] + _off, bGh[1] + _k0);                       \
        cp_async16(bSh[0] + SC_HALF + _off, bGh[0] + bLoD + _k0);      \
        cp_async16(bSh[1] + SC_HALF + _off, bGh[1] + bLoD + _k0);      \
        asm volatile("cp.async.commit_group;");                        \
    } while (0)

    SISSUE(0, 0);
    SISSUE(1, 1);

    int stC = 0, stI = 2;
    for (int i = 0; i < nT; i++) {
        if (i + 1 < nT)
            asm volatile("cp.async.wait_group 1;");
        else
            asm volatile("cp.async.wait_group 0;");
        __syncthreads();
        if (i + 2 < nT) {
            SISSUE(i + 2, stI);
            stI = (stI == 2) ? 0 : stI + 1;
        }
        const uint32_t* Ah2 = (const uint32_t*)(smem + stOff[stC]);
        const uint32_t* Al2 = Ah2 + (SC_HALF / 4);
        const uint32_t* Bh2 = (const uint32_t*)(smem + stOff[stC] + 2 * SC_HALF);
        const uint32_t* Bl2 = Bh2 + (SC_HALF / 4);
        stC = (stC == 2) ? 0 : stC + 1;

        uint32_t ah[4][4], al[4][4], bh[8][2], bl[8][2];
#pragma unroll
        for (int mt = 0; mt < 4; mt++) {
            int mrow = warpM * 64 + mt * 16;
            ah[mt][0] = Ah2[(mrow + g) * X_APAD + t4];
            ah[mt][1] = Ah2[(mrow + g + 8) * X_APAD + t4];
            ah[mt][2] = Ah2[(mrow + g) * X_APAD + t4 + 4];
            ah[mt][3] = Ah2[(mrow + g + 8) * X_APAD + t4 + 4];
            al[mt][0] = Al2[(mrow + g) * X_APAD + t4];
            al[mt][1] = Al2[(mrow + g + 8) * X_APAD + t4];
            al[mt][2] = Al2[(mrow + g) * X_APAD + t4 + 4];
            al[mt][3] = Al2[(mrow + g + 8) * X_APAD + t4 + 4];
        }
#pragma unroll
        for (int nt = 0; nt < 8; nt++) {
            int ncol = warpN * 64 + nt * 8;
            bh[nt][0] = Bh2[(ncol + g) * X_APAD + t4];
            bh[nt][1] = Bh2[(ncol + g) * X_APAD + t4 + 4];
            bl[nt][0] = Bl2[(ncol + g) * X_APAD + t4];
            bl[nt][1] = Bl2[(ncol + g) * X_APAD + t4 + 4];
        }
#pragma unroll
        for (int mt = 0; mt < 4; mt++)
#pragma unroll
            for (int nt = 0; nt < 8; nt++) {
                mma_tf32(acc[mt][nt], ah[mt], bh[nt]);
                mma_tf32(acc[mt][nt], ah[mt], bl[nt]);
                mma_tf32(acc[mt][nt], al[mt], bh[nt]);
            }
    }
#undef SISSUE

    float* Cbase = scores + (size_t)h * S * S;
#pragma unroll
    for (int mt = 0; mt < 4; mt++) {
        int rBase = row0 + warpM * 64 + mt * 16 + g;
#pragma unroll
        for (int half = 0; half < 2; half++) {
            int r = rBase + half * 8;
            float* cp = Cbase + (size_t)r * S;
#pragma unroll
            for (int nt = 0; nt < 8; nt++) {
                int col = col0 + warpN * 64 + nt * 8 + t4 * 2;
                float v0 = acc[mt][nt][half * 2 + 0] * scale;
                float v1 = acc[mt][nt][half * 2 + 1] * scale;
                if (col > r) v0 = -3.4028234663852886e38f;
                if (col + 1 > r) v1 = -3.4028234663852886e38f;
                cp[col] = v0;
                cp[col + 1] = v1;
            }
        }
    }
}

// ================= 3xTF32 PV kernel: split-K into 4 chunks, partial outputs ===
__global__ __launch_bounds__(128, 2)
void pv3x_kernel(const float* __restrict__ phi, const float* __restrict__ plo,
                 const float* __restrict__ vhi, const float* __restrict__ vlo,
                 float* __restrict__ part) {
    extern __shared__ char smem[];
    const uint32_t sb = smem_to_u32(smem);
    const int cz = blockIdx.x;   // chunk 0..3
    const int h = blockIdx.z;
    const int row0 = blockIdx.y * 128;

    const int chunkK = (row0 + 128) >> 2;  // multiple of 32
    const int kOff = cz * chunkK;

    const int lda = S;
    const int ldb = NH * D;
    const float* Ah = phi + (size_t)h * S * S;
    const float* Bh = vhi + (size_t)h * D;
    const long long aLoD = plo - phi;
    const long long bLoD = vlo - vhi;

    const int tid = threadIdx.x;
    const int wid = tid >> 5;
    const int lane = tid & 31;
    const int g = lane >> 2;
    const int t4 = lane & 3;
    const int warpM = wid >> 1;
    const int warpN = wid & 1;

    const float* aGh[2];
    uint32_t aSh[2];
#pragma unroll
    for (int j = 0; j < 2; j++) {
        int u = tid + 128 * j;
        int m = u >> 1, c4 = u & 1;
        aGh[j] = Ah + (size_t)(row0 + m) * lda + kOff + c4 * 4;
        aSh[j] = sb + (uint32_t)(m * X_APAD + c4 * 4) * 4u;
    }
    const float* bGh[2];
    uint32_t bSh[2];
#pragma unroll
    for (int j = 0; j < 2; j++) {
        int u = tid + 128 * j;
        int kk = u >> 5, n4 = u & 31;
        bGh[j] = Bh + (size_t)(kOff + kk) * ldb + n4 * 4;
        bSh[j] = sb + (uint32_t)(2 * X_A_B) +
                 (uint32_t)(kk * X_BPAD + n4 * 4) * 4u;
    }

    float acc[4][8][4];
#pragma unroll
    for (int mt = 0; mt < 4; mt++)
#pragma unroll
        for (int nt = 0; nt < 8; nt++)
#pragma unroll
            for (int r = 0; r < 4; r++) acc[mt][nt][r] = 0.f;

    const int nT = chunkK / 8;  // >= 4

#define PISSUE(i)                                                       \
    do {                                                                \
        uint32_t _off = (uint32_t)((i) & 3) * X_STAGE;                  \
        int _k0 = (i) * 8;                                              \
        cp_async16(aSh[0] + _off, aGh[0] + _k0);                        \
        cp_async16(aSh[1] + _off, aGh[1] + _k0);                        \
        cp_async16(aSh[0] + X_A_B + _off, aGh[0] + aLoD + _k0);         \
        cp_async16(aSh[1] + X_A_B + _off, aGh[1] + aLoD + _k0);         \
        cp_async16(bSh[0] + _off, bGh[0] + (size_t)_k0 * ldb);          \
        cp_async16(bSh[1] + _off, bGh[1] + (size_t)_k0 * ldb);          \
        cp_async16(bSh[0] + X_B_B + _off, bGh[0] + bLoD + (size_t)_k0 * ldb); \
        cp_async16(bSh[1] + X_B_B + _off, bGh[1] + bLoD + (size_t)_k0 * ldb); \
        asm volatile("cp.async.commit_group;");                         \
    } while (0)

    PISSUE(0);
    PISSUE(1);
    PISSUE(2);

    for (int i = 0; i < nT; i++) {
        const int rem = nT - 1 - i;
        if (rem >= 2)
            asm volatile("cp.async.wait_group 2;");
        else if (rem == 1)
            asm volatile("cp.async.wait_group 1;");
        else
            asm volatile("cp.async.wait_group 0;");
        __syncthreads();
        if (i + 3 < nT) PISSUE(i + 3);

        const uint32_t* Ah2 = (const uint32_t*)(smem + (size_t)(i & 3) * X_STAGE);
        const uint32_t* Al2 = Ah2 + (X_A_B / 4);
        const uint32_t* Bh2 =
            (const uint32_t*)(smem + (size_t)(i & 3) * X_STAGE + 2 * X_A_B);
        const uint32_t* Bl2 = Bh2 + (X_B_B / 4);

        uint32_t ah[4][4], al[4][4], bh[8][2], bl[8][2];
#pragma unroll
        for (int mt = 0; mt < 4; mt++) {
            int mrow = warpM * 64 + mt * 16;
            ah[mt][0] = Ah2[(mrow + g) * X_APAD + t4];
            ah[mt][1] = Ah2[(mrow + g + 8) * X_APAD + t4];
            ah[mt][2] = Ah2[(mrow + g) * X_APAD + t4 + 4];
            ah[mt][3] = Ah2[(mrow + g + 8) * X_APAD + t4 + 4];
            al[mt][0] = Al2[(mrow + g) * X_APAD + t4];
            al[mt][1] = Al2[(mrow + g + 8) * X_APAD + t4];
            al[mt][2] = Al2[(mrow + g) * X_APAD + t4 + 4];
            al[mt][3] = Al2[(mrow + g + 8) * X_APAD + t4 + 4];
        }
#pragma unroll
        for (int nt = 0; nt < 8; nt++) {
            int ncol = warpN * 64 + nt * 8;
            bh[nt][0] = Bh2[t4 * X_BPAD + ncol + g];
            bh[nt][1] = Bh2[(t4 + 4) * X_BPAD + ncol + g];
            bl[nt][0] = Bl2[t4 * X_BPAD + ncol + g];
            bl[nt][1] = Bl2[(t4 + 4) * X_BPAD + ncol + g];
        }
#pragma unroll
        for (int mt = 0; mt < 4; mt++)
#pragma unroll
            for (int nt = 0; nt < 8; nt++) {
                mma_tf32(acc[mt][nt], ah[mt], bh[nt]);
                mma_tf32(acc[mt][nt], ah[mt], bl[nt]);
                mma_tf32(acc[mt][nt], al[mt], bh[nt]);
            }
    }
#undef PISSUE

    float* Cbase = part + (size_t)cz * S * H + (size_t)h * D;
#pragma unroll
    for (int mt = 0; mt < 4; mt++) {
        int rBase = row0 + warpM * 64 + mt * 16 + g;
#pragma unroll
        for (int half = 0; half < 2; half++) {
            int r = rBase + half * 8;
            float* cp = Cbase + (size_t)r * (NH * D);
#pragma unroll
            for (int nt = 0; nt < 8; nt++) {
                int col = warpN * 64 + nt * 8 + t4 * 2;
                cp[col] = acc[mt][nt][half * 2 + 0];
                cp[col + 1] = acc[mt][nt][half * 2 + 1];
            }
        }
    }
}

// ---------------- PV reduce: sum 4 partials (fixed order) + hi/lo split ------
__global__ void pvreduce_kernel(const float4* __restrict__ part,
                                float4* __restrict__ ahi,
                                float4* __restrict__ alo) {
    const long long n4 = (long long)S * H / 4;
    long long i = (long long)blockIdx.x * 256 + threadIdx.x;
    if (i >= n4) return;
    float4 p0 = part[i];
    float4 p1 = part[i + n4];
    float4 p2 = part[i + 2 * n4];
    float4 p3 = part[i + 3 * n4];
    float4 s;
    s.x = ((p0.x + p1.x) + p2.x) + p3.x;
    s.y = ((p0.y + p1.y) + p2.y) + p3.y;
    s.z = ((p0.z + p1.z) + p2.z) + p3.z;
    s.w = ((p0.w + p1.w) + p2.w) + p3.w;
    float4 hv, lv;
    hv.x = f2tf32f(s.x); lv.x = f2tf32f(s.x - hv.x);
    hv.y = f2tf32f(s.y); lv.y = f2tf32f(s.y - hv.y);
    hv.z = f2tf32f(s.z); lv.z = f2tf32f(s.z - hv.z);
    hv.w = f2tf32f(s.w); lv.w = f2tf32f(s.w - hv.w);
    ahi[i] = hv;
    alo[i] = lv;
}

// ---------------- weight prep: hi/lo split of 4 attention weights only -------
__global__ void prep_kernel(const float4* wq, const float4* wk,
                            const float4* wv, const float4* wo,
                            float4* wsp) {
    const long long nWW = (long long)H * H / 4;
    long long i = (long long)blockIdx.x * 256 + threadIdx.x;
    int y = blockIdx.y;
    const float4* src = (y == 0) ? wq : (y == 1) ? wk : (y == 2) ? wv : wo;
    float4* hi = wsp + (size_t)(2 * y) * nWW;
    float4* lo = hi + nWW;
    if (i < nWW) {
        float4 v = src[i];
        float4 hv, lv;
        hv.x = f2tf32f(v.x); lv.x = f2tf32f(v.x - hv.x);
        hv.y = f2tf32f(v.y); lv.y = f2tf32f(v.y - hv.y);
        hv.z = f2tf32f(v.z); lv.z = f2tf32f(v.z - hv.z);
        hv.w = f2tf32f(v.w); lv.w = f2tf32f(v.w - hv.w);
        hi[i] = hv;
        lo[i] = lv;
    }
}

// ---------------- RMSNorm: hi+lo split or tf32 copy ----------------
__global__ void rmsnorm_kernel(const float* __restrict__ x,
                               const float* __restrict__ w,
                               float* __restrict__ out,
                               float* __restrict__ outTf,
                               float* __restrict__ outLo) {
    const float* xr = x + (long long)blockIdx.x * H;
    float* orow = out + (long long)blockIdx.x * H;
    __shared__ float red[256];
    float s = 0.f;
    for (int j = threadIdx.x; j < H; j += 256) {
        float v = xr[j];
        s += v * v;
    }
    red[threadIdx.x] = s;
    __syncthreads();
    for (int st = 128; st > 0; st >>= 1) {
        if (threadIdx.x < st) red[threadIdx.x] += red[threadIdx.x + st];
        __syncthreads();
    }
    float inv = 1.0f / sqrtf(red[0] / (float)H + 1e-6f);
    if (outLo) {
        float* lrow = outLo + (long long)blockIdx.x * H;
        for (int j = threadIdx.x; j < H; j += 256) {
            float v = w[j] * xr[j] * inv;
            float hi = f2tf32f(v);
            orow[j] = hi;
            lrow[j] = f2tf32f(v - hi);
        }
    } else if (outTf) {
        float* trow = outTf + (long long)blockIdx.x * H;
        for (int j = threadIdx.x; j < H; j += 256) {
            float v = w[j] * xr[j] * inv;
            orow[j] = v;
            trow[j] = f2tf32f(v);
        }
    } else {
        for (int j = threadIdx.x; j < H; j += 256) orow[j] = w[j] * xr[j] * inv;
    }
}

// ---------------- RoPE: rotate + hi/lo split ----------------
__global__ void rope_kernel(const float* __restrict__ q,
                            const float* __restrict__ k,
                            float* __restrict__ qhi, float* __restrict__ qlo,
                            float* __restrict__ khi, float* __restrict__ klo) {
    int s = blockIdx.x;
    int h = blockIdx.y;
    int j = threadIdx.x;
    float inv = exp2f(-(float)j * 0.31143075889569023f);
    float ang = (float)s * inv;
    float c, sn;
    sincosf(ang, &sn, &c);
    long long base = ((long long)s * NH + h) * D;
    float q1 = q[base + j], q2 = q[base + j + 64];
    float k1 = k[base + j], k2 = k[base + j + 64];
    float qa = q1 * c - q2 * sn;
    float qb = q2 * c + q1 * sn;
    float ka = k1 * c - k2 * sn;
    float kb = k2 * c + k1 * sn;
    float t;
    t = f2tf32f(qa); qhi[base + j] = t; qlo[base + j] = f2tf32f(qa - t);
    t = f2tf32f(qb); qhi[base + j + 64] = t; qlo[base + j + 64] = f2tf32f(qb - t);
    t = f2tf32f(ka); khi[base + j] = t; klo[base + j] = f2tf32f(ka - t);
    t = f2tf32f(kb); khi[base + j + 64] = t; klo[base + j + 64] = f2tf32f(kb - t);
}

// ---------------- causal row softmax, hi/lo output ----------------
__global__ void softmax_kernel(float* __restrict__ scores,
                               float* __restrict__ slo) {
    int r = blockIdx.x;
    float* row = scores + ((size_t)blockIdx.y * S + r) * S;
    float* lrow = slo + ((size_t)blockIdx.y * S + r) * S;
    const int limit = r + 1;
    const int rBlk = ((r >> 7) + 1) << 7;
    __shared__ float red[256];
    int tid = threadIdx.x;
    float m = -FLT_MAX;
    for (int j = tid; j < limit; j += 256) m = fmaxf(m, row[j]);
    red[tid] = m;
    __syncthreads();
    for (int st = 128; st > 0; st >>= 1) {
        if (tid < st) red[tid] = fmaxf(red[tid], red[tid + st]);
        __syncthreads();
    }
    m = red[0];
    __syncthreads();
    float sum = 0.f;
    for (int j = tid; j < limit; j += 256) {
        float e = expf(row[j] - m);
        row[j] = e;
        sum += e;
    }
    red[tid] = sum;
    __syncthreads();
    for (int st = 128; st > 0; st >>= 1) {
        if (tid < st) red[tid] += red[tid + st];
        __syncthreads();
    }
    float inv = 1.0f / red[0];
    for (int j = tid; j < limit; j += 256) {
        float p = row[j] * inv;
        float hi = f2tf32f(p);
        row[j] = hi;
        lrow[j] = f2tf32f(p - hi);
    }
    for (int j = limit + tid; j < rBlk; j += 256) {
        row[j] = 0.f;
        lrow[j] = 0.f;
    }
}

// ---------------- router ----------------
__global__ void router_kernel(const float* __restrict__ h2,
                              const float* __restrict__ gate_w,
                              float* __restrict__ logits_out,
                              int* __restrict__ idxbuf,
                              int* __restrict__ cnt,
                              int* __restrict__ tokmap,
                              float* __restrict__ tokw) {
    int s = blockIdx.x;
    const float* hr = h2 + (long long)s * H;
    __shared__ float red[256][E];
    float p[E];
#pragma unroll
    for (int e = 0; e < E; e++) p[e] = 0.f;
    for (int j = threadIdx.x; j < H; j += 256) {
        float hv = hr[j];
#pragma unroll
        for (int e = 0; e < E; e++) p[e] += hv * gate_w[j * E + e];
    }
#pragma unroll
    for (int e = 0; e < E; e++) red[threadIdx.x][e] = p[e];
    __syncthreads();
    for (int st = 128; st > 0; st >>= 1) {
        if (threadIdx.x < st)
#pragma unroll
            for (int e = 0; e < E; e++) red[threadIdx.x][e] += red[threadIdx.x + st][e];
        __syncthreads();
    }
    if (threadIdx.x == 0) {
        float logit[E];
        float m = -FLT_MAX;
#pragma unroll
        for (int e = 0; e < E; e++) {
            logit[e] = red[0][e];
            logits_out[(long long)s * E + e] = logit[e];
            m = fmaxf(m, logit[e]);
        }
        float sum = 0.f, rw[E];
#pragma unroll
        for (int e = 0; e < E; e++) {
            rw[e] = expf(logit[e] - m);
            sum += rw[e];
        }
        float inv = 1.0f / sum;
#pragma unroll
        for (int e = 0; e < E; e++) rw[e] *= inv;
        bool used[E];
#pragma unroll
        for (int e = 0; e < E; e++) used[e] = false;
        for (int k = 0; k < TOPK; k++) {
            int best = -1;
            float bvv = -FLT_MAX;
            for (int e = 0; e < E; e++)
                if (!used[e] && rw[e] > bvv) { bvv = rw[e]; best = e; }
            used[best] = true;
            int pos = atomicAdd(&cnt[best], 1);
            idxbuf[best * S + pos] = s;
            tokmap[s * TOPK + k] = best * S + pos;
            tokw[s * TOPK + k] = bvv;
        }
    }
}

// ---------------- h2 . sgate ----------------
__global__ void rowdot_kernel(const float* __restrict__ h2,
                              const float* __restrict__ sgate,
                              float* __restrict__ gatev) {
    int s = blockIdx.x;
    const float* hr = h2 + (long long)s * H;
    __shared__ float red[256];
    float acc = 0.f;
    for (int j = threadIdx.x; j < H; j += 256) acc += hr[j] * sgate[j];
    red[threadIdx.x] = acc;
    __syncthreads();
    for (int st = 128; st > 0; st >>= 1) {
        if (threadIdx.x < st) red[threadIdx.x] += red[threadIdx.x + st];
        __syncthreads();
    }
    if (threadIdx.x == 0) gatev[s] = red[0];
}

// ---------------- silu kernels ----------------
__global__ void silu_mul_expert_kernel(float* __restrict__ gb,
                                       const float* __restrict__ ub,
                                       const int* __restrict__ cnt) {
    int e = blockIdx.y;
    long long i = (long long)blockIdx.x * 256 + threadIdx.x;
    long long lim = (long long)cnt[e] * IE;
    if (i >= lim) return;
    size_t o = (size_t)e * S * IE + i;
    float x = gb[o];
    float sg = 1.0f / (1.0f + expf(-x));
    gb[o] = f2tf32f(x * sg * ub[o]);
}
__global__ void silu_mul_kernel(float* __restrict__ g, const float* __restrict__ u,
                                long long n) {
    long long i = (long long)blockIdx.x * 256 + threadIdx.x;
    if (i < n) {
        float x = g[i];
        float sg = 1.0f / (1.0f + expf(-x));
        g[i] = f2tf32f(x * sg * u[i]);
    }
}

// ---------------- final combine ----------------
__global__ void final_kernel(const float* __restrict__ x1,
                             const float* __restrict__ eo,
                             const int* __restrict__ tokmap,
                             const float* __restrict__ tokw,
                             const float* __restrict__ sdwn,
                             const float* __restrict__ gatev,
                             float* __restrict__ out) {
    long long i = (long long)blockIdx.x * 256 + threadIdx.x;
    int s = (int)(i / H);
    int c = (int)(i % H);
    float gv = 1.0f / (1.0f + expf(-gatev[s]));
    float acc = x1[i] + gv * sdwn[i];
#pragma unroll
    for (int j = 0; j < TOPK; j++) {
        int row = tokmap[s * TOPK + j];
        acc += tokw[s * TOPK + j] * eo[(size_t)row * H + c];
    }
    out[i] = acc;
}

// ---------------- host ----------------
static void launch_mma(const float* A, int lda, long long aStrE,
                       const float* B0, const float* B1, int ldb, long long bStrE,
                       float* C0, float* C1, int ldc, long long cStrE,
                       int M, int N, int K,
                       const int* gidx, int gstr, const int* cnt, int eShift,
                       int nz) {
    dim3 grid(N / 128, (M + 127) / 128, nz);
    mma_gemm_kernel<<<grid, 128, MMA_SMEM>>>(A, lda, aStrE, B0, B1, ldb, bStrE,
                                             C0, C1, ldc, cStrE, M, N, K,
                                             gidx, gstr, cnt, eShift);
}

extern "C" void kernel_launch(void* const* d_in, const int* in_sizes, int n_in,
                              void* d_out, int out_size) {
    (void)in_sizes; (void)n_in; (void)out_size;
    const float* x     = (const float*)d_in[0];
    const float* ln1   = (const float*)d_in[1];
    const float* ln2   = (const float*)d_in[2];
    const float* wq    = (const float*)d_in[3];
    const float* bq    = (const float*)d_in[4];
    const float* wk    = (const float*)d_in[5];
    const float* bk    = (const float*)d_in[6];
    const float* wv    = (const float*)d_in[7];
    const float* bv    = (const float*)d_in[8];
    const float* wo    = (const float*)d_in[9];
    const float* gatew = (const float*)d_in[10];
    const float* eg    = (const float*)d_in[11];
    const float* eu    = (const float*)d_in[12];
    const float* ed    = (const float*)d_in[13];
    const float* sg    = (const float*)d_in[14];
    const float* su    = (const float*)d_in[15];
    const float* sd    = (const float*)d_in[16];
    const float* sgate = (const float*)d_in[17];
    float* out = (float*)d_out;

    cudaFuncSetAttribute(mma_gemm_kernel,
                         cudaFuncAttributeMaxDynamicSharedMemorySize, MMA_SMEM);
    cudaFuncSetAttribute(mma3x_kernel,
                         cudaFuncAttributeMaxDynamicSharedMemorySize, X_SMEM);
    cudaFuncSetAttribute(sc3x_kernel,
                         cudaFuncAttributeMaxDynamicSharedMemorySize, SC_SMEM);
    cudaFuncSetAttribute(pv3x_kernel,
                         cudaFuncAttributeMaxDynamicSharedMemorySize, X_SMEM);

    float *hhi, *hlo, *q, *k, *qhi, *qlo, *khi, *klo, *vhi, *vlo, *scores,
        *slo, *pvpart, *ahi, *alo, *x1, *h2, *ch2, *gb, *ub, *eo, *sgb, *sub,
        *sdwn, *gatev, *tokw, *wsp;
    int *idx, *cnt, *tokmap;
    cudaGetSymbolAddress((void**)&hhi, g_hhi);
    cudaGetSymbolAddress((void**)&hlo, g_hlo);
    cudaGetSymbolAddress((void**)&q, g_q);
    cudaGetSymbolAddress((void**)&k, g_k);
    cudaGetSymbolAddress((void**)&qhi, g_qhi);
    cudaGetSymbolAddress((void**)&qlo, g_qlo);
    cudaGetSymbolAddress((void**)&khi, g_khi);
    cudaGetSymbolAddress((void**)&klo, g_klo);
    cudaGetSymbolAddress((void**)&vhi, g_vhi);
    cudaGetSymbolAddress((void**)&vlo, g_vlo);
    cudaGetSymbolAddress((void**)&scores, g_scores);
    cudaGetSymbolAddress((void**)&slo, g_slo);
    cudaGetSymbolAddress((void**)&pvpart, g_pvpart);
    cudaGetSymbolAddress((void**)&ahi, g_ahi);
    cudaGetSymbolAddress((void**)&alo, g_alo);
    cudaGetSymbolAddress((void**)&x1, g_x1);
    cudaGetSymbolAddress((void**)&h2, g_h2);
    cudaGetSymbolAddress((void**)&ch2, g_ch2);
    cudaGetSymbolAddress((void**)&gb, g_gb);
    cudaGetSymbolAddress((void**)&ub, g_ub);
    cudaGetSymbolAddress((void**)&eo, g_eo);
    cudaGetSymbolAddress((void**)&sgb, g_sgb);
    cudaGetSymbolAddress((void**)&sub, g_sub);
    cudaGetSymbolAddress((void**)&sdwn, g_sdwn);
    cudaGetSymbolAddress((void**)&gatev, g_gatev);
    cudaGetSymbolAddress((void**)&idx, g_idx);
    cudaGetSymbolAddress((void**)&cnt, g_cnt);
    cudaGetSymbolAddress((void**)&tokmap, g_tokmap);
    cudaGetSymbolAddress((void**)&tokw, g_tokw);
    cudaGetSymbolAddress((void**)&wsp, g_wsp);

    const size_t WW = (size_t)H * H;
    const float* wqh = wsp;
    const float* wql = wsp + WW;
    const float* wkh = wsp + 2 * WW;
    const float* wkl = wsp + 3 * WW;
    const float* wvh = wsp + 4 * WW;
    const float* wvl = wsp + 5 * WW;
    const float* woh = wsp + 6 * WW;
    const float* wol = wsp + 7 * WW;

    const float ascale = 0.08838834764831845f;

    // 0. weight prep: attention hi/lo splits only
    {
        unsigned gx = (unsigned)((WW / 4 + 255) / 256);
        dim3 grid(gx, 4);
        prep_kernel<<<grid, 256>>>((const float4*)wq, (const float4*)wk,
                                   (const float4*)wv, (const float4*)wo,
                                   (float4*)wsp);
    }

    // 1. h = rmsnorm(x, ln1), hi/lo split
    rmsnorm_kernel<<<S, 256>>>(x, ln1, hhi, nullptr, hlo);

    // 2. q,k,v via 3xTF32; v written pre-split (hi->vhi, lo->vlo)
    {
        dim3 grid(16, 16, 3);
        mma3x_kernel<<<grid, 128, X_SMEM>>>(
            hhi, hlo, H, wqh, wql, wkh, wkl, wvh, wvl, NH * D,
            bq, bk, bv, q, k, vhi, vlo, NH * D, nullptr, H);
    }

    // 3. RoPE + q/k hi-lo split
    rope_kernel<<<dim3(S, NH), 64>>>(q, k, qhi, qlo, khi, klo);

    // 4. scores via 3xTF32 (causal blocks only)
    {
        dim3 grid(S / 128, S / 128, NH);
        sc3x_kernel<<<grid, 128, SC_SMEM>>>(qhi, qlo, khi, klo, scores, ascale);
    }

    // 5. softmax -> probs hi (in place) + lo
    softmax_kernel<<<dim3(S, NH), 256>>>(scores, slo);

    // 6. attn = probs @ v via 3xTF32, split-K over 4 chunks -> partials
    {
        dim3 grid(4, S / 128, NH);
        pv3x_kernel<<<grid, 128, X_SMEM>>>(scores, slo, vhi, vlo, pvpart);
    }
    // 6b. reduce partials (fixed order) + hi/lo split
    {
        long long n4 = (long long)S * H / 4;
        pvreduce_kernel<<<(unsigned)((n4 + 255) / 256), 256>>>(
            (const float4*)pvpart, (float4*)ahi, (float4*)alo);
    }

    // 7. x1 = x + attn @ wo via 3xTF32
    {
        dim3 grid(16, 16, 1);
        mma3x_kernel<<<grid, 128, X_SMEM>>>(
            ahi, alo, NH * D, woh, wol, nullptr, nullptr, nullptr, nullptr, H,
            nullptr, nullptr, nullptr, x1, nullptr, nullptr, nullptr, H, x,
            NH * D);
    }

    // 8. h2 = rmsnorm(x1, ln2) + tf32 copy
    rmsnorm_kernel<<<S, 256>>>(x1, ln2, h2, ch2, nullptr);

    // 9. router
    cudaMemsetAsync(cnt, 0, E * sizeof(int));
    router_kernel<<<S, 256>>>(h2, gatew, out + (long long)S * H, idx, cnt,
                              tokmap, tokw);

    // 10. MoE gate+up (raw fp32 weights)
    launch_mma(ch2, H, 0, eg, eu, IE, (long long)H * IE,
               gb, ub, IE, (long long)S * IE, S, IE, H, idx, S, cnt, 1, 2 * E);

    // 11. silu
    {
        dim3 grid((unsigned)(((long long)S * IE + 255) / 256), E);
        silu_mul_expert_kernel<<<grid, 256>>>(gb, ub, cnt);
    }

    // 12. MoE down (raw fp32 weights)
    launch_mma(gb, IE, (long long)S * IE, ed, nullptr, H, (long long)IE * H,
               eo, nullptr, H, (long long)S * H, S, H, IE, nullptr, 0, cnt, 0, E);

    // 13. shared expert (raw fp32 weights)
    launch_mma(ch2, H, 0, sg, su, IS, 0, sgb, sub, IS, 0, S, IS, H,
               nullptr, 0, nullptr, 1, 2);
    {
        long long n = (long long)S * IS;
        silu_mul_kernel<<<(unsigned)((n + 255) / 256), 256>>>(sgb, sub, n);
    }
    launch_mma(sgb, IS, 0, sd, nullptr, H, 0, sdwn, nullptr, H, 0, S, H, IS,
               nullptr, 0, nullptr, 0, 1);

    // 14. gate scalar
    rowdot_kernel<<<S, 256>>>(h2, sgate, gatev);

    // 15. combine
    final_kernel<<<(S * H) / 256, 256>>>(x1, eo, tokmap, tokw, sdwn, gatev, out);
}